// round 10
// baseline (speedup 1.0000x reference)
#include <cuda_runtime.h>
#include <cuda_bf16.h>
#include <mma.h>
#include <math.h>
#include <stdint.h>

using namespace nvcuda;

// ---------------- problem constants ----------------
#define BATCH   32
#define ETOT    262144
#define NMAX    32768
#define K1      615
#define K2      369
#define K3      185
#define N1      32768
#define N2      (BATCH*K1)      // 19680
#define N3      (BATCH*K2)      // 11808
#define N4      (BATCH*K3)      // 5920

#define CEILDIV(a,b) (((a)+(b)-1)/(b))

// ---------------- static device scratch ----------------
__device__ float g_buf0[(size_t)NMAX * 512];
__device__ float g_buf1[(size_t)NMAX * 512];
__device__ float g_dis[NMAX];
__device__ float g_score[NMAX];
__device__ float g_t[NMAX];
__device__ float g_gain[NMAX];
__device__ int   g_newid[NMAX];
__device__ int   g_perm[NMAX];
__device__ int   g_src[ETOT];
__device__ int   g_dst[ETOT];
__device__ float g_ew[ETOT];
__device__ float g_sum[512];
__device__ float g_sumsq[512];
// CSR scratch
__device__ int   g_icount[NMAX];
__device__ int   g_rowptr[NMAX + 1];
__device__ int   g_cursor[NMAX];
__device__ int   g_esrc[ETOT];
__device__ float g_enorm[ETOT];
__device__ int   g_blocksum[32];
__device__ int   g_blockoff[32];
// bf16 split-precision GEMM scratch
__device__ __nv_bfloat16 g_aHi[(size_t)NMAX * 512];
__device__ __nv_bfloat16 g_aLo[(size_t)NMAX * 512];
__device__ __nv_bfloat16 g_wHiT[512 * 512];
__device__ __nv_bfloat16 g_wLoT[512 * 512];

// ---------------- kernels ----------------

// edge init fused with layer-1 in-degree count (icount pre-zeroed)
__global__ void edge_init_count_kernel(const int* __restrict__ ei,
                                       int* __restrict__ src, int* __restrict__ dst,
                                       float* __restrict__ ew, int* __restrict__ cnt) {
    int e = blockIdx.x * blockDim.x + threadIdx.x;
    if (e >= ETOT) return;
    int d = ei[ETOT + e];
    src[e] = ei[e];
    dst[e] = d;
    ew[e]  = 1.0f;
    atomicAdd(&cnt[d], 1);
}

// ---------------- bf16 split conversion ----------------

__global__ void convertA_kernel(const float4* __restrict__ A,
                                __nv_bfloat162* __restrict__ hi2,
                                __nv_bfloat162* __restrict__ lo2, int n4) {
    int i = blockIdx.x * blockDim.x + threadIdx.x;
    if (i >= n4) return;
    float4 v = A[i];
    __nv_bfloat16 h0 = __float2bfloat16(v.x);
    __nv_bfloat16 h1 = __float2bfloat16(v.y);
    __nv_bfloat16 h2 = __float2bfloat16(v.z);
    __nv_bfloat16 h3 = __float2bfloat16(v.w);
    hi2[2 * i]     = __halves2bfloat162(h0, h1);
    hi2[2 * i + 1] = __halves2bfloat162(h2, h3);
    lo2[2 * i]     = __halves2bfloat162(__float2bfloat16(v.x - __bfloat162float(h0)),
                                        __float2bfloat16(v.y - __bfloat162float(h1)));
    lo2[2 * i + 1] = __halves2bfloat162(__float2bfloat16(v.z - __bfloat162float(h2)),
                                        __float2bfloat16(v.w - __bfloat162float(h3)));
}

// W [K,N] fp32 -> WT_hi/lo [N,K] bf16 (output-coalesced)
__global__ void convertW_kernel(const float* __restrict__ W,
                                __nv_bfloat16* __restrict__ hiT,
                                __nv_bfloat16* __restrict__ loT, int K, int N) {
    int idx = blockIdx.x * blockDim.x + threadIdx.x;
    if (idx >= K * N) return;
    int n = idx / K, k = idx - n * K;
    float v = W[k * N + n];
    __nv_bfloat16 h = __float2bfloat16(v);
    __nv_bfloat16 l = __float2bfloat16(v - __bfloat162float(h));
    hiT[idx] = h;
    loT[idx] = l;
}

// ---------------------------------------------------------------
// WMMA bf16 split-precision GEMM v3.
// C[M,N] = A[M,K] @ B[K,N]; A as Ahi/Alo [M,K]; B transposed Bhi/Blo [N,K].
// CTA tile 128x128, 4 warps in 2(M)x2(N), warp tile 64x64 (acc 4x4).
// cp.async 2-stage pipeline, TBK=32 per stage. 2 CTAs/SM.
// Acc = Ahi*Bhi + Ahi*Blo + Alo*Bhi in fp32.
// ---------------------------------------------------------------
#define TBM 128
#define TBN 128
#define TBK 32
#define WLDA 40                            // 80B rows: conflict-free, 16B aligned
#define TILE_BYTES (128 * WLDA * 2)        // 10240
#define TILE_ELEMS (128 * WLDA)            // 5120
#define STAGE_BYTES (4 * TILE_BYTES)       // 40960
#define GEMM_SMEM (2 * STAGE_BYTES)        // 81920

__device__ __forceinline__ void cp16(uint32_t s, const void* g, int sz) {
    asm volatile("cp.async.cg.shared.global [%0], [%1], 16, %2;"
                 :: "r"(s), "l"(g), "r"(sz));
}

__global__ void __launch_bounds__(128, 2)
wmma_gemm_kernel(const __nv_bfloat16* __restrict__ Ahi,
                 const __nv_bfloat16* __restrict__ Alo,
                 const __nv_bfloat16* __restrict__ Bhi,
                 const __nv_bfloat16* __restrict__ Blo,
                 float* __restrict__ C, int M, int K, int N) {
    extern __shared__ __nv_bfloat16 sm[];

    const int tid = threadIdx.x;          // 128 threads
    const int wid = tid >> 5;             // 0..3
    const int warpM = wid & 1;
    const int warpN = wid >> 1;
    const int mBase = blockIdx.y * TBM;
    const int nBase = blockIdx.x * TBN;

    wmma::fragment<wmma::accumulator, 16, 16, 16, float> acc[4][4];
#pragma unroll
    for (int i = 0; i < 4; i++)
#pragma unroll
        for (int j = 0; j < 4; j++) wmma::fill_fragment(acc[i][j], 0.f);

    const uint32_t sbase = (uint32_t)__cvta_generic_to_shared(sm);
    const int grow = mBase + tid;
    const int nrow = nBase + tid;
    const size_t aoff = (size_t)(grow < M ? grow : 0) * K;
    const size_t boff = (size_t)nrow * K;
    const int szA = (grow < M) ? 16 : 0;
    const uint32_t srow = sbase + (uint32_t)tid * (WLDA * 2);

    // stage s covers K range [kc, kc+32); each thread fills one row of all 4 tiles
#define LOAD_STAGE(s, kc) do { \
        uint32_t s0 = srow + (uint32_t)(s) * STAGE_BYTES; \
        _Pragma("unroll") \
        for (int q = 0; q < 4; q++) { \
            cp16(s0 + q * 16,                  Ahi + aoff + (kc) + q * 8, szA); \
            cp16(s0 + q * 16 + TILE_BYTES,     Alo + aoff + (kc) + q * 8, szA); \
            cp16(s0 + q * 16 + 2 * TILE_BYTES, Bhi + boff + (kc) + q * 8, 16); \
            cp16(s0 + q * 16 + 3 * TILE_BYTES, Blo + boff + (kc) + q * 8, 16); \
        } \
    } while (0)

    LOAD_STAGE(0, 0);
    asm volatile("cp.async.commit_group;" ::: "memory");

    const int nCh = K >> 5;
    for (int ch = 0; ch < nCh; ch++) {
        if (ch + 1 < nCh) {
            LOAD_STAGE((ch + 1) & 1, (ch + 1) << 5);
            asm volatile("cp.async.commit_group;" ::: "memory");
            asm volatile("cp.async.wait_group 1;" ::: "memory");
        } else {
            asm volatile("cp.async.wait_group 0;" ::: "memory");
        }
        __syncthreads();

        const __nv_bfloat16* sb   = sm + (ch & 1) * (2 * STAGE_BYTES / 4); // elems
        const __nv_bfloat16* sAhi = sb;
        const __nv_bfloat16* sAlo = sb + TILE_ELEMS;
        const __nv_bfloat16* sBhi = sb + 2 * TILE_ELEMS;
        const __nv_bfloat16* sBlo = sb + 3 * TILE_ELEMS;

#pragma unroll
        for (int ks = 0; ks < TBK; ks += 16) {
            wmma::fragment<wmma::matrix_b, 16, 16, 16, __nv_bfloat16, wmma::col_major> bh[4], bl[4];
#pragma unroll
            for (int j = 0; j < 4; j++) {
                wmma::load_matrix_sync(bh[j], sBhi + (warpN * 64 + j * 16) * WLDA + ks, WLDA);
                wmma::load_matrix_sync(bl[j], sBlo + (warpN * 64 + j * 16) * WLDA + ks, WLDA);
            }
#pragma unroll
            for (int i = 0; i < 4; i++) {
                wmma::fragment<wmma::matrix_a, 16, 16, 16, __nv_bfloat16, wmma::row_major> ah, al;
                wmma::load_matrix_sync(ah, sAhi + (warpM * 64 + i * 16) * WLDA + ks, WLDA);
                wmma::load_matrix_sync(al, sAlo + (warpM * 64 + i * 16) * WLDA + ks, WLDA);
#pragma unroll
                for (int j = 0; j < 4; j++) wmma::mma_sync(acc[i][j], ah, bh[j], acc[i][j]);
#pragma unroll
                for (int j = 0; j < 4; j++) wmma::mma_sync(acc[i][j], ah, bl[j], acc[i][j]);
#pragma unroll
                for (int j = 0; j < 4; j++) wmma::mma_sync(acc[i][j], al, bh[j], acc[i][j]);
            }
        }
        __syncthreads();
    }
#undef LOAD_STAGE

#pragma unroll
    for (int i = 0; i < 4; i++) {
        int r0 = mBase + warpM * 64 + i * 16;
#pragma unroll
        for (int j = 0; j < 4; j++) {
            float* cp = C + (size_t)r0 * N + nBase + warpN * 64 + j * 16;
            wmma::store_matrix_sync(cp, acc[i][j], N, wmma::mem_row_major);
        }
    }
}

// ---------------- CSR build ----------------

__global__ void __launch_bounds__(1024)
scan_partial_kernel(const int* __restrict__ cnt, int* __restrict__ rowptr,
                    int* __restrict__ blocksum, int n) {
    __shared__ int warpsum[32];
    const int tid = threadIdx.x;
    const int i = blockIdx.x * 1024 + tid;
    int v = (i < n) ? cnt[i] : 0;
    const int s = v;

    const int lane = tid & 31, wid = tid >> 5;
#pragma unroll
    for (int off = 1; off < 32; off <<= 1) {
        int u = __shfl_up_sync(0xffffffffu, v, off);
        if (lane >= off) v += u;
    }
    if (lane == 31) warpsum[wid] = v;
    __syncthreads();
    if (wid == 0) {
        int w = warpsum[lane];
#pragma unroll
        for (int off = 1; off < 32; off <<= 1) {
            int u = __shfl_up_sync(0xffffffffu, w, off);
            if (lane >= off) w += u;
        }
        warpsum[lane] = w;
    }
    __syncthreads();
    int excl = v - s + (wid > 0 ? warpsum[wid - 1] : 0);
    if (i < n) rowptr[i] = excl;
    if (tid == 1023) blocksum[blockIdx.x] = excl + s;
}

__global__ void scan_blocksums_kernel(const int* __restrict__ blocksum,
                                      int* __restrict__ blockoff,
                                      int* __restrict__ rowptr,
                                      int nblocks, int n) {
    const int lane = threadIdx.x;
    int v = (lane < nblocks) ? blocksum[lane] : 0;
    const int s = v;
#pragma unroll
    for (int off = 1; off < 32; off <<= 1) {
        int u = __shfl_up_sync(0xffffffffu, v, off);
        if (lane >= off) v += u;
    }
    if (lane < nblocks) blockoff[lane] = v - s;
    if (lane == 31) rowptr[n] = v;
}

__global__ void __launch_bounds__(1024)
scan_finalize_kernel(const int* __restrict__ cnt, int* __restrict__ rowptr,
                     const int* __restrict__ blockoff,
                     int* __restrict__ cursor, float* __restrict__ dis, int n) {
    const int i = blockIdx.x * 1024 + threadIdx.x;
    if (i >= n) return;
    int r = rowptr[i] + blockoff[blockIdx.x];
    rowptr[i] = r;
    cursor[i] = r;
    int c = cnt[i];
    dis[i] = (c > 0) ? rsqrtf((float)c) : 0.f;
}

__global__ void fill_kernel(const int* __restrict__ src, const int* __restrict__ dst,
                            const float* __restrict__ ew, const float* __restrict__ dis,
                            int* __restrict__ cursor,
                            int* __restrict__ esrc, float* __restrict__ enorm) {
    int e = blockIdx.x * blockDim.x + threadIdx.x;
    if (e >= ETOT) return;
    float w = ew[e];
    if (w == 0.f) return;
    int s = src[e], d = dst[e];
    int pos = atomicAdd(&cursor[d], 1);
    esrc[pos] = s;
    enorm[pos] = dis[s] * dis[d] * w;
}

template <int C>
__global__ void gather_agg_kernel(const float* __restrict__ h,
                                  const int* __restrict__ rowptr,
                                  const int* __restrict__ esrc,
                                  const float* __restrict__ enorm,
                                  const float* __restrict__ bias,
                                  float* __restrict__ out) {
    const int node = blockIdx.x;
    const int tid = threadIdx.x;
    float4 acc = *(const float4*)(bias + tid * 4);
    int b = rowptr[node];
    const int e = rowptr[node + 1];
    for (; b + 1 < e; b += 2) {
        int s0 = esrc[b],     s1 = esrc[b + 1];
        float n0 = enorm[b],  n1 = enorm[b + 1];
        float4 v0 = *(const float4*)(h + (size_t)s0 * C + tid * 4);
        float4 v1 = *(const float4*)(h + (size_t)s1 * C + tid * 4);
        acc.x += v0.x * n0; acc.y += v0.y * n0; acc.z += v0.z * n0; acc.w += v0.w * n0;
        acc.x += v1.x * n1; acc.y += v1.y * n1; acc.z += v1.z * n1; acc.w += v1.w * n1;
    }
    if (b < e) {
        int s0 = esrc[b];
        float n0 = enorm[b];
        float4 v0 = *(const float4*)(h + (size_t)s0 * C + tid * 4);
        acc.x += v0.x * n0; acc.y += v0.y * n0; acc.z += v0.z * n0; acc.w += v0.w * n0;
    }
    *(float4*)(out + (size_t)node * C + tid * 4) = acc;
}

// ---------------- BN / pool / misc ----------------

__global__ void bn_stats_kernel(const float* __restrict__ h,
                                float* __restrict__ sum, float* __restrict__ sumsq,
                                int n, int C) {
    int c = blockIdx.x * 256 + threadIdx.x;
    if (c >= C) return;
    int rowsPer = CEILDIV(n, gridDim.y);
    int r0 = blockIdx.y * rowsPer;
    int r1 = min(n, r0 + rowsPer);
    float s = 0.f, sq = 0.f;
    for (int r = r0; r < r1; r++) {
        float v = h[(size_t)r * C + c];
        s += v;
        sq += v * v;
    }
    atomicAdd(&sum[c], s);
    atomicAdd(&sumsq[c], sq);
}

// fused BN(apply)+tanh + pool dot-products; warp per node
__global__ void bn_dots_kernel(float* __restrict__ h,
                               const float* __restrict__ sum, const float* __restrict__ sumsq,
                               const float* __restrict__ gma, const float* __restrict__ bta,
                               const float* __restrict__ relw, const float* __restrict__ rootw,
                               const float* __restrict__ relb,
                               float* __restrict__ t, float* __restrict__ score,
                               int n, int C) {
    int node = (blockIdx.x * blockDim.x + threadIdx.x) >> 5;
    int lane = threadIdx.x & 31;
    if (node >= n) return;
    float* hp = h + (size_t)node * C;
    const float invn = 1.f / (float)n;
    float a = 0.f, b = 0.f;
    for (int c = lane; c < C; c += 32) {
        float mean = sum[c] * invn;
        float var = sumsq[c] * invn - mean * mean;
        float y = tanhf((hp[c] - mean) * rsqrtf(var + 1e-5f) * gma[c] + bta[c]);
        hp[c] = y;
        a += y * relw[c];
        b += y * rootw[c];
    }
#pragma unroll
    for (int o = 16; o > 0; o >>= 1) {
        a += __shfl_down_sync(0xffffffffu, a, o);
        b += __shfl_down_sync(0xffffffffu, b, o);
    }
    if (lane == 0) {
        t[node] = a;
        score[node] = b + relb[0];
    }
}

__global__ void score_edge_kernel(const int* __restrict__ src, const int* __restrict__ dst,
                                  const float* __restrict__ ew, const float* __restrict__ t,
                                  float* __restrict__ score) {
    int e = blockIdx.x * blockDim.x + threadIdx.x;
    if (e >= ETOT) return;
    float w = ew[e];
    if (w != 0.f) atomicAdd(&score[dst[e]], w * t[src[e]]);
}

__global__ void init_newid_kernel(int* __restrict__ newid, int n) {
    int i = blockIdx.x * blockDim.x + threadIdx.x;
    if (i < n) newid[i] = -1;
}

template <int SZ>
__global__ void __launch_bounds__(512)
topk_kernel(const float* __restrict__ score, int n_per, int ksel,
            int* __restrict__ perm, float* __restrict__ gain, int* __restrict__ newid) {
    __shared__ float sk[SZ];
    __shared__ int si[SZ];
    const int g = blockIdx.x;
    const int tid = threadIdx.x;
    for (int i = tid; i < SZ; i += 512) {
        if (i < n_per) { sk[i] = score[g * n_per + i]; si[i] = i; }
        else           { sk[i] = -INFINITY;            si[i] = 0x40000000 + i; }
    }
    __syncthreads();
    for (int kk = 2; kk <= SZ; kk <<= 1) {
        for (int j = kk >> 1; j > 0; j >>= 1) {
            for (int i = tid; i < SZ; i += 512) {
                int ixj = i ^ j;
                if (ixj > i) {
                    bool up = ((i & kk) == 0);
                    float s1 = sk[i], s2 = sk[ixj];
                    int i1 = si[i], i2 = si[ixj];
                    bool after = (s1 < s2) || (s1 == s2 && i1 > i2);
                    if (up == after) {
                        sk[i] = s2; sk[ixj] = s1;
                        si[i] = i2; si[ixj] = i1;
                    }
                }
            }
            __syncthreads();
        }
    }
    for (int r = tid; r < ksel; r += 512) {
        int old = g * n_per + si[r];
        int ng = g * ksel + r;
        perm[ng] = old;
        gain[ng] = tanhf(sk[r]);
        newid[old] = ng;
    }
}

// pool gather fused with bf16 hi/lo split: x_new = h[perm]*tanh(score[perm])
__global__ void gather_split_kernel(const float* __restrict__ hin,
                                    __nv_bfloat16* __restrict__ hi,
                                    __nv_bfloat16* __restrict__ lo,
                                    const int* __restrict__ perm,
                                    const float* __restrict__ gain,
                                    int rows, int C4) {
    int idx = blockIdx.x * blockDim.x + threadIdx.x;
    if (idx >= rows * C4) return;
    int row = idx / C4;
    int c = idx - row * C4;
    float gn = gain[row];
    float4 v = ((const float4*)hin)[(size_t)perm[row] * C4 + c];
    v.x *= gn; v.y *= gn; v.z *= gn; v.w *= gn;
    __nv_bfloat16 h0 = __float2bfloat16(v.x);
    __nv_bfloat16 h1 = __float2bfloat16(v.y);
    __nv_bfloat16 h2 = __float2bfloat16(v.z);
    __nv_bfloat16 h3 = __float2bfloat16(v.w);
    __nv_bfloat162* hp = (__nv_bfloat162*)(hi) + 2 * idx;
    __nv_bfloat162* lp = (__nv_bfloat162*)(lo) + 2 * idx;
    hp[0] = __halves2bfloat162(h0, h1);
    hp[1] = __halves2bfloat162(h2, h3);
    lp[0] = __halves2bfloat162(__float2bfloat16(v.x - __bfloat162float(h0)),
                               __float2bfloat16(v.y - __bfloat162float(h1)));
    lp[1] = __halves2bfloat162(__float2bfloat16(v.z - __bfloat162float(h2)),
                               __float2bfloat16(v.w - __bfloat162float(h3)));
}

// remap fused with next layer's in-degree count (icount pre-zeroed)
__global__ void remap_count_kernel(int* __restrict__ src, int* __restrict__ dst,
                                   float* __restrict__ ew, const int* __restrict__ newid,
                                   int* __restrict__ cnt) {
    int e = blockIdx.x * blockDim.x + threadIdx.x;
    if (e >= ETOT) return;
    int ns = newid[src[e]];
    int nd = newid[dst[e]];
    bool keep = (ns >= 0) && (nd >= 0) && (ew[e] != 0.f);
    src[e] = keep ? ns : 0;
    dst[e] = keep ? nd : 0;
    ew[e] = keep ? ew[e] : 0.f;
    if (keep) atomicAdd(&cnt[nd], 1);
}

__global__ void readout_kernel(const float* __restrict__ h, float* __restrict__ out) {
    int g = blockIdx.x;
    int c = threadIdx.x;
    const float* p = h + (size_t)(g * K3) * 256 + c;
    float mx = -INFINITY, sm = 0.f;
    for (int i = 0; i < K3; i++) {
        float v = p[(size_t)i * 256];
        mx = fmaxf(mx, v);
        sm += v;
    }
    out[g * 512 + c] = mx;
    out[g * 512 + 256 + c] = sm / (float)K3;
}

// ---------------- host orchestration ----------------

extern "C" void kernel_launch(void* const* d_in, const int* in_sizes, int n_in,
                              void* d_out, int out_size) {
    const float* x    = (const float*)d_in[0];
    const int*   ei   = (const int*)d_in[1];
    const float* W1   = (const float*)d_in[2];
    const float* b1   = (const float*)d_in[3];
    const float* W2   = (const float*)d_in[4];
    const float* b2   = (const float*)d_in[5];
    const float* W3   = (const float*)d_in[6];
    const float* b3   = (const float*)d_in[7];
    const float* W4   = (const float*)d_in[8];
    const float* b4   = (const float*)d_in[9];
    const float* g1   = (const float*)d_in[10];
    const float* be1  = (const float*)d_in[11];
    const float* g2   = (const float*)d_in[12];
    const float* be2  = (const float*)d_in[13];
    const float* g3   = (const float*)d_in[14];
    const float* be3  = (const float*)d_in[15];
    const float* p1rw = (const float*)d_in[16];
    const float* p1rb = (const float*)d_in[17];
    const float* p1ow = (const float*)d_in[18];
    const float* p2rw = (const float*)d_in[19];
    const float* p2rb = (const float*)d_in[20];
    const float* p2ow = (const float*)d_in[21];
    const float* p3rw = (const float*)d_in[22];
    const float* p3rb = (const float*)d_in[23];
    const float* p3ow = (const float*)d_in[24];
    float* out = (float*)d_out;

    float *buf0, *buf1, *dis, *score, *t, *gain, *ew, *sum, *sumsq, *enorm;
    int *src, *dst, *newid, *perm, *icount, *rowptr, *cursor, *esrc, *blocksum, *blockoff;
    __nv_bfloat16 *aHi, *aLo, *wHiT, *wLoT;
    cudaGetSymbolAddress((void**)&buf0, g_buf0);
    cudaGetSymbolAddress((void**)&buf1, g_buf1);
    cudaGetSymbolAddress((void**)&dis, g_dis);
    cudaGetSymbolAddress((void**)&score, g_score);
    cudaGetSymbolAddress((void**)&t, g_t);
    cudaGetSymbolAddress((void**)&gain, g_gain);
    cudaGetSymbolAddress((void**)&ew, g_ew);
    cudaGetSymbolAddress((void**)&sum, g_sum);
    cudaGetSymbolAddress((void**)&sumsq, g_sumsq);
    cudaGetSymbolAddress((void**)&src, g_src);
    cudaGetSymbolAddress((void**)&dst, g_dst);
    cudaGetSymbolAddress((void**)&newid, g_newid);
    cudaGetSymbolAddress((void**)&perm, g_perm);
    cudaGetSymbolAddress((void**)&icount, g_icount);
    cudaGetSymbolAddress((void**)&rowptr, g_rowptr);
    cudaGetSymbolAddress((void**)&cursor, g_cursor);
    cudaGetSymbolAddress((void**)&esrc, g_esrc);
    cudaGetSymbolAddress((void**)&enorm, g_enorm);
    cudaGetSymbolAddress((void**)&blocksum, g_blocksum);
    cudaGetSymbolAddress((void**)&blockoff, g_blockoff);
    cudaGetSymbolAddress((void**)&aHi, g_aHi);
    cudaGetSymbolAddress((void**)&aLo, g_aLo);
    cudaGetSymbolAddress((void**)&wHiT, g_wHiT);
    cudaGetSymbolAddress((void**)&wLoT, g_wLoT);

    cudaFuncSetAttribute(wmma_gemm_kernel,
                         cudaFuncAttributeMaxDynamicSharedMemorySize, GEMM_SMEM);

    const int EB = CEILDIV(ETOT, 256);

    // layer-1 edge init + count (icount zeroed first)
    cudaMemsetAsync(icount, 0, (size_t)N1 * sizeof(int));
    edge_init_count_kernel<<<EB, 256>>>(ei, src, dst, ew, icount);

    // gcn: GEMM (aHi/aLo populated) -> buf1; CSR (icount pre-counted); agg -> buf0
    auto gcn = [&](int n, int Cin, int Cout, const float* W, const float* b) {
        convertW_kernel<<<CEILDIV(Cin * Cout, 256), 256>>>(W, wHiT, wLoT, Cin, Cout);
        wmma_gemm_kernel<<<dim3(Cout / TBN, CEILDIV(n, TBM)), 128, GEMM_SMEM>>>(
            aHi, aLo, wHiT, wLoT, buf1, n, Cin, Cout);
        int nb = CEILDIV(n, 1024);
        scan_partial_kernel<<<nb, 1024>>>(icount, rowptr, blocksum, n);
        scan_blocksums_kernel<<<1, 32>>>(blocksum, blockoff, rowptr, nb, n);
        scan_finalize_kernel<<<nb, 1024>>>(icount, rowptr, blockoff, cursor, dis, n);
        fill_kernel<<<EB, 256>>>(src, dst, ew, dis, cursor, esrc, enorm);
        if (Cout == 512)
            gather_agg_kernel<512><<<n, 128>>>(buf1, rowptr, esrc, enorm, b, buf0);
        else
            gather_agg_kernel<256><<<n, 64>>>(buf1, rowptr, esrc, enorm, b, buf0);
    };
    auto bn_pool_pre = [&](int n, int C, const float* gma, const float* bta,
                           const float* rw, const float* rb, const float* ow) {
        cudaMemsetAsync(sum, 0, C * sizeof(float));
        cudaMemsetAsync(sumsq, 0, C * sizeof(float));
        bn_stats_kernel<<<dim3(CEILDIV(C, 256), 64), 256>>>(buf0, sum, sumsq, n, C);
        bn_dots_kernel<<<CEILDIV(n * 32, 256), 256>>>(buf0, sum, sumsq, gma, bta,
                                                      rw, ow, rb, t, score, n, C);
        score_edge_kernel<<<EB, 256>>>(src, dst, ew, t, score);
        init_newid_kernel<<<CEILDIV(n, 256), 256>>>(newid, n);
    };
    auto pool_post = [&](int ksel, int C) {
        int rows = BATCH * ksel;
        gather_split_kernel<<<CEILDIV(rows * (C / 4), 256), 256>>>(
            buf0, aHi, aLo, perm, gain, rows, C / 4);
        cudaMemsetAsync(icount, 0, (size_t)rows * sizeof(int));
        remap_count_kernel<<<EB, 256>>>(src, dst, ew, newid, icount);
    };

    // ---------- Layer 1 ----------
    {
        int n4 = N1 * 512 / 4;
        convertA_kernel<<<CEILDIV(n4, 256), 256>>>((const float4*)x,
                                                   (__nv_bfloat162*)aHi,
                                                   (__nv_bfloat162*)aLo, n4);
    }
    gcn(N1, 512, 512, W1, b1);
    bn_pool_pre(N1, 512, g1, be1, p1rw, p1rb, p1ow);
    topk_kernel<1024><<<BATCH, 512>>>(score, 1024, K1, perm, gain, newid);
    pool_post(K1, 512);

    // ---------- Layer 2 ----------
    gcn(N2, 512, 512, W2, b2);
    bn_pool_pre(N2, 512, g2, be2, p2rw, p2rb, p2ow);
    topk_kernel<1024><<<BATCH, 512>>>(score, K1, K2, perm, gain, newid);
    pool_post(K2, 512);

    // ---------- Layer 3 ----------
    gcn(N3, 512, 256, W3, b3);
    bn_pool_pre(N3, 256, g3, be3, p3rw, p3rb, p3ow);
    topk_kernel<512><<<BATCH, 512>>>(score, K2, K3, perm, gain, newid);
    pool_post(K3, 256);

    // ---------- Layer 4 (no BN / pool) ----------
    gcn(N4, 256, 256, W4, b4);

    // ---------- readout ----------
    readout_kernel<<<BATCH, 256>>>(buf0, out);
    (void)in_sizes; (void)n_in; (void)out_size;
}

// round 11
// speedup vs baseline: 1.0668x; 1.0668x over previous
#include <cuda_runtime.h>
#include <cuda_bf16.h>
#include <mma.h>
#include <math.h>
#include <stdint.h>

using namespace nvcuda;

// ---------------- problem constants ----------------
#define BATCH   32
#define ETOT    262144
#define NMAX    32768
#define K1      615
#define K2      369
#define K3      185
#define N1      32768
#define N2      (BATCH*K1)      // 19680
#define N3      (BATCH*K2)      // 11808
#define N4      (BATCH*K3)      // 5920

#define CEILDIV(a,b) (((a)+(b)-1)/(b))

// ---------------- static device scratch ----------------
__device__ float g_buf0[(size_t)NMAX * 512];
__device__ float g_buf1[(size_t)NMAX * 512];
__device__ float g_dis[NMAX];
__device__ float g_score[NMAX];
__device__ float g_t[NMAX];
__device__ float g_gain[NMAX];
__device__ int   g_newid[NMAX];
__device__ int   g_perm[NMAX];
__device__ int   g_src[ETOT];
__device__ int   g_dst[ETOT];
__device__ float g_ew[ETOT];
__device__ float g_sum[512];
__device__ float g_sumsq[512];
// CSR scratch
__device__ int   g_icount[NMAX];
__device__ int   g_rowptr[NMAX + 1];
__device__ int   g_cursor[NMAX];
__device__ int   g_esrc[ETOT];
__device__ float g_enorm[ETOT];
__device__ int   g_blocksum[32];
__device__ int   g_blockoff[32];
// bf16 split-precision GEMM scratch
__device__ __nv_bfloat16 g_aHi[(size_t)NMAX * 512];
__device__ __nv_bfloat16 g_aLo[(size_t)NMAX * 512];
__device__ __nv_bfloat16 g_wHiT[512 * 512];
__device__ __nv_bfloat16 g_wLoT[512 * 512];

// ---------------- kernels ----------------

// edge init fused with layer-1 in-degree count (icount pre-zeroed)
__global__ void edge_init_count_kernel(const int* __restrict__ ei,
                                       int* __restrict__ src, int* __restrict__ dst,
                                       float* __restrict__ ew, int* __restrict__ cnt) {
    int e = blockIdx.x * blockDim.x + threadIdx.x;
    if (e >= ETOT) return;
    int d = ei[ETOT + e];
    src[e] = ei[e];
    dst[e] = d;
    ew[e]  = 1.0f;
    atomicAdd(&cnt[d], 1);
}

// ---------------- bf16 split conversion ----------------

__global__ void convertA_kernel(const float4* __restrict__ A,
                                __nv_bfloat162* __restrict__ hi2,
                                __nv_bfloat162* __restrict__ lo2, int n4) {
    int i = blockIdx.x * blockDim.x + threadIdx.x;
    if (i >= n4) return;
    float4 v = A[i];
    __nv_bfloat16 h0 = __float2bfloat16(v.x);
    __nv_bfloat16 h1 = __float2bfloat16(v.y);
    __nv_bfloat16 h2 = __float2bfloat16(v.z);
    __nv_bfloat16 h3 = __float2bfloat16(v.w);
    hi2[2 * i]     = __halves2bfloat162(h0, h1);
    hi2[2 * i + 1] = __halves2bfloat162(h2, h3);
    lo2[2 * i]     = __halves2bfloat162(__float2bfloat16(v.x - __bfloat162float(h0)),
                                        __float2bfloat16(v.y - __bfloat162float(h1)));
    lo2[2 * i + 1] = __halves2bfloat162(__float2bfloat16(v.z - __bfloat162float(h2)),
                                        __float2bfloat16(v.w - __bfloat162float(h3)));
}

// W [K,N] fp32 -> WT_hi/lo [N,K] bf16 (output-coalesced)
__global__ void convertW_kernel(const float* __restrict__ W,
                                __nv_bfloat16* __restrict__ hiT,
                                __nv_bfloat16* __restrict__ loT, int K, int N) {
    int idx = blockIdx.x * blockDim.x + threadIdx.x;
    if (idx >= K * N) return;
    int n = idx / K, k = idx - n * K;
    float v = W[k * N + n];
    __nv_bfloat16 h = __float2bfloat16(v);
    __nv_bfloat16 l = __float2bfloat16(v - __bfloat162float(h));
    hiT[idx] = h;
    loT[idx] = l;
}

// ---------------------------------------------------------------
// WMMA bf16 split-precision GEMM v4 (r9 shape + TBK=32).
// C[M,N] = A[M,K] @ B[K,N]; A as Ahi/Alo [M,K]; B transposed Bhi/Blo [N,K].
// CTA tile 128x128, 8 warps in 2(M)x4(N), warp tile 64x32 (acc 4x2).
// cp.async 2-stage pipeline, TBK=32 per stage. 2 CTAs/SM (regs ~126).
// Acc = Ahi*Bhi + Ahi*Blo + Alo*Bhi in fp32.
// ---------------------------------------------------------------
#define TBM 128
#define TBN 128
#define TBK 32
#define WLDA 40                            // 80B rows: conflict-free, 16B aligned
#define TILE_BYTES (128 * WLDA * 2)        // 10240
#define TILE_ELEMS (128 * WLDA)            // 5120
#define STAGE_BYTES (4 * TILE_BYTES)       // 40960
#define GEMM_SMEM (2 * STAGE_BYTES)        // 81920

__device__ __forceinline__ void cp16(uint32_t s, const void* g, int sz) {
    asm volatile("cp.async.cg.shared.global [%0], [%1], 16, %2;"
                 :: "r"(s), "l"(g), "r"(sz));
}

__global__ void __launch_bounds__(256, 2)
wmma_gemm_kernel(const __nv_bfloat16* __restrict__ Ahi,
                 const __nv_bfloat16* __restrict__ Alo,
                 const __nv_bfloat16* __restrict__ Bhi,
                 const __nv_bfloat16* __restrict__ Blo,
                 float* __restrict__ C, int M, int K, int N) {
    extern __shared__ __nv_bfloat16 sm[];

    const int tid = threadIdx.x;          // 256 threads, 8 warps
    const int wid = tid >> 5;
    const int warpM = wid & 1;            // 0..1
    const int warpN = wid >> 1;           // 0..3
    const int mBase = blockIdx.y * TBM;
    const int nBase = blockIdx.x * TBN;

    wmma::fragment<wmma::accumulator, 16, 16, 16, float> acc[4][2];
#pragma unroll
    for (int i = 0; i < 4; i++)
#pragma unroll
        for (int j = 0; j < 2; j++) wmma::fill_fragment(acc[i][j], 0.f);

    const uint32_t sbase = (uint32_t)__cvta_generic_to_shared(sm);
    const int row = tid >> 1;             // 0..127
    const int q0 = (tid & 1) * 2;         // chunks {0,1} or {2,3} of the 64B row
    const int grow = mBase + row;
    const int nrow = nBase + row;
    const size_t aoff = (size_t)(grow < M ? grow : 0) * K;
    const size_t boff = (size_t)nrow * K;
    const int szA = (grow < M) ? 16 : 0;
    const uint32_t srow = sbase + (uint32_t)row * (WLDA * 2);

    // stage s covers K range [kc, kc+32); each thread: 2 chunks x 4 tiles
#define LOAD_STAGE(s, kc) do { \
        uint32_t s0 = srow + (uint32_t)(s) * STAGE_BYTES; \
        _Pragma("unroll") \
        for (int qq = 0; qq < 2; qq++) { \
            int q = q0 + qq; \
            cp16(s0 + q * 16,                  Ahi + aoff + (kc) + q * 8, szA); \
            cp16(s0 + q * 16 + TILE_BYTES,     Alo + aoff + (kc) + q * 8, szA); \
            cp16(s0 + q * 16 + 2 * TILE_BYTES, Bhi + boff + (kc) + q * 8, 16); \
            cp16(s0 + q * 16 + 3 * TILE_BYTES, Blo + boff + (kc) + q * 8, 16); \
        } \
    } while (0)

    LOAD_STAGE(0, 0);
    asm volatile("cp.async.commit_group;" ::: "memory");

    const int nCh = K >> 5;
    for (int ch = 0; ch < nCh; ch++) {
        if (ch + 1 < nCh) {
            LOAD_STAGE((ch + 1) & 1, (ch + 1) << 5);
            asm volatile("cp.async.commit_group;" ::: "memory");
            asm volatile("cp.async.wait_group 1;" ::: "memory");
        } else {
            asm volatile("cp.async.wait_group 0;" ::: "memory");
        }
        __syncthreads();

        const __nv_bfloat16* sb   = sm + (ch & 1) * (4 * TILE_ELEMS);
        const __nv_bfloat16* sAhi = sb;
        const __nv_bfloat16* sAlo = sb + TILE_ELEMS;
        const __nv_bfloat16* sBhi = sb + 2 * TILE_ELEMS;
        const __nv_bfloat16* sBlo = sb + 3 * TILE_ELEMS;

#pragma unroll
        for (int ks = 0; ks < TBK; ks += 16) {
            wmma::fragment<wmma::matrix_b, 16, 16, 16, __nv_bfloat16, wmma::col_major> bh[2], bl[2];
#pragma unroll
            for (int j = 0; j < 2; j++) {
                wmma::load_matrix_sync(bh[j], sBhi + (warpN * 32 + j * 16) * WLDA + ks, WLDA);
                wmma::load_matrix_sync(bl[j], sBlo + (warpN * 32 + j * 16) * WLDA + ks, WLDA);
            }
#pragma unroll
            for (int i = 0; i < 4; i++) {
                wmma::fragment<wmma::matrix_a, 16, 16, 16, __nv_bfloat16, wmma::row_major> ah, al;
                wmma::load_matrix_sync(ah, sAhi + (warpM * 64 + i * 16) * WLDA + ks, WLDA);
                wmma::load_matrix_sync(al, sAlo + (warpM * 64 + i * 16) * WLDA + ks, WLDA);
#pragma unroll
                for (int j = 0; j < 2; j++) wmma::mma_sync(acc[i][j], ah, bh[j], acc[i][j]);
#pragma unroll
                for (int j = 0; j < 2; j++) wmma::mma_sync(acc[i][j], ah, bl[j], acc[i][j]);
#pragma unroll
                for (int j = 0; j < 2; j++) wmma::mma_sync(acc[i][j], al, bh[j], acc[i][j]);
            }
        }
        __syncthreads();
    }
#undef LOAD_STAGE

#pragma unroll
    for (int i = 0; i < 4; i++) {
        int r0 = mBase + warpM * 64 + i * 16;
#pragma unroll
        for (int j = 0; j < 2; j++) {
            float* cp = C + (size_t)r0 * N + nBase + warpN * 32 + j * 16;
            wmma::store_matrix_sync(cp, acc[i][j], N, wmma::mem_row_major);
        }
    }
}

// ---------------- CSR build ----------------

__global__ void __launch_bounds__(1024)
scan_partial_kernel(const int* __restrict__ cnt, int* __restrict__ rowptr,
                    int* __restrict__ blocksum, int n) {
    __shared__ int warpsum[32];
    const int tid = threadIdx.x;
    const int i = blockIdx.x * 1024 + tid;
    int v = (i < n) ? cnt[i] : 0;
    const int s = v;

    const int lane = tid & 31, wid = tid >> 5;
#pragma unroll
    for (int off = 1; off < 32; off <<= 1) {
        int u = __shfl_up_sync(0xffffffffu, v, off);
        if (lane >= off) v += u;
    }
    if (lane == 31) warpsum[wid] = v;
    __syncthreads();
    if (wid == 0) {
        int w = warpsum[lane];
#pragma unroll
        for (int off = 1; off < 32; off <<= 1) {
            int u = __shfl_up_sync(0xffffffffu, w, off);
            if (lane >= off) w += u;
        }
        warpsum[lane] = w;
    }
    __syncthreads();
    int excl = v - s + (wid > 0 ? warpsum[wid - 1] : 0);
    if (i < n) rowptr[i] = excl;
    if (tid == 1023) blocksum[blockIdx.x] = excl + s;
}

__global__ void scan_blocksums_kernel(const int* __restrict__ blocksum,
                                      int* __restrict__ blockoff,
                                      int* __restrict__ rowptr,
                                      int nblocks, int n) {
    const int lane = threadIdx.x;
    int v = (lane < nblocks) ? blocksum[lane] : 0;
    const int s = v;
#pragma unroll
    for (int off = 1; off < 32; off <<= 1) {
        int u = __shfl_up_sync(0xffffffffu, v, off);
        if (lane >= off) v += u;
    }
    if (lane < nblocks) blockoff[lane] = v - s;
    if (lane == 31) rowptr[n] = v;
}

__global__ void __launch_bounds__(1024)
scan_finalize_kernel(const int* __restrict__ cnt, int* __restrict__ rowptr,
                     const int* __restrict__ blockoff,
                     int* __restrict__ cursor, float* __restrict__ dis, int n) {
    const int i = blockIdx.x * 1024 + threadIdx.x;
    if (i >= n) return;
    int r = rowptr[i] + blockoff[blockIdx.x];
    rowptr[i] = r;
    cursor[i] = r;
    int c = cnt[i];
    dis[i] = (c > 0) ? rsqrtf((float)c) : 0.f;
}

__global__ void fill_kernel(const int* __restrict__ src, const int* __restrict__ dst,
                            const float* __restrict__ ew, const float* __restrict__ dis,
                            int* __restrict__ cursor,
                            int* __restrict__ esrc, float* __restrict__ enorm) {
    int e = blockIdx.x * blockDim.x + threadIdx.x;
    if (e >= ETOT) return;
    float w = ew[e];
    if (w == 0.f) return;
    int s = src[e], d = dst[e];
    int pos = atomicAdd(&cursor[d], 1);
    esrc[pos] = s;
    enorm[pos] = dis[s] * dis[d] * w;
}

template <int C>
__global__ void gather_agg_kernel(const float* __restrict__ h,
                                  const int* __restrict__ rowptr,
                                  const int* __restrict__ esrc,
                                  const float* __restrict__ enorm,
                                  const float* __restrict__ bias,
                                  float* __restrict__ out) {
    const int node = blockIdx.x;
    const int tid = threadIdx.x;
    float4 acc = *(const float4*)(bias + tid * 4);
    int b = rowptr[node];
    const int e = rowptr[node + 1];
    for (; b + 1 < e; b += 2) {
        int s0 = esrc[b],     s1 = esrc[b + 1];
        float n0 = enorm[b],  n1 = enorm[b + 1];
        float4 v0 = *(const float4*)(h + (size_t)s0 * C + tid * 4);
        float4 v1 = *(const float4*)(h + (size_t)s1 * C + tid * 4);
        acc.x += v0.x * n0; acc.y += v0.y * n0; acc.z += v0.z * n0; acc.w += v0.w * n0;
        acc.x += v1.x * n1; acc.y += v1.y * n1; acc.z += v1.z * n1; acc.w += v1.w * n1;
    }
    if (b < e) {
        int s0 = esrc[b];
        float n0 = enorm[b];
        float4 v0 = *(const float4*)(h + (size_t)s0 * C + tid * 4);
        acc.x += v0.x * n0; acc.y += v0.y * n0; acc.z += v0.z * n0; acc.w += v0.w * n0;
    }
    *(float4*)(out + (size_t)node * C + tid * 4) = acc;
}

// ---------------- BN / pool / misc ----------------

__global__ void bn_stats_kernel(const float* __restrict__ h,
                                float* __restrict__ sum, float* __restrict__ sumsq,
                                int n, int C) {
    int c = blockIdx.x * 256 + threadIdx.x;
    if (c >= C) return;
    int rowsPer = CEILDIV(n, gridDim.y);
    int r0 = blockIdx.y * rowsPer;
    int r1 = min(n, r0 + rowsPer);
    float s = 0.f, sq = 0.f;
    for (int r = r0; r < r1; r++) {
        float v = h[(size_t)r * C + c];
        s += v;
        sq += v * v;
    }
    atomicAdd(&sum[c], s);
    atomicAdd(&sumsq[c], sq);
}

// fused BN(apply)+tanh + pool dot-products; warp per node
__global__ void bn_dots_kernel(float* __restrict__ h,
                               const float* __restrict__ sum, const float* __restrict__ sumsq,
                               const float* __restrict__ gma, const float* __restrict__ bta,
                               const float* __restrict__ relw, const float* __restrict__ rootw,
                               const float* __restrict__ relb,
                               float* __restrict__ t, float* __restrict__ score,
                               int n, int C) {
    int node = (blockIdx.x * blockDim.x + threadIdx.x) >> 5;
    int lane = threadIdx.x & 31;
    if (node >= n) return;
    float* hp = h + (size_t)node * C;
    const float invn = 1.f / (float)n;
    float a = 0.f, b = 0.f;
    for (int c = lane; c < C; c += 32) {
        float mean = sum[c] * invn;
        float var = sumsq[c] * invn - mean * mean;
        float y = tanhf((hp[c] - mean) * rsqrtf(var + 1e-5f) * gma[c] + bta[c]);
        hp[c] = y;
        a += y * relw[c];
        b += y * rootw[c];
    }
#pragma unroll
    for (int o = 16; o > 0; o >>= 1) {
        a += __shfl_down_sync(0xffffffffu, a, o);
        b += __shfl_down_sync(0xffffffffu, b, o);
    }
    if (lane == 0) {
        t[node] = a;
        score[node] = b + relb[0];
    }
}

__global__ void score_edge_kernel(const int* __restrict__ src, const int* __restrict__ dst,
                                  const float* __restrict__ ew, const float* __restrict__ t,
                                  float* __restrict__ score) {
    int e = blockIdx.x * blockDim.x + threadIdx.x;
    if (e >= ETOT) return;
    float w = ew[e];
    if (w != 0.f) atomicAdd(&score[dst[e]], w * t[src[e]]);
}

__global__ void init_newid_kernel(int* __restrict__ newid, int n) {
    int i = blockIdx.x * blockDim.x + threadIdx.x;
    if (i < n) newid[i] = -1;
}

template <int SZ>
__global__ void __launch_bounds__(512)
topk_kernel(const float* __restrict__ score, int n_per, int ksel,
            int* __restrict__ perm, float* __restrict__ gain, int* __restrict__ newid) {
    __shared__ float sk[SZ];
    __shared__ int si[SZ];
    const int g = blockIdx.x;
    const int tid = threadIdx.x;
    for (int i = tid; i < SZ; i += 512) {
        if (i < n_per) { sk[i] = score[g * n_per + i]; si[i] = i; }
        else           { sk[i] = -INFINITY;            si[i] = 0x40000000 + i; }
    }
    __syncthreads();
    for (int kk = 2; kk <= SZ; kk <<= 1) {
        for (int j = kk >> 1; j > 0; j >>= 1) {
            for (int i = tid; i < SZ; i += 512) {
                int ixj = i ^ j;
                if (ixj > i) {
                    bool up = ((i & kk) == 0);
                    float s1 = sk[i], s2 = sk[ixj];
                    int i1 = si[i], i2 = si[ixj];
                    bool after = (s1 < s2) || (s1 == s2 && i1 > i2);
                    if (up == after) {
                        sk[i] = s2; sk[ixj] = s1;
                        si[i] = i2; si[ixj] = i1;
                    }
                }
            }
            __syncthreads();
        }
    }
    for (int r = tid; r < ksel; r += 512) {
        int old = g * n_per + si[r];
        int ng = g * ksel + r;
        perm[ng] = old;
        gain[ng] = tanhf(sk[r]);
        newid[old] = ng;
    }
}

// pool gather fused with bf16 hi/lo split: x_new = h[perm]*tanh(score[perm])
__global__ void gather_split_kernel(const float* __restrict__ hin,
                                    __nv_bfloat16* __restrict__ hi,
                                    __nv_bfloat16* __restrict__ lo,
                                    const int* __restrict__ perm,
                                    const float* __restrict__ gain,
                                    int rows, int C4) {
    int idx = blockIdx.x * blockDim.x + threadIdx.x;
    if (idx >= rows * C4) return;
    int row = idx / C4;
    int c = idx - row * C4;
    float gn = gain[row];
    float4 v = ((const float4*)hin)[(size_t)perm[row] * C4 + c];
    v.x *= gn; v.y *= gn; v.z *= gn; v.w *= gn;
    __nv_bfloat16 h0 = __float2bfloat16(v.x);
    __nv_bfloat16 h1 = __float2bfloat16(v.y);
    __nv_bfloat16 h2 = __float2bfloat16(v.z);
    __nv_bfloat16 h3 = __float2bfloat16(v.w);
    __nv_bfloat162* hp = (__nv_bfloat162*)(hi) + 2 * idx;
    __nv_bfloat162* lp = (__nv_bfloat162*)(lo) + 2 * idx;
    hp[0] = __halves2bfloat162(h0, h1);
    hp[1] = __halves2bfloat162(h2, h3);
    lp[0] = __halves2bfloat162(__float2bfloat16(v.x - __bfloat162float(h0)),
                               __float2bfloat16(v.y - __bfloat162float(h1)));
    lp[1] = __halves2bfloat162(__float2bfloat16(v.z - __bfloat162float(h2)),
                               __float2bfloat16(v.w - __bfloat162float(h3)));
}

// remap fused with next layer's in-degree count (icount pre-zeroed)
__global__ void remap_count_kernel(int* __restrict__ src, int* __restrict__ dst,
                                   float* __restrict__ ew, const int* __restrict__ newid,
                                   int* __restrict__ cnt) {
    int e = blockIdx.x * blockDim.x + threadIdx.x;
    if (e >= ETOT) return;
    int ns = newid[src[e]];
    int nd = newid[dst[e]];
    bool keep = (ns >= 0) && (nd >= 0) && (ew[e] != 0.f);
    src[e] = keep ? ns : 0;
    dst[e] = keep ? nd : 0;
    ew[e] = keep ? ew[e] : 0.f;
    if (keep) atomicAdd(&cnt[nd], 1);
}

__global__ void readout_kernel(const float* __restrict__ h, float* __restrict__ out) {
    int g = blockIdx.x;
    int c = threadIdx.x;
    const float* p = h + (size_t)(g * K3) * 256 + c;
    float mx = -INFINITY, sm = 0.f;
    for (int i = 0; i < K3; i++) {
        float v = p[(size_t)i * 256];
        mx = fmaxf(mx, v);
        sm += v;
    }
    out[g * 512 + c] = mx;
    out[g * 512 + 256 + c] = sm / (float)K3;
}

// ---------------- host orchestration ----------------

extern "C" void kernel_launch(void* const* d_in, const int* in_sizes, int n_in,
                              void* d_out, int out_size) {
    const float* x    = (const float*)d_in[0];
    const int*   ei   = (const int*)d_in[1];
    const float* W1   = (const float*)d_in[2];
    const float* b1   = (const float*)d_in[3];
    const float* W2   = (const float*)d_in[4];
    const float* b2   = (const float*)d_in[5];
    const float* W3   = (const float*)d_in[6];
    const float* b3   = (const float*)d_in[7];
    const float* W4   = (const float*)d_in[8];
    const float* b4   = (const float*)d_in[9];
    const float* g1   = (const float*)d_in[10];
    const float* be1  = (const float*)d_in[11];
    const float* g2   = (const float*)d_in[12];
    const float* be2  = (const float*)d_in[13];
    const float* g3   = (const float*)d_in[14];
    const float* be3  = (const float*)d_in[15];
    const float* p1rw = (const float*)d_in[16];
    const float* p1rb = (const float*)d_in[17];
    const float* p1ow = (const float*)d_in[18];
    const float* p2rw = (const float*)d_in[19];
    const float* p2rb = (const float*)d_in[20];
    const float* p2ow = (const float*)d_in[21];
    const float* p3rw = (const float*)d_in[22];
    const float* p3rb = (const float*)d_in[23];
    const float* p3ow = (const float*)d_in[24];
    float* out = (float*)d_out;

    float *buf0, *buf1, *dis, *score, *t, *gain, *ew, *sum, *sumsq, *enorm;
    int *src, *dst, *newid, *perm, *icount, *rowptr, *cursor, *esrc, *blocksum, *blockoff;
    __nv_bfloat16 *aHi, *aLo, *wHiT, *wLoT;
    cudaGetSymbolAddress((void**)&buf0, g_buf0);
    cudaGetSymbolAddress((void**)&buf1, g_buf1);
    cudaGetSymbolAddress((void**)&dis, g_dis);
    cudaGetSymbolAddress((void**)&score, g_score);
    cudaGetSymbolAddress((void**)&t, g_t);
    cudaGetSymbolAddress((void**)&gain, g_gain);
    cudaGetSymbolAddress((void**)&ew, g_ew);
    cudaGetSymbolAddress((void**)&sum, g_sum);
    cudaGetSymbolAddress((void**)&sumsq, g_sumsq);
    cudaGetSymbolAddress((void**)&src, g_src);
    cudaGetSymbolAddress((void**)&dst, g_dst);
    cudaGetSymbolAddress((void**)&newid, g_newid);
    cudaGetSymbolAddress((void**)&perm, g_perm);
    cudaGetSymbolAddress((void**)&icount, g_icount);
    cudaGetSymbolAddress((void**)&rowptr, g_rowptr);
    cudaGetSymbolAddress((void**)&cursor, g_cursor);
    cudaGetSymbolAddress((void**)&esrc, g_esrc);
    cudaGetSymbolAddress((void**)&enorm, g_enorm);
    cudaGetSymbolAddress((void**)&blocksum, g_blocksum);
    cudaGetSymbolAddress((void**)&blockoff, g_blockoff);
    cudaGetSymbolAddress((void**)&aHi, g_aHi);
    cudaGetSymbolAddress((void**)&aLo, g_aLo);
    cudaGetSymbolAddress((void**)&wHiT, g_wHiT);
    cudaGetSymbolAddress((void**)&wLoT, g_wLoT);

    cudaFuncSetAttribute(wmma_gemm_kernel,
                         cudaFuncAttributeMaxDynamicSharedMemorySize, GEMM_SMEM);

    const int EB = CEILDIV(ETOT, 256);

    // layer-1 edge init + count (icount zeroed first)
    cudaMemsetAsync(icount, 0, (size_t)N1 * sizeof(int));
    edge_init_count_kernel<<<EB, 256>>>(ei, src, dst, ew, icount);

    // gcn: GEMM (aHi/aLo populated) -> buf1; CSR (icount pre-counted); agg -> buf0
    auto gcn = [&](int n, int Cin, int Cout, const float* W, const float* b) {
        convertW_kernel<<<CEILDIV(Cin * Cout, 256), 256>>>(W, wHiT, wLoT, Cin, Cout);
        wmma_gemm_kernel<<<dim3(Cout / TBN, CEILDIV(n, TBM)), 256, GEMM_SMEM>>>(
            aHi, aLo, wHiT, wLoT, buf1, n, Cin, Cout);
        int nb = CEILDIV(n, 1024);
        scan_partial_kernel<<<nb, 1024>>>(icount, rowptr, blocksum, n);
        scan_blocksums_kernel<<<1, 32>>>(blocksum, blockoff, rowptr, nb, n);
        scan_finalize_kernel<<<nb, 1024>>>(icount, rowptr, blockoff, cursor, dis, n);
        fill_kernel<<<EB, 256>>>(src, dst, ew, dis, cursor, esrc, enorm);
        if (Cout == 512)
            gather_agg_kernel<512><<<n, 128>>>(buf1, rowptr, esrc, enorm, b, buf0);
        else
            gather_agg_kernel<256><<<n, 64>>>(buf1, rowptr, esrc, enorm, b, buf0);
    };
    auto bn_pool_pre = [&](int n, int C, const float* gma, const float* bta,
                           const float* rw, const float* rb, const float* ow) {
        cudaMemsetAsync(sum, 0, C * sizeof(float));
        cudaMemsetAsync(sumsq, 0, C * sizeof(float));
        bn_stats_kernel<<<dim3(CEILDIV(C, 256), 64), 256>>>(buf0, sum, sumsq, n, C);
        bn_dots_kernel<<<CEILDIV(n * 32, 256), 256>>>(buf0, sum, sumsq, gma, bta,
                                                      rw, ow, rb, t, score, n, C);
        score_edge_kernel<<<EB, 256>>>(src, dst, ew, t, score);
        init_newid_kernel<<<CEILDIV(n, 256), 256>>>(newid, n);
    };
    auto pool_post = [&](int ksel, int C) {
        int rows = BATCH * ksel;
        gather_split_kernel<<<CEILDIV(rows * (C / 4), 256), 256>>>(
            buf0, aHi, aLo, perm, gain, rows, C / 4);
        cudaMemsetAsync(icount, 0, (size_t)rows * sizeof(int));
        remap_count_kernel<<<EB, 256>>>(src, dst, ew, newid, icount);
    };

    // ---------- Layer 1 ----------
    {
        int n4 = N1 * 512 / 4;
        convertA_kernel<<<CEILDIV(n4, 256), 256>>>((const float4*)x,
                                                   (__nv_bfloat162*)aHi,
                                                   (__nv_bfloat162*)aLo, n4);
    }
    gcn(N1, 512, 512, W1, b1);
    bn_pool_pre(N1, 512, g1, be1, p1rw, p1rb, p1ow);
    topk_kernel<1024><<<BATCH, 512>>>(score, 1024, K1, perm, gain, newid);
    pool_post(K1, 512);

    // ---------- Layer 2 ----------
    gcn(N2, 512, 512, W2, b2);
    bn_pool_pre(N2, 512, g2, be2, p2rw, p2rb, p2ow);
    topk_kernel<1024><<<BATCH, 512>>>(score, K1, K2, perm, gain, newid);
    pool_post(K2, 512);

    // ---------- Layer 3 ----------
    gcn(N3, 512, 256, W3, b3);
    bn_pool_pre(N3, 256, g3, be3, p3rw, p3rb, p3ow);
    topk_kernel<512><<<BATCH, 512>>>(score, K2, K3, perm, gain, newid);
    pool_post(K3, 256);

    // ---------- Layer 4 (no BN / pool) ----------
    gcn(N4, 256, 256, W4, b4);

    // ---------- readout ----------
    readout_kernel<<<BATCH, 256>>>(buf0, out);
    (void)in_sizes; (void)n_in; (void)out_size;
}

// round 12
// speedup vs baseline: 1.1115x; 1.0419x over previous
#include <cuda_runtime.h>
#include <cuda_bf16.h>
#include <mma.h>
#include <math.h>
#include <stdint.h>

using namespace nvcuda;

// ---------------- problem constants ----------------
#define BATCH   32
#define ETOT    262144
#define NMAX    32768
#define K1      615
#define K2      369
#define K3      185
#define N1      32768
#define N2      (BATCH*K1)      // 19680
#define N3      (BATCH*K2)      // 11808
#define N4      (BATCH*K3)      // 5920

#define CEILDIV(a,b) (((a)+(b)-1)/(b))

// ---------------- static device scratch ----------------
__device__ float g_buf0[(size_t)NMAX * 512];
__device__ float g_buf1[(size_t)NMAX * 512];
__device__ float g_dis[NMAX];
__device__ float g_score[NMAX];
__device__ float g_t[NMAX];
__device__ float g_gain[NMAX];
__device__ int   g_newid[NMAX];
__device__ int   g_perm[NMAX];
__device__ int   g_src[ETOT];
__device__ int   g_dst[ETOT];
__device__ float g_ew[ETOT];
__device__ float g_bnstats[1024];          // [0:512) sum, [512:1024) sumsq
// CSR scratch
__device__ int   g_icount[NMAX];
__device__ int   g_rowptr[NMAX + 1];
__device__ int   g_cursor[NMAX];
__device__ int   g_esrc[ETOT];
__device__ float g_enorm[ETOT];
__device__ int   g_blocksum[32];
__device__ int   g_blockoff[32];
// bf16 split-precision GEMM scratch
__device__ __nv_bfloat16 g_aHi[(size_t)NMAX * 512];
__device__ __nv_bfloat16 g_aLo[(size_t)NMAX * 512];
__device__ __nv_bfloat16 g_w1Hi[512 * 512], g_w1Lo[512 * 512];
__device__ __nv_bfloat16 g_w2Hi[512 * 512], g_w2Lo[512 * 512];
__device__ __nv_bfloat16 g_w3Hi[256 * 512], g_w3Lo[256 * 512];
__device__ __nv_bfloat16 g_w4Hi[256 * 256], g_w4Lo[256 * 256];

// ---------------- kernels ----------------

// edge init fused with layer-1 in-degree count (icount zeroed by convertA)
__global__ void edge_init_count_kernel(const int* __restrict__ ei,
                                       int* __restrict__ src, int* __restrict__ dst,
                                       float* __restrict__ ew, int* __restrict__ cnt) {
    int e = blockIdx.x * blockDim.x + threadIdx.x;
    if (e >= ETOT) return;
    int d = ei[ETOT + e];
    src[e] = ei[e];
    dst[e] = d;
    ew[e]  = 1.0f;
    atomicAdd(&cnt[d], 1);
}

// ---------------- bf16 split conversion ----------------

// layer-1 activations; also zeroes icount[0:N1)
__global__ void convertA_kernel(const float4* __restrict__ A,
                                __nv_bfloat162* __restrict__ hi2,
                                __nv_bfloat162* __restrict__ lo2, int n4,
                                int* __restrict__ icount) {
    int i = blockIdx.x * blockDim.x + threadIdx.x;
    if (i >= n4) return;
    if (i < N1) icount[i] = 0;
    float4 v = A[i];
    __nv_bfloat16 h0 = __float2bfloat16(v.x);
    __nv_bfloat16 h1 = __float2bfloat16(v.y);
    __nv_bfloat16 h2 = __float2bfloat16(v.z);
    __nv_bfloat16 h3 = __float2bfloat16(v.w);
    hi2[2 * i]     = __halves2bfloat162(h0, h1);
    hi2[2 * i + 1] = __halves2bfloat162(h2, h3);
    lo2[2 * i]     = __halves2bfloat162(__float2bfloat16(v.x - __bfloat162float(h0)),
                                        __float2bfloat16(v.y - __bfloat162float(h1)));
    lo2[2 * i + 1] = __halves2bfloat162(__float2bfloat16(v.z - __bfloat162float(h2)),
                                        __float2bfloat16(v.w - __bfloat162float(h3)));
}

// all 4 weight matrices: W [K,N] fp32 -> WT_hi/lo [N,K] bf16, one kernel
#define W1_ELEMS (512 * 512)
#define W2_END   (2 * W1_ELEMS)
#define W3_END   (W2_END + 256 * 512)
#define W4_END   (W3_END + 256 * 256)
__global__ void convertW_all_kernel(const float* __restrict__ W1, const float* __restrict__ W2,
                                    const float* __restrict__ W3, const float* __restrict__ W4,
                                    __nv_bfloat16* w1h, __nv_bfloat16* w1l,
                                    __nv_bfloat16* w2h, __nv_bfloat16* w2l,
                                    __nv_bfloat16* w3h, __nv_bfloat16* w3l,
                                    __nv_bfloat16* w4h, __nv_bfloat16* w4l) {
    int idx = blockIdx.x * blockDim.x + threadIdx.x;
    const float* W; __nv_bfloat16 *h, *l; int K, N, local;
    if (idx < W1_ELEMS)      { W = W1; h = w1h; l = w1l; K = 512; N = 512; local = idx; }
    else if (idx < W2_END)   { W = W2; h = w2h; l = w2l; K = 512; N = 512; local = idx - W1_ELEMS; }
    else if (idx < W3_END)   { W = W3; h = w3h; l = w3l; K = 512; N = 256; local = idx - W2_END; }
    else if (idx < W4_END)   { W = W4; h = w4h; l = w4l; K = 256; N = 256; local = idx - W3_END; }
    else return;
    int n = local / K, k = local - n * K;
    float v = W[k * N + n];
    __nv_bfloat16 hh = __float2bfloat16(v);
    h[local] = hh;
    l[local] = __float2bfloat16(v - __bfloat162float(hh));
}

// ---------------------------------------------------------------
// WMMA bf16 split-precision GEMM (r11 config — unchanged).
// ---------------------------------------------------------------
#define TBM 128
#define TBN 128
#define TBK 32
#define WLDA 40
#define TILE_BYTES (128 * WLDA * 2)        // 10240
#define TILE_ELEMS (128 * WLDA)            // 5120
#define STAGE_BYTES (4 * TILE_BYTES)       // 40960
#define GEMM_SMEM (2 * STAGE_BYTES)        // 81920

__device__ __forceinline__ void cp16(uint32_t s, const void* g, int sz) {
    asm volatile("cp.async.cg.shared.global [%0], [%1], 16, %2;"
                 :: "r"(s), "l"(g), "r"(sz));
}

__global__ void __launch_bounds__(256, 2)
wmma_gemm_kernel(const __nv_bfloat16* __restrict__ Ahi,
                 const __nv_bfloat16* __restrict__ Alo,
                 const __nv_bfloat16* __restrict__ Bhi,
                 const __nv_bfloat16* __restrict__ Blo,
                 float* __restrict__ C, int M, int K, int N) {
    extern __shared__ __nv_bfloat16 sm[];

    const int tid = threadIdx.x;
    const int wid = tid >> 5;
    const int warpM = wid & 1;
    const int warpN = wid >> 1;
    const int mBase = blockIdx.y * TBM;
    const int nBase = blockIdx.x * TBN;

    wmma::fragment<wmma::accumulator, 16, 16, 16, float> acc[4][2];
#pragma unroll
    for (int i = 0; i < 4; i++)
#pragma unroll
        for (int j = 0; j < 2; j++) wmma::fill_fragment(acc[i][j], 0.f);

    const uint32_t sbase = (uint32_t)__cvta_generic_to_shared(sm);
    const int row = tid >> 1;
    const int q0 = (tid & 1) * 2;
    const int grow = mBase + row;
    const int nrow = nBase + row;
    const size_t aoff = (size_t)(grow < M ? grow : 0) * K;
    const size_t boff = (size_t)nrow * K;
    const int szA = (grow < M) ? 16 : 0;
    const uint32_t srow = sbase + (uint32_t)row * (WLDA * 2);

#define LOAD_STAGE(s, kc) do { \
        uint32_t s0 = srow + (uint32_t)(s) * STAGE_BYTES; \
        _Pragma("unroll") \
        for (int qq = 0; qq < 2; qq++) { \
            int q = q0 + qq; \
            cp16(s0 + q * 16,                  Ahi + aoff + (kc) + q * 8, szA); \
            cp16(s0 + q * 16 + TILE_BYTES,     Alo + aoff + (kc) + q * 8, szA); \
            cp16(s0 + q * 16 + 2 * TILE_BYTES, Bhi + boff + (kc) + q * 8, 16); \
            cp16(s0 + q * 16 + 3 * TILE_BYTES, Blo + boff + (kc) + q * 8, 16); \
        } \
    } while (0)

    LOAD_STAGE(0, 0);
    asm volatile("cp.async.commit_group;" ::: "memory");

    const int nCh = K >> 5;
    for (int ch = 0; ch < nCh; ch++) {
        if (ch + 1 < nCh) {
            LOAD_STAGE((ch + 1) & 1, (ch + 1) << 5);
            asm volatile("cp.async.commit_group;" ::: "memory");
            asm volatile("cp.async.wait_group 1;" ::: "memory");
        } else {
            asm volatile("cp.async.wait_group 0;" ::: "memory");
        }
        __syncthreads();

        const __nv_bfloat16* sb   = sm + (ch & 1) * (4 * TILE_ELEMS);
        const __nv_bfloat16* sAhi = sb;
        const __nv_bfloat16* sAlo = sb + TILE_ELEMS;
        const __nv_bfloat16* sBhi = sb + 2 * TILE_ELEMS;
        const __nv_bfloat16* sBlo = sb + 3 * TILE_ELEMS;

#pragma unroll
        for (int ks = 0; ks < TBK; ks += 16) {
            wmma::fragment<wmma::matrix_b, 16, 16, 16, __nv_bfloat16, wmma::col_major> bh[2], bl[2];
#pragma unroll
            for (int j = 0; j < 2; j++) {
                wmma::load_matrix_sync(bh[j], sBhi + (warpN * 32 + j * 16) * WLDA + ks, WLDA);
                wmma::load_matrix_sync(bl[j], sBlo + (warpN * 32 + j * 16) * WLDA + ks, WLDA);
            }
#pragma unroll
            for (int i = 0; i < 4; i++) {
                wmma::fragment<wmma::matrix_a, 16, 16, 16, __nv_bfloat16, wmma::row_major> ah, al;
                wmma::load_matrix_sync(ah, sAhi + (warpM * 64 + i * 16) * WLDA + ks, WLDA);
                wmma::load_matrix_sync(al, sAlo + (warpM * 64 + i * 16) * WLDA + ks, WLDA);
#pragma unroll
                for (int j = 0; j < 2; j++) wmma::mma_sync(acc[i][j], ah, bh[j], acc[i][j]);
#pragma unroll
                for (int j = 0; j < 2; j++) wmma::mma_sync(acc[i][j], ah, bl[j], acc[i][j]);
#pragma unroll
                for (int j = 0; j < 2; j++) wmma::mma_sync(acc[i][j], al, bh[j], acc[i][j]);
            }
        }
        __syncthreads();
    }
#undef LOAD_STAGE

#pragma unroll
    for (int i = 0; i < 4; i++) {
        int r0 = mBase + warpM * 64 + i * 16;
#pragma unroll
        for (int j = 0; j < 2; j++) {
            float* cp = C + (size_t)r0 * N + nBase + warpN * 32 + j * 16;
            wmma::store_matrix_sync(cp, acc[i][j], N, wmma::mem_row_major);
        }
    }
}

// ---------------- CSR build ----------------

__global__ void __launch_bounds__(1024)
scan_partial_kernel(const int* __restrict__ cnt, int* __restrict__ rowptr,
                    int* __restrict__ blocksum, int n) {
    __shared__ int warpsum[32];
    const int tid = threadIdx.x;
    const int i = blockIdx.x * 1024 + tid;
    int v = (i < n) ? cnt[i] : 0;
    const int s = v;

    const int lane = tid & 31, wid = tid >> 5;
#pragma unroll
    for (int off = 1; off < 32; off <<= 1) {
        int u = __shfl_up_sync(0xffffffffu, v, off);
        if (lane >= off) v += u;
    }
    if (lane == 31) warpsum[wid] = v;
    __syncthreads();
    if (wid == 0) {
        int w = warpsum[lane];
#pragma unroll
        for (int off = 1; off < 32; off <<= 1) {
            int u = __shfl_up_sync(0xffffffffu, w, off);
            if (lane >= off) w += u;
        }
        warpsum[lane] = w;
    }
    __syncthreads();
    int excl = v - s + (wid > 0 ? warpsum[wid - 1] : 0);
    if (i < n) rowptr[i] = excl;
    if (tid == 1023) blocksum[blockIdx.x] = excl + s;
}

__global__ void scan_blocksums_kernel(const int* __restrict__ blocksum,
                                      int* __restrict__ blockoff,
                                      int* __restrict__ rowptr,
                                      int nblocks, int n) {
    const int lane = threadIdx.x;
    int v = (lane < nblocks) ? blocksum[lane] : 0;
    const int s = v;
#pragma unroll
    for (int off = 1; off < 32; off <<= 1) {
        int u = __shfl_up_sync(0xffffffffu, v, off);
        if (lane >= off) v += u;
    }
    if (lane < nblocks) blockoff[lane] = v - s;
    if (lane == 31) rowptr[n] = v;
}

// finalize + newid init fused
__global__ void __launch_bounds__(1024)
scan_finalize_kernel(const int* __restrict__ cnt, int* __restrict__ rowptr,
                     const int* __restrict__ blockoff,
                     int* __restrict__ cursor, float* __restrict__ dis,
                     int* __restrict__ newid, int n) {
    const int i = blockIdx.x * 1024 + threadIdx.x;
    if (i >= n) return;
    int r = rowptr[i] + blockoff[blockIdx.x];
    rowptr[i] = r;
    cursor[i] = r;
    int c = cnt[i];
    dis[i] = (c > 0) ? rsqrtf((float)c) : 0.f;
    newid[i] = -1;
}

__global__ void fill_kernel(const int* __restrict__ src, const int* __restrict__ dst,
                            const float* __restrict__ ew, const float* __restrict__ dis,
                            int* __restrict__ cursor,
                            int* __restrict__ esrc, float* __restrict__ enorm) {
    int e = blockIdx.x * blockDim.x + threadIdx.x;
    if (e >= ETOT) return;
    float w = ew[e];
    if (w == 0.f) return;
    int s = src[e], d = dst[e];
    int pos = atomicAdd(&cursor[d], 1);
    esrc[pos] = s;
    enorm[pos] = dis[s] * dis[d] * w;
}

// one block per node, C/4 threads; block 0 also zeroes bnstats
template <int C>
__global__ void gather_agg_kernel(const float* __restrict__ h,
                                  const int* __restrict__ rowptr,
                                  const int* __restrict__ esrc,
                                  const float* __restrict__ enorm,
                                  const float* __restrict__ bias,
                                  float* __restrict__ out,
                                  float* __restrict__ bnstats) {
    const int node = blockIdx.x;
    const int tid = threadIdx.x;
    if (node == 0)
        for (int k = tid; k < 1024; k += (C / 4)) bnstats[k] = 0.f;
    float4 acc = *(const float4*)(bias + tid * 4);
    int b = rowptr[node];
    const int e = rowptr[node + 1];
    for (; b + 1 < e; b += 2) {
        int s0 = esrc[b],     s1 = esrc[b + 1];
        float n0 = enorm[b],  n1 = enorm[b + 1];
        float4 v0 = *(const float4*)(h + (size_t)s0 * C + tid * 4);
        float4 v1 = *(const float4*)(h + (size_t)s1 * C + tid * 4);
        acc.x += v0.x * n0; acc.y += v0.y * n0; acc.z += v0.z * n0; acc.w += v0.w * n0;
        acc.x += v1.x * n1; acc.y += v1.y * n1; acc.z += v1.z * n1; acc.w += v1.w * n1;
    }
    if (b < e) {
        int s0 = esrc[b];
        float n0 = enorm[b];
        float4 v0 = *(const float4*)(h + (size_t)s0 * C + tid * 4);
        acc.x += v0.x * n0; acc.y += v0.y * n0; acc.z += v0.z * n0; acc.w += v0.w * n0;
    }
    *(float4*)(out + (size_t)node * C + tid * 4) = acc;
}

// ---------------- BN / pool / misc ----------------

__global__ void bn_stats_kernel(const float* __restrict__ h,
                                float* __restrict__ bnstats,
                                int n, int C) {
    int c = blockIdx.x * 256 + threadIdx.x;
    if (c >= C) return;
    int rowsPer = CEILDIV(n, gridDim.y);
    int r0 = blockIdx.y * rowsPer;
    int r1 = min(n, r0 + rowsPer);
    float s = 0.f, sq = 0.f;
    for (int r = r0; r < r1; r++) {
        float v = h[(size_t)r * C + c];
        s += v;
        sq += v * v;
    }
    atomicAdd(&bnstats[c], s);
    atomicAdd(&bnstats[512 + c], sq);
}

// fused BN(apply)+tanh + pool dot-products; warp per node
__global__ void bn_dots_kernel(float* __restrict__ h,
                               const float* __restrict__ bnstats,
                               const float* __restrict__ gma, const float* __restrict__ bta,
                               const float* __restrict__ relw, const float* __restrict__ rootw,
                               const float* __restrict__ relb,
                               float* __restrict__ t, float* __restrict__ score,
                               int n, int C) {
    int node = (blockIdx.x * blockDim.x + threadIdx.x) >> 5;
    int lane = threadIdx.x & 31;
    if (node >= n) return;
    float* hp = h + (size_t)node * C;
    const float invn = 1.f / (float)n;
    float a = 0.f, b = 0.f;
    for (int c = lane; c < C; c += 32) {
        float mean = bnstats[c] * invn;
        float var = bnstats[512 + c] * invn - mean * mean;
        float y = tanhf((hp[c] - mean) * rsqrtf(var + 1e-5f) * gma[c] + bta[c]);
        hp[c] = y;
        a += y * relw[c];
        b += y * rootw[c];
    }
#pragma unroll
    for (int o = 16; o > 0; o >>= 1) {
        a += __shfl_down_sync(0xffffffffu, a, o);
        b += __shfl_down_sync(0xffffffffu, b, o);
    }
    if (lane == 0) {
        t[node] = a;
        score[node] = b + relb[0];
    }
}

__global__ void score_edge_kernel(const int* __restrict__ src, const int* __restrict__ dst,
                                  const float* __restrict__ ew, const float* __restrict__ t,
                                  float* __restrict__ score) {
    int e = blockIdx.x * blockDim.x + threadIdx.x;
    if (e >= ETOT) return;
    float w = ew[e];
    if (w != 0.f) atomicAdd(&score[dst[e]], w * t[src[e]]);
}

template <int SZ>
__global__ void __launch_bounds__(512)
topk_kernel(const float* __restrict__ score, int n_per, int ksel,
            int* __restrict__ perm, float* __restrict__ gain, int* __restrict__ newid) {
    __shared__ float sk[SZ];
    __shared__ int si[SZ];
    const int g = blockIdx.x;
    const int tid = threadIdx.x;
    for (int i = tid; i < SZ; i += 512) {
        if (i < n_per) { sk[i] = score[g * n_per + i]; si[i] = i; }
        else           { sk[i] = -INFINITY;            si[i] = 0x40000000 + i; }
    }
    __syncthreads();
    for (int kk = 2; kk <= SZ; kk <<= 1) {
        for (int j = kk >> 1; j > 0; j >>= 1) {
            for (int i = tid; i < SZ; i += 512) {
                int ixj = i ^ j;
                if (ixj > i) {
                    bool up = ((i & kk) == 0);
                    float s1 = sk[i], s2 = sk[ixj];
                    int i1 = si[i], i2 = si[ixj];
                    bool after = (s1 < s2) || (s1 == s2 && i1 > i2);
                    if (up == after) {
                        sk[i] = s2; sk[ixj] = s1;
                        si[i] = i2; si[ixj] = i1;
                    }
                }
            }
            __syncthreads();
        }
    }
    for (int r = tid; r < ksel; r += 512) {
        int old = g * n_per + si[r];
        int ng = g * ksel + r;
        perm[ng] = old;
        gain[ng] = tanhf(sk[r]);
        newid[old] = ng;
    }
}

// pool gather fused with bf16 hi/lo split + next-layer icount zeroing
__global__ void gather_split_kernel(const float* __restrict__ hin,
                                    __nv_bfloat16* __restrict__ hi,
                                    __nv_bfloat16* __restrict__ lo,
                                    const int* __restrict__ perm,
                                    const float* __restrict__ gain,
                                    int rows, int C4,
                                    int* __restrict__ icount) {
    int idx = blockIdx.x * blockDim.x + threadIdx.x;
    if (idx >= rows * C4) return;
    if (idx < rows) icount[idx] = 0;
    int row = idx / C4;
    int c = idx - row * C4;
    float gn = gain[row];
    float4 v = ((const float4*)hin)[(size_t)perm[row] * C4 + c];
    v.x *= gn; v.y *= gn; v.z *= gn; v.w *= gn;
    __nv_bfloat16 h0 = __float2bfloat16(v.x);
    __nv_bfloat16 h1 = __float2bfloat16(v.y);
    __nv_bfloat16 h2 = __float2bfloat16(v.z);
    __nv_bfloat16 h3 = __float2bfloat16(v.w);
    __nv_bfloat162* hp = (__nv_bfloat162*)(hi) + 2 * idx;
    __nv_bfloat162* lp = (__nv_bfloat162*)(lo) + 2 * idx;
    hp[0] = __halves2bfloat162(h0, h1);
    hp[1] = __halves2bfloat162(h2, h3);
    lp[0] = __halves2bfloat162(__float2bfloat16(v.x - __bfloat162float(h0)),
                               __float2bfloat16(v.y - __bfloat162float(h1)));
    lp[1] = __halves2bfloat162(__float2bfloat16(v.z - __bfloat162float(h2)),
                               __float2bfloat16(v.w - __bfloat162float(h3)));
}

// remap fused with next layer's in-degree count (icount zeroed by gather_split)
__global__ void remap_count_kernel(int* __restrict__ src, int* __restrict__ dst,
                                   float* __restrict__ ew, const int* __restrict__ newid,
                                   int* __restrict__ cnt) {
    int e = blockIdx.x * blockDim.x + threadIdx.x;
    if (e >= ETOT) return;
    int ns = newid[src[e]];
    int nd = newid[dst[e]];
    bool keep = (ns >= 0) && (nd >= 0) && (ew[e] != 0.f);
    src[e] = keep ? ns : 0;
    dst[e] = keep ? nd : 0;
    ew[e] = keep ? ew[e] : 0.f;
    if (keep) atomicAdd(&cnt[nd], 1);
}

__global__ void readout_kernel(const float* __restrict__ h, float* __restrict__ out) {
    int g = blockIdx.x;
    int c = threadIdx.x;
    const float* p = h + (size_t)(g * K3) * 256 + c;
    float mx = -INFINITY, sm = 0.f;
    for (int i = 0; i < K3; i++) {
        float v = p[(size_t)i * 256];
        mx = fmaxf(mx, v);
        sm += v;
    }
    out[g * 512 + c] = mx;
    out[g * 512 + 256 + c] = sm / (float)K3;
}

// ---------------- host orchestration ----------------

extern "C" void kernel_launch(void* const* d_in, const int* in_sizes, int n_in,
                              void* d_out, int out_size) {
    const float* x    = (const float*)d_in[0];
    const int*   ei   = (const int*)d_in[1];
    const float* W1   = (const float*)d_in[2];
    const float* b1   = (const float*)d_in[3];
    const float* W2   = (const float*)d_in[4];
    const float* b2   = (const float*)d_in[5];
    const float* W3   = (const float*)d_in[6];
    const float* b3   = (const float*)d_in[7];
    const float* W4   = (const float*)d_in[8];
    const float* b4   = (const float*)d_in[9];
    const float* g1   = (const float*)d_in[10];
    const float* be1  = (const float*)d_in[11];
    const float* g2   = (const float*)d_in[12];
    const float* be2  = (const float*)d_in[13];
    const float* g3   = (const float*)d_in[14];
    const float* be3  = (const float*)d_in[15];
    const float* p1rw = (const float*)d_in[16];
    const float* p1rb = (const float*)d_in[17];
    const float* p1ow = (const float*)d_in[18];
    const float* p2rw = (const float*)d_in[19];
    const float* p2rb = (const float*)d_in[20];
    const float* p2ow = (const float*)d_in[21];
    const float* p3rw = (const float*)d_in[22];
    const float* p3rb = (const float*)d_in[23];
    const float* p3ow = (const float*)d_in[24];
    float* out = (float*)d_out;

    float *buf0, *buf1, *dis, *score, *t, *gain, *ew, *bnstats, *enorm;
    int *src, *dst, *newid, *perm, *icount, *rowptr, *cursor, *esrc, *blocksum, *blockoff;
    __nv_bfloat16 *aHi, *aLo;
    __nv_bfloat16 *w1h, *w1l, *w2h, *w2l, *w3h, *w3l, *w4h, *w4l;
    cudaGetSymbolAddress((void**)&buf0, g_buf0);
    cudaGetSymbolAddress((void**)&buf1, g_buf1);
    cudaGetSymbolAddress((void**)&dis, g_dis);
    cudaGetSymbolAddress((void**)&score, g_score);
    cudaGetSymbolAddress((void**)&t, g_t);
    cudaGetSymbolAddress((void**)&gain, g_gain);
    cudaGetSymbolAddress((void**)&ew, g_ew);
    cudaGetSymbolAddress((void**)&bnstats, g_bnstats);
    cudaGetSymbolAddress((void**)&src, g_src);
    cudaGetSymbolAddress((void**)&dst, g_dst);
    cudaGetSymbolAddress((void**)&newid, g_newid);
    cudaGetSymbolAddress((void**)&perm, g_perm);
    cudaGetSymbolAddress((void**)&icount, g_icount);
    cudaGetSymbolAddress((void**)&rowptr, g_rowptr);
    cudaGetSymbolAddress((void**)&cursor, g_cursor);
    cudaGetSymbolAddress((void**)&esrc, g_esrc);
    cudaGetSymbolAddress((void**)&enorm, g_enorm);
    cudaGetSymbolAddress((void**)&blocksum, g_blocksum);
    cudaGetSymbolAddress((void**)&blockoff, g_blockoff);
    cudaGetSymbolAddress((void**)&aHi, g_aHi);
    cudaGetSymbolAddress((void**)&aLo, g_aLo);
    cudaGetSymbolAddress((void**)&w1h, g_w1Hi);
    cudaGetSymbolAddress((void**)&w1l, g_w1Lo);
    cudaGetSymbolAddress((void**)&w2h, g_w2Hi);
    cudaGetSymbolAddress((void**)&w2l, g_w2Lo);
    cudaGetSymbolAddress((void**)&w3h, g_w3Hi);
    cudaGetSymbolAddress((void**)&w3l, g_w3Lo);
    cudaGetSymbolAddress((void**)&w4h, g_w4Hi);
    cudaGetSymbolAddress((void**)&w4l, g_w4Lo);

    cudaFuncSetAttribute(wmma_gemm_kernel,
                         cudaFuncAttributeMaxDynamicSharedMemorySize, GEMM_SMEM);

    const int EB = CEILDIV(ETOT, 256);

    // upfront: all weight conversions, layer-1 activation split (+icount zero), edges
    convertW_all_kernel<<<CEILDIV(W4_END, 256), 256>>>(W1, W2, W3, W4,
                                                       w1h, w1l, w2h, w2l,
                                                       w3h, w3l, w4h, w4l);
    {
        int n4 = N1 * 512 / 4;
        convertA_kernel<<<CEILDIV(n4, 256), 256>>>((const float4*)x,
                                                   (__nv_bfloat162*)aHi,
                                                   (__nv_bfloat162*)aLo, n4, icount);
    }
    edge_init_count_kernel<<<EB, 256>>>(ei, src, dst, ew, icount);

    // gcn: GEMM -> buf1; CSR (icount pre-counted); agg -> buf0 (+bnstats zero)
    auto gcn = [&](int n, int Cin, int Cout,
                   const __nv_bfloat16* wh, const __nv_bfloat16* wl, const float* b) {
        wmma_gemm_kernel<<<dim3(Cout / TBN, CEILDIV(n, TBM)), 256, GEMM_SMEM>>>(
            aHi, aLo, wh, wl, buf1, n, Cin, Cout);
        int nb = CEILDIV(n, 1024);
        scan_partial_kernel<<<nb, 1024>>>(icount, rowptr, blocksum, n);
        scan_blocksums_kernel<<<1, 32>>>(blocksum, blockoff, rowptr, nb, n);
        scan_finalize_kernel<<<nb, 1024>>>(icount, rowptr, blockoff, cursor, dis, newid, n);
        fill_kernel<<<EB, 256>>>(src, dst, ew, dis, cursor, esrc, enorm);
        if (Cout == 512)
            gather_agg_kernel<512><<<n, 128>>>(buf1, rowptr, esrc, enorm, b, buf0, bnstats);
        else
            gather_agg_kernel<256><<<n, 64>>>(buf1, rowptr, esrc, enorm, b, buf0, bnstats);
    };
    auto bn_pool_pre = [&](int n, int C, const float* gma, const float* bta,
                           const float* rw, const float* rb, const float* ow) {
        bn_stats_kernel<<<dim3(CEILDIV(C, 256), 64), 256>>>(buf0, bnstats, n, C);
        bn_dots_kernel<<<CEILDIV(n * 32, 256), 256>>>(buf0, bnstats, gma, bta,
                                                      rw, ow, rb, t, score, n, C);
        score_edge_kernel<<<EB, 256>>>(src, dst, ew, t, score);
    };
    auto pool_post = [&](int ksel, int C) {
        int rows = BATCH * ksel;
        gather_split_kernel<<<CEILDIV(rows * (C / 4), 256), 256>>>(
            buf0, aHi, aLo, perm, gain, rows, C / 4, icount);
        remap_count_kernel<<<EB, 256>>>(src, dst, ew, newid, icount);
    };

    // ---------- Layer 1 ----------
    gcn(N1, 512, 512, w1h, w1l, b1);
    bn_pool_pre(N1, 512, g1, be1, p1rw, p1rb, p1ow);
    topk_kernel<1024><<<BATCH, 512>>>(score, 1024, K1, perm, gain, newid);
    pool_post(K1, 512);

    // ---------- Layer 2 ----------
    gcn(N2, 512, 512, w2h, w2l, b2);
    bn_pool_pre(N2, 512, g2, be2, p2rw, p2rb, p2ow);
    topk_kernel<1024><<<BATCH, 512>>>(score, K1, K2, perm, gain, newid);
    pool_post(K2, 512);

    // ---------- Layer 3 ----------
    gcn(N3, 512, 256, w3h, w3l, b3);
    bn_pool_pre(N3, 256, g3, be3, p3rw, p3rb, p3ow);
    topk_kernel<512><<<BATCH, 512>>>(score, K2, K3, perm, gain, newid);
    pool_post(K3, 256);

    // ---------- Layer 4 (no BN / pool) ----------
    gcn(N4, 256, 256, w4h, w4l, b4);

    // ---------- readout ----------
    readout_kernel<<<BATCH, 256>>>(buf0, out);
    (void)in_sizes; (void)n_in; (void)out_size;
}

// round 13
// speedup vs baseline: 1.1577x; 1.0416x over previous
#include <cuda_runtime.h>
#include <cuda_bf16.h>
#include <mma.h>
#include <math.h>
#include <stdint.h>

using namespace nvcuda;

// ---------------- problem constants ----------------
#define BATCH   32
#define ETOT    262144
#define NMAX    32768
#define K1      615
#define K2      369
#define K3      185
#define N1      32768
#define N2      (BATCH*K1)      // 19680
#define N3      (BATCH*K2)      // 11808
#define N4      (BATCH*K3)      // 5920

#define CEILDIV(a,b) (((a)+(b)-1)/(b))

// ---------------- static device scratch ----------------
__device__ float g_buf0[(size_t)NMAX * 512];
__device__ float g_buf1[(size_t)NMAX * 512];
__device__ float g_dis[NMAX];
__device__ float g_score[NMAX];
__device__ float g_t[NMAX];
__device__ float g_gain[NMAX];
__device__ int   g_newid[NMAX];
__device__ int   g_perm[NMAX];
__device__ int   g_src[ETOT];
__device__ int   g_dst[ETOT];
__device__ float g_ew[ETOT];
__device__ float g_bnstats[1024];
// CSR scratch
__device__ int   g_icount[NMAX];
__device__ int   g_rowptr[NMAX + 1];
__device__ int   g_cursor[NMAX];
__device__ int   g_esrc[ETOT];
__device__ float g_enorm[ETOT];
// bf16 split-precision GEMM scratch
__device__ __nv_bfloat16 g_aHi[(size_t)NMAX * 512];
__device__ __nv_bfloat16 g_aLo[(size_t)NMAX * 512];
__device__ __nv_bfloat16 g_w1Hi[512 * 512], g_w1Lo[512 * 512];
__device__ __nv_bfloat16 g_w2Hi[512 * 512], g_w2Lo[512 * 512];
__device__ __nv_bfloat16 g_w3Hi[256 * 512], g_w3Lo[256 * 512];
__device__ __nv_bfloat16 g_w4Hi[256 * 256], g_w4Lo[256 * 256];

// ---------------- kernels ----------------

__global__ void edge_init_count_kernel(const int* __restrict__ ei,
                                       int* __restrict__ src, int* __restrict__ dst,
                                       float* __restrict__ ew, int* __restrict__ cnt) {
    int e = blockIdx.x * blockDim.x + threadIdx.x;
    if (e >= ETOT) return;
    int d = ei[ETOT + e];
    src[e] = ei[e];
    dst[e] = d;
    ew[e]  = 1.0f;
    atomicAdd(&cnt[d], 1);
}

// layer-1 activations; also zeroes icount[0:N1)
__global__ void convertA_kernel(const float4* __restrict__ A,
                                __nv_bfloat162* __restrict__ hi2,
                                __nv_bfloat162* __restrict__ lo2, int n4,
                                int* __restrict__ icount) {
    int i = blockIdx.x * blockDim.x + threadIdx.x;
    if (i >= n4) return;
    if (i < N1) icount[i] = 0;
    float4 v = A[i];
    __nv_bfloat16 h0 = __float2bfloat16(v.x);
    __nv_bfloat16 h1 = __float2bfloat16(v.y);
    __nv_bfloat16 h2 = __float2bfloat16(v.z);
    __nv_bfloat16 h3 = __float2bfloat16(v.w);
    hi2[2 * i]     = __halves2bfloat162(h0, h1);
    hi2[2 * i + 1] = __halves2bfloat162(h2, h3);
    lo2[2 * i]     = __halves2bfloat162(__float2bfloat16(v.x - __bfloat162float(h0)),
                                        __float2bfloat16(v.y - __bfloat162float(h1)));
    lo2[2 * i + 1] = __halves2bfloat162(__float2bfloat16(v.z - __bfloat162float(h2)),
                                        __float2bfloat16(v.w - __bfloat162float(h3)));
}

// all 4 weight matrices: W [K,N] fp32 -> WT_hi/lo [N,K] bf16
#define W1_ELEMS (512 * 512)
#define W2_END   (2 * W1_ELEMS)
#define W3_END   (W2_END + 256 * 512)
#define W4_END   (W3_END + 256 * 256)
__global__ void convertW_all_kernel(const float* __restrict__ W1, const float* __restrict__ W2,
                                    const float* __restrict__ W3, const float* __restrict__ W4,
                                    __nv_bfloat16* w1h, __nv_bfloat16* w1l,
                                    __nv_bfloat16* w2h, __nv_bfloat16* w2l,
                                    __nv_bfloat16* w3h, __nv_bfloat16* w3l,
                                    __nv_bfloat16* w4h, __nv_bfloat16* w4l) {
    int idx = blockIdx.x * blockDim.x + threadIdx.x;
    const float* W; __nv_bfloat16 *h, *l; int K, N, local;
    if (idx < W1_ELEMS)      { W = W1; h = w1h; l = w1l; K = 512; N = 512; local = idx; }
    else if (idx < W2_END)   { W = W2; h = w2h; l = w2l; K = 512; N = 512; local = idx - W1_ELEMS; }
    else if (idx < W3_END)   { W = W3; h = w3h; l = w3l; K = 512; N = 256; local = idx - W2_END; }
    else if (idx < W4_END)   { W = W4; h = w4h; l = w4l; K = 256; N = 256; local = idx - W3_END; }
    else return;
    int n = local / K, k = local - n * K;
    float v = W[k * N + n];
    __nv_bfloat16 hh = __float2bfloat16(v);
    h[local] = hh;
    l[local] = __float2bfloat16(v - __bfloat162float(hh));
}

// ---------------------------------------------------------------
// WMMA bf16 split-precision GEMM (r11/r12 config — unchanged).
// ---------------------------------------------------------------
#define TBM 128
#define TBN 128
#define TBK 32
#define WLDA 40
#define TILE_BYTES (128 * WLDA * 2)
#define TILE_ELEMS (128 * WLDA)
#define STAGE_BYTES (4 * TILE_BYTES)
#define GEMM_SMEM (2 * STAGE_BYTES)

__device__ __forceinline__ void cp16(uint32_t s, const void* g, int sz) {
    asm volatile("cp.async.cg.shared.global [%0], [%1], 16, %2;"
                 :: "r"(s), "l"(g), "r"(sz));
}

__global__ void __launch_bounds__(256, 2)
wmma_gemm_kernel(const __nv_bfloat16* __restrict__ Ahi,
                 const __nv_bfloat16* __restrict__ Alo,
                 const __nv_bfloat16* __restrict__ Bhi,
                 const __nv_bfloat16* __restrict__ Blo,
                 float* __restrict__ C, int M, int K, int N) {
    extern __shared__ __nv_bfloat16 sm[];

    const int tid = threadIdx.x;
    const int wid = tid >> 5;
    const int warpM = wid & 1;
    const int warpN = wid >> 1;
    const int mBase = blockIdx.y * TBM;
    const int nBase = blockIdx.x * TBN;

    wmma::fragment<wmma::accumulator, 16, 16, 16, float> acc[4][2];
#pragma unroll
    for (int i = 0; i < 4; i++)
#pragma unroll
        for (int j = 0; j < 2; j++) wmma::fill_fragment(acc[i][j], 0.f);

    const uint32_t sbase = (uint32_t)__cvta_generic_to_shared(sm);
    const int row = tid >> 1;
    const int q0 = (tid & 1) * 2;
    const int grow = mBase + row;
    const int nrow = nBase + row;
    const size_t aoff = (size_t)(grow < M ? grow : 0) * K;
    const size_t boff = (size_t)nrow * K;
    const int szA = (grow < M) ? 16 : 0;
    const uint32_t srow = sbase + (uint32_t)row * (WLDA * 2);

#define LOAD_STAGE(s, kc) do { \
        uint32_t s0 = srow + (uint32_t)(s) * STAGE_BYTES; \
        _Pragma("unroll") \
        for (int qq = 0; qq < 2; qq++) { \
            int q = q0 + qq; \
            cp16(s0 + q * 16,                  Ahi + aoff + (kc) + q * 8, szA); \
            cp16(s0 + q * 16 + TILE_BYTES,     Alo + aoff + (kc) + q * 8, szA); \
            cp16(s0 + q * 16 + 2 * TILE_BYTES, Bhi + boff + (kc) + q * 8, 16); \
            cp16(s0 + q * 16 + 3 * TILE_BYTES, Blo + boff + (kc) + q * 8, 16); \
        } \
    } while (0)

    LOAD_STAGE(0, 0);
    asm volatile("cp.async.commit_group;" ::: "memory");

    const int nCh = K >> 5;
    for (int ch = 0; ch < nCh; ch++) {
        if (ch + 1 < nCh) {
            LOAD_STAGE((ch + 1) & 1, (ch + 1) << 5);
            asm volatile("cp.async.commit_group;" ::: "memory");
            asm volatile("cp.async.wait_group 1;" ::: "memory");
        } else {
            asm volatile("cp.async.wait_group 0;" ::: "memory");
        }
        __syncthreads();

        const __nv_bfloat16* sb   = sm + (ch & 1) * (4 * TILE_ELEMS);
        const __nv_bfloat16* sAhi = sb;
        const __nv_bfloat16* sAlo = sb + TILE_ELEMS;
        const __nv_bfloat16* sBhi = sb + 2 * TILE_ELEMS;
        const __nv_bfloat16* sBlo = sb + 3 * TILE_ELEMS;

#pragma unroll
        for (int ks = 0; ks < TBK; ks += 16) {
            wmma::fragment<wmma::matrix_b, 16, 16, 16, __nv_bfloat16, wmma::col_major> bh[2], bl[2];
#pragma unroll
            for (int j = 0; j < 2; j++) {
                wmma::load_matrix_sync(bh[j], sBhi + (warpN * 32 + j * 16) * WLDA + ks, WLDA);
                wmma::load_matrix_sync(bl[j], sBlo + (warpN * 32 + j * 16) * WLDA + ks, WLDA);
            }
#pragma unroll
            for (int i = 0; i < 4; i++) {
                wmma::fragment<wmma::matrix_a, 16, 16, 16, __nv_bfloat16, wmma::row_major> ah, al;
                wmma::load_matrix_sync(ah, sAhi + (warpM * 64 + i * 16) * WLDA + ks, WLDA);
                wmma::load_matrix_sync(al, sAlo + (warpM * 64 + i * 16) * WLDA + ks, WLDA);
#pragma unroll
                for (int j = 0; j < 2; j++) wmma::mma_sync(acc[i][j], ah, bh[j], acc[i][j]);
#pragma unroll
                for (int j = 0; j < 2; j++) wmma::mma_sync(acc[i][j], ah, bl[j], acc[i][j]);
#pragma unroll
                for (int j = 0; j < 2; j++) wmma::mma_sync(acc[i][j], al, bh[j], acc[i][j]);
            }
        }
        __syncthreads();
    }
#undef LOAD_STAGE

#pragma unroll
    for (int i = 0; i < 4; i++) {
        int r0 = mBase + warpM * 64 + i * 16;
#pragma unroll
        for (int j = 0; j < 2; j++) {
            float* cp = C + (size_t)r0 * N + nBase + warpN * 32 + j * 16;
            wmma::store_matrix_sync(cp, acc[i][j], N, wmma::mem_row_major);
        }
    }
}

// ---------------- CSR build ----------------

// single-block full scan: exclusive scan of cnt -> rowptr/cursor, dis, newid=-1
__global__ void __launch_bounds__(1024)
scan_all_kernel(const int* __restrict__ cnt, int* __restrict__ rowptr,
                int* __restrict__ cursor, float* __restrict__ dis,
                int* __restrict__ newid, int n) {
    __shared__ int warpsum[32];
    const int tid = threadIdx.x;
    const int lane = tid & 31, wid = tid >> 5;
    int offset = 0;
    const int iters = (n + 1023) >> 10;
    for (int it = 0; it < iters; it++) {
        const int i = (it << 10) + tid;
        const int s = (i < n) ? cnt[i] : 0;
        int v = s;
#pragma unroll
        for (int off = 1; off < 32; off <<= 1) {
            int u = __shfl_up_sync(0xffffffffu, v, off);
            if (lane >= off) v += u;
        }
        if (lane == 31) warpsum[wid] = v;
        __syncthreads();
        if (wid == 0) {
            int w = warpsum[lane];
#pragma unroll
            for (int off = 1; off < 32; off <<= 1) {
                int u = __shfl_up_sync(0xffffffffu, w, off);
                if (lane >= off) w += u;
            }
            warpsum[lane] = w;
        }
        __syncthreads();
        int excl = v - s + (wid > 0 ? warpsum[wid - 1] : 0);
        if (i < n) {
            int r = offset + excl;
            rowptr[i] = r;
            cursor[i] = r;
            dis[i] = (s > 0) ? rsqrtf((float)s) : 0.f;
            newid[i] = -1;
        }
        int tot = warpsum[31];
        __syncthreads();
        offset += tot;
    }
    if (tid == 0) rowptr[n] = offset;
}

__global__ void fill_kernel(const int* __restrict__ src, const int* __restrict__ dst,
                            const float* __restrict__ ew, const float* __restrict__ dis,
                            int* __restrict__ cursor,
                            int* __restrict__ esrc, float* __restrict__ enorm) {
    int e = blockIdx.x * blockDim.x + threadIdx.x;
    if (e >= ETOT) return;
    float w = ew[e];
    if (w == 0.f) return;
    int s = src[e], d = dst[e];
    int pos = atomicAdd(&cursor[d], 1);
    esrc[pos] = s;
    enorm[pos] = dis[s] * dis[d] * w;
}

template <int C>
__global__ void gather_agg_kernel(const float* __restrict__ h,
                                  const int* __restrict__ rowptr,
                                  const int* __restrict__ esrc,
                                  const float* __restrict__ enorm,
                                  const float* __restrict__ bias,
                                  float* __restrict__ out,
                                  float* __restrict__ bnstats) {
    const int node = blockIdx.x;
    const int tid = threadIdx.x;
    if (node == 0)
        for (int k = tid; k < 1024; k += (C / 4)) bnstats[k] = 0.f;
    float4 acc = *(const float4*)(bias + tid * 4);
    int b = rowptr[node];
    const int e = rowptr[node + 1];
    for (; b + 1 < e; b += 2) {
        int s0 = esrc[b],     s1 = esrc[b + 1];
        float n0 = enorm[b],  n1 = enorm[b + 1];
        float4 v0 = *(const float4*)(h + (size_t)s0 * C + tid * 4);
        float4 v1 = *(const float4*)(h + (size_t)s1 * C + tid * 4);
        acc.x += v0.x * n0; acc.y += v0.y * n0; acc.z += v0.z * n0; acc.w += v0.w * n0;
        acc.x += v1.x * n1; acc.y += v1.y * n1; acc.z += v1.z * n1; acc.w += v1.w * n1;
    }
    if (b < e) {
        int s0 = esrc[b];
        float n0 = enorm[b];
        float4 v0 = *(const float4*)(h + (size_t)s0 * C + tid * 4);
        acc.x += v0.x * n0; acc.y += v0.y * n0; acc.z += v0.z * n0; acc.w += v0.w * n0;
    }
    *(float4*)(out + (size_t)node * C + tid * 4) = acc;
}

// ---------------- BN / pool / misc ----------------

__global__ void bn_stats_kernel(const float* __restrict__ h,
                                float* __restrict__ bnstats,
                                int n, int C) {
    int c = blockIdx.x * 256 + threadIdx.x;
    if (c >= C) return;
    int rowsPer = CEILDIV(n, gridDim.y);
    int r0 = blockIdx.y * rowsPer;
    int r1 = min(n, r0 + rowsPer);
    float s = 0.f, sq = 0.f;
    for (int r = r0; r < r1; r++) {
        float v = h[(size_t)r * C + c];
        s += v;
        sq += v * v;
    }
    atomicAdd(&bnstats[c], s);
    atomicAdd(&bnstats[512 + c], sq);
}

__global__ void bn_dots_kernel(float* __restrict__ h,
                               const float* __restrict__ bnstats,
                               const float* __restrict__ gma, const float* __restrict__ bta,
                               const float* __restrict__ relw, const float* __restrict__ rootw,
                               const float* __restrict__ relb,
                               float* __restrict__ t, float* __restrict__ score,
                               int n, int C) {
    int node = (blockIdx.x * blockDim.x + threadIdx.x) >> 5;
    int lane = threadIdx.x & 31;
    if (node >= n) return;
    float* hp = h + (size_t)node * C;
    const float invn = 1.f / (float)n;
    float a = 0.f, b = 0.f;
    for (int c = lane; c < C; c += 32) {
        float mean = bnstats[c] * invn;
        float var = bnstats[512 + c] * invn - mean * mean;
        float y = tanhf((hp[c] - mean) * rsqrtf(var + 1e-5f) * gma[c] + bta[c]);
        hp[c] = y;
        a += y * relw[c];
        b += y * rootw[c];
    }
#pragma unroll
    for (int o = 16; o > 0; o >>= 1) {
        a += __shfl_down_sync(0xffffffffu, a, o);
        b += __shfl_down_sync(0xffffffffu, b, o);
    }
    if (lane == 0) {
        t[node] = a;
        score[node] = b + relb[0];
    }
}

__global__ void score_edge_kernel(const int* __restrict__ src, const int* __restrict__ dst,
                                  const float* __restrict__ ew, const float* __restrict__ t,
                                  float* __restrict__ score) {
    int e = blockIdx.x * blockDim.x + threadIdx.x;
    if (e >= ETOT) return;
    float w = ew[e];
    if (w != 0.f) atomicAdd(&score[dst[e]], w * t[src[e]]);
}

// topk also zeroes icount[0 : B*ksel) for the next layer's counting
template <int SZ>
__global__ void __launch_bounds__(512)
topk_kernel(const float* __restrict__ score, int n_per, int ksel,
            int* __restrict__ perm, float* __restrict__ gain, int* __restrict__ newid,
            int* __restrict__ icount) {
    __shared__ float sk[SZ];
    __shared__ int si[SZ];
    const int g = blockIdx.x;
    const int tid = threadIdx.x;
    for (int i = tid; i < SZ; i += 512) {
        if (i < n_per) { sk[i] = score[g * n_per + i]; si[i] = i; }
        else           { sk[i] = -INFINITY;            si[i] = 0x40000000 + i; }
    }
    __syncthreads();
    for (int kk = 2; kk <= SZ; kk <<= 1) {
        for (int j = kk >> 1; j > 0; j >>= 1) {
            for (int i = tid; i < SZ; i += 512) {
                int ixj = i ^ j;
                if (ixj > i) {
                    bool up = ((i & kk) == 0);
                    float s1 = sk[i], s2 = sk[ixj];
                    int i1 = si[i], i2 = si[ixj];
                    bool after = (s1 < s2) || (s1 == s2 && i1 > i2);
                    if (up == after) {
                        sk[i] = s2; sk[ixj] = s1;
                        si[i] = i2; si[ixj] = i1;
                    }
                }
            }
            __syncthreads();
        }
    }
    for (int r = tid; r < ksel; r += 512) {
        int old = g * n_per + si[r];
        int ng = g * ksel + r;
        perm[ng] = old;
        gain[ng] = tanhf(sk[r]);
        newid[old] = ng;
        icount[ng] = 0;
    }
}

__global__ void gather_split_kernel(const float* __restrict__ hin,
                                    __nv_bfloat16* __restrict__ hi,
                                    __nv_bfloat16* __restrict__ lo,
                                    const int* __restrict__ perm,
                                    const float* __restrict__ gain,
                                    int rows, int C4) {
    int idx = blockIdx.x * blockDim.x + threadIdx.x;
    if (idx >= rows * C4) return;
    int row = idx / C4;
    int c = idx - row * C4;
    float gn = gain[row];
    float4 v = ((const float4*)hin)[(size_t)perm[row] * C4 + c];
    v.x *= gn; v.y *= gn; v.z *= gn; v.w *= gn;
    __nv_bfloat16 h0 = __float2bfloat16(v.x);
    __nv_bfloat16 h1 = __float2bfloat16(v.y);
    __nv_bfloat16 h2 = __float2bfloat16(v.z);
    __nv_bfloat16 h3 = __float2bfloat16(v.w);
    __nv_bfloat162* hp = (__nv_bfloat162*)(hi) + 2 * idx;
    __nv_bfloat162* lp = (__nv_bfloat162*)(lo) + 2 * idx;
    hp[0] = __halves2bfloat162(h0, h1);
    hp[1] = __halves2bfloat162(h2, h3);
    lp[0] = __halves2bfloat162(__float2bfloat16(v.x - __bfloat162float(h0)),
                               __float2bfloat16(v.y - __bfloat162float(h1)));
    lp[1] = __halves2bfloat162(__float2bfloat16(v.z - __bfloat162float(h2)),
                               __float2bfloat16(v.w - __bfloat162float(h3)));
}

__global__ void remap_count_kernel(int* __restrict__ src, int* __restrict__ dst,
                                   float* __restrict__ ew, const int* __restrict__ newid,
                                   int* __restrict__ cnt) {
    int e = blockIdx.x * blockDim.x + threadIdx.x;
    if (e >= ETOT) return;
    int ns = newid[src[e]];
    int nd = newid[dst[e]];
    bool keep = (ns >= 0) && (nd >= 0) && (ew[e] != 0.f);
    src[e] = keep ? ns : 0;
    dst[e] = keep ? nd : 0;
    ew[e] = keep ? ew[e] : 0.f;
    if (keep) atomicAdd(&cnt[nd], 1);
}

__global__ void readout_kernel(const float* __restrict__ h, float* __restrict__ out) {
    int g = blockIdx.x;
    int c = threadIdx.x;
    const float* p = h + (size_t)(g * K3) * 256 + c;
    float mx = -INFINITY, sm = 0.f;
    for (int i = 0; i < K3; i++) {
        float v = p[(size_t)i * 256];
        mx = fmaxf(mx, v);
        sm += v;
    }
    out[g * 512 + c] = mx;
    out[g * 512 + 256 + c] = sm / (float)K3;
}

// ---------------- host orchestration ----------------

extern "C" void kernel_launch(void* const* d_in, const int* in_sizes, int n_in,
                              void* d_out, int out_size) {
    const float* x    = (const float*)d_in[0];
    const int*   ei   = (const int*)d_in[1];
    const float* W1   = (const float*)d_in[2];
    const float* b1   = (const float*)d_in[3];
    const float* W2   = (const float*)d_in[4];
    const float* b2   = (const float*)d_in[5];
    const float* W3   = (const float*)d_in[6];
    const float* b3   = (const float*)d_in[7];
    const float* W4   = (const float*)d_in[8];
    const float* b4   = (const float*)d_in[9];
    const float* g1   = (const float*)d_in[10];
    const float* be1  = (const float*)d_in[11];
    const float* g2   = (const float*)d_in[12];
    const float* be2  = (const float*)d_in[13];
    const float* g3   = (const float*)d_in[14];
    const float* be3  = (const float*)d_in[15];
    const float* p1rw = (const float*)d_in[16];
    const float* p1rb = (const float*)d_in[17];
    const float* p1ow = (const float*)d_in[18];
    const float* p2rw = (const float*)d_in[19];
    const float* p2rb = (const float*)d_in[20];
    const float* p2ow = (const float*)d_in[21];
    const float* p3rw = (const float*)d_in[22];
    const float* p3rb = (const float*)d_in[23];
    const float* p3ow = (const float*)d_in[24];
    float* out = (float*)d_out;

    float *buf0, *buf1, *dis, *score, *t, *gain, *ew, *bnstats, *enorm;
    int *src, *dst, *newid, *perm, *icount, *rowptr, *cursor, *esrc;
    __nv_bfloat16 *aHi, *aLo;
    __nv_bfloat16 *w1h, *w1l, *w2h, *w2l, *w3h, *w3l, *w4h, *w4l;
    cudaGetSymbolAddress((void**)&buf0, g_buf0);
    cudaGetSymbolAddress((void**)&buf1, g_buf1);
    cudaGetSymbolAddress((void**)&dis, g_dis);
    cudaGetSymbolAddress((void**)&score, g_score);
    cudaGetSymbolAddress((void**)&t, g_t);
    cudaGetSymbolAddress((void**)&gain, g_gain);
    cudaGetSymbolAddress((void**)&ew, g_ew);
    cudaGetSymbolAddress((void**)&bnstats, g_bnstats);
    cudaGetSymbolAddress((void**)&src, g_src);
    cudaGetSymbolAddress((void**)&dst, g_dst);
    cudaGetSymbolAddress((void**)&newid, g_newid);
    cudaGetSymbolAddress((void**)&perm, g_perm);
    cudaGetSymbolAddress((void**)&icount, g_icount);
    cudaGetSymbolAddress((void**)&rowptr, g_rowptr);
    cudaGetSymbolAddress((void**)&cursor, g_cursor);
    cudaGetSymbolAddress((void**)&esrc, g_esrc);
    cudaGetSymbolAddress((void**)&enorm, g_enorm);
    cudaGetSymbolAddress((void**)&aHi, g_aHi);
    cudaGetSymbolAddress((void**)&aLo, g_aLo);
    cudaGetSymbolAddress((void**)&w1h, g_w1Hi);
    cudaGetSymbolAddress((void**)&w1l, g_w1Lo);
    cudaGetSymbolAddress((void**)&w2h, g_w2Hi);
    cudaGetSymbolAddress((void**)&w2l, g_w2Lo);
    cudaGetSymbolAddress((void**)&w3h, g_w3Hi);
    cudaGetSymbolAddress((void**)&w3l, g_w3Lo);
    cudaGetSymbolAddress((void**)&w4h, g_w4Hi);
    cudaGetSymbolAddress((void**)&w4l, g_w4Lo);

    cudaFuncSetAttribute(wmma_gemm_kernel,
                         cudaFuncAttributeMaxDynamicSharedMemorySize, GEMM_SMEM);

    // persistent side stream + events (created once; capture-time only overhead)
    static cudaStream_t s2 = nullptr;
    static cudaEvent_t evRoot, evW, evE, evCSR[4], evT[3];
    if (s2 == nullptr) {
        cudaStreamCreateWithFlags(&s2, cudaStreamNonBlocking);
        cudaEventCreateWithFlags(&evRoot, cudaEventDisableTiming);
        cudaEventCreateWithFlags(&evW, cudaEventDisableTiming);
        cudaEventCreateWithFlags(&evE, cudaEventDisableTiming);
        for (int i = 0; i < 4; i++) cudaEventCreateWithFlags(&evCSR[i], cudaEventDisableTiming);
        for (int i = 0; i < 3; i++) cudaEventCreateWithFlags(&evT[i], cudaEventDisableTiming);
    }

    const int EB = CEILDIV(ETOT, 256);
    const cudaStream_t s0 = 0;

    // ---- fork side stream; weight conversion there ----
    cudaEventRecord(evRoot, s0);
    cudaStreamWaitEvent(s2, evRoot, 0);
    convertW_all_kernel<<<CEILDIV(W4_END, 256), 256, 0, s2>>>(W1, W2, W3, W4,
                                                              w1h, w1l, w2h, w2l,
                                                              w3h, w3l, w4h, w4l);
    cudaEventRecord(evW, s2);

    // ---- main stream: activation split (+icount zero) and edge init ----
    {
        int n4 = N1 * 512 / 4;
        convertA_kernel<<<CEILDIV(n4, 256), 256, 0, s0>>>((const float4*)x,
                                                          (__nv_bfloat162*)aHi,
                                                          (__nv_bfloat162*)aLo, n4, icount);
    }
    edge_init_count_kernel<<<EB, 256, 0, s0>>>(ei, src, dst, ew, icount);
    cudaEventRecord(evE, s0);

    // ---- layer-1 CSR on side stream ----
    cudaStreamWaitEvent(s2, evE, 0);
    scan_all_kernel<<<1, 1024, 0, s2>>>(icount, rowptr, cursor, dis, newid, N1);
    fill_kernel<<<EB, 256, 0, s2>>>(src, dst, ew, dis, cursor, esrc, enorm);
    cudaEventRecord(evCSR[0], s2);

    auto gemm = [&](int n, int Cin, int Cout,
                    const __nv_bfloat16* wh, const __nv_bfloat16* wl) {
        wmma_gemm_kernel<<<dim3(Cout / TBN, CEILDIV(n, TBM)), 256, GEMM_SMEM, s0>>>(
            aHi, aLo, wh, wl, buf1, n, Cin, Cout);
    };
    auto agg_bn_pool = [&](int n, int C, const float* b,
                           const float* gma, const float* bta,
                           const float* rw, const float* rb, const float* ow) {
        if (C == 512)
            gather_agg_kernel<512><<<n, 128, 0, s0>>>(buf1, rowptr, esrc, enorm, b, buf0, bnstats);
        else
            gather_agg_kernel<256><<<n, 64, 0, s0>>>(buf1, rowptr, esrc, enorm, b, buf0, bnstats);
        bn_stats_kernel<<<dim3(CEILDIV(C, 256), 64), 256, 0, s0>>>(buf0, bnstats, n, C);
        bn_dots_kernel<<<CEILDIV(n * 32, 256), 256, 0, s0>>>(buf0, bnstats, gma, bta,
                                                             rw, ow, rb, t, score, n, C);
        score_edge_kernel<<<EB, 256, 0, s0>>>(src, dst, ew, t, score);
    };
    // after topk (evT recorded on s0): side stream remaps edges + builds next CSR
    auto side_csr = [&](int li, int nNext) {
        cudaStreamWaitEvent(s2, evT[li], 0);
        remap_count_kernel<<<EB, 256, 0, s2>>>(src, dst, ew, newid, icount);
        scan_all_kernel<<<1, 1024, 0, s2>>>(icount, rowptr, cursor, dis, newid, nNext);
        fill_kernel<<<EB, 256, 0, s2>>>(src, dst, ew, dis, cursor, esrc, enorm);
        cudaEventRecord(evCSR[li + 1], s2);
    };

    // ---------- Layer 1 ----------
    cudaStreamWaitEvent(s0, evW, 0);
    gemm(N1, 512, 512, w1h, w1l);
    cudaStreamWaitEvent(s0, evCSR[0], 0);
    agg_bn_pool(N1, 512, b1, g1, be1, p1rw, p1rb, p1ow);
    topk_kernel<1024><<<BATCH, 512, 0, s0>>>(score, 1024, K1, perm, gain, newid, icount);
    cudaEventRecord(evT[0], s0);
    side_csr(0, N2);
    gather_split_kernel<<<CEILDIV(N2 * 128, 256), 256, 0, s0>>>(buf0, aHi, aLo, perm, gain,
                                                                N2, 128);

    // ---------- Layer 2 ----------
    gemm(N2, 512, 512, w2h, w2l);
    cudaStreamWaitEvent(s0, evCSR[1], 0);
    agg_bn_pool(N2, 512, b2, g2, be2, p2rw, p2rb, p2ow);
    topk_kernel<1024><<<BATCH, 512, 0, s0>>>(score, K1, K2, perm, gain, newid, icount);
    cudaEventRecord(evT[1], s0);
    side_csr(1, N3);
    gather_split_kernel<<<CEILDIV(N3 * 128, 256), 256, 0, s0>>>(buf0, aHi, aLo, perm, gain,
                                                                N3, 128);

    // ---------- Layer 3 ----------
    gemm(N3, 512, 256, w3h, w3l);
    cudaStreamWaitEvent(s0, evCSR[2], 0);
    agg_bn_pool(N3, 256, b3, g3, be3, p3rw, p3rb, p3ow);
    topk_kernel<512><<<BATCH, 512, 0, s0>>>(score, K2, K3, perm, gain, newid, icount);
    cudaEventRecord(evT[2], s0);
    side_csr(2, N4);
    gather_split_kernel<<<CEILDIV(N4 * 64, 256), 256, 0, s0>>>(buf0, aHi, aLo, perm, gain,
                                                               N4, 64);

    // ---------- Layer 4 (no BN / pool) ----------
    gemm(N4, 256, 256, w4h, w4l);
    cudaStreamWaitEvent(s0, evCSR[3], 0);
    gather_agg_kernel<256><<<N4, 64, 0, s0>>>(buf1, rowptr, esrc, enorm, b4, buf0, bnstats);

    // ---------- readout ----------
    readout_kernel<<<BATCH, 256, 0, s0>>>(buf0, out);
    (void)in_sizes; (void)n_in; (void)out_size;
}

// round 14
// speedup vs baseline: 1.1718x; 1.0122x over previous
#include <cuda_runtime.h>
#include <cuda_bf16.h>
#include <mma.h>
#include <math.h>
#include <stdint.h>

using namespace nvcuda;

// ---------------- problem constants ----------------
#define BATCH   32
#define ETOT    262144
#define NMAX    32768
#define K1      615
#define K2      369
#define K3      185
#define N1      32768
#define N2      (BATCH*K1)      // 19680
#define N3      (BATCH*K2)      // 11808
#define N4      (BATCH*K3)      // 5920

#define CEILDIV(a,b) (((a)+(b)-1)/(b))

// ---------------- static device scratch ----------------
__device__ float g_buf0[(size_t)NMAX * 512];
__device__ float g_buf1[(size_t)NMAX * 512];
__device__ float g_dis[NMAX];
__device__ float g_score[NMAX];
__device__ float g_t[NMAX];
__device__ float g_gain[NMAX];
__device__ int   g_newid[NMAX];
__device__ int   g_perm[NMAX];
__device__ int   g_src[ETOT];
__device__ int   g_dst[ETOT];
__device__ float g_ew[ETOT];
__device__ float g_bnstats[1024];
// CSR scratch
__device__ int   g_icount[NMAX];
__device__ int   g_rowptr[NMAX + 1];
__device__ int   g_cursor[NMAX];
__device__ int   g_esrc[ETOT];
__device__ float g_enorm[ETOT];
__device__ int   g_blocksum[32];
__device__ int   g_blockoff[32];
// bf16 split-precision GEMM scratch
__device__ __nv_bfloat16 g_aHi[(size_t)NMAX * 512];
__device__ __nv_bfloat16 g_aLo[(size_t)NMAX * 512];
__device__ __nv_bfloat16 g_w1Hi[512 * 512], g_w1Lo[512 * 512];
__device__ __nv_bfloat16 g_w2Hi[512 * 512], g_w2Lo[512 * 512];
__device__ __nv_bfloat16 g_w3Hi[256 * 512], g_w3Lo[256 * 512];
__device__ __nv_bfloat16 g_w4Hi[256 * 256], g_w4Lo[256 * 256];

// ---------------- kernels ----------------

__global__ void edge_init_count_kernel(const int* __restrict__ ei,
                                       int* __restrict__ src, int* __restrict__ dst,
                                       float* __restrict__ ew, int* __restrict__ cnt) {
    int e = blockIdx.x * blockDim.x + threadIdx.x;
    if (e >= ETOT) return;
    int d = ei[ETOT + e];
    src[e] = ei[e];
    dst[e] = d;
    ew[e]  = 1.0f;
    atomicAdd(&cnt[d], 1);
}

// layer-1 activations; also zeroes icount[0:N1)
__global__ void convertA_kernel(const float4* __restrict__ A,
                                __nv_bfloat162* __restrict__ hi2,
                                __nv_bfloat162* __restrict__ lo2, int n4,
                                int* __restrict__ icount) {
    int i = blockIdx.x * blockDim.x + threadIdx.x;
    if (i >= n4) return;
    if (i < N1) icount[i] = 0;
    float4 v = A[i];
    __nv_bfloat16 h0 = __float2bfloat16(v.x);
    __nv_bfloat16 h1 = __float2bfloat16(v.y);
    __nv_bfloat16 h2 = __float2bfloat16(v.z);
    __nv_bfloat16 h3 = __float2bfloat16(v.w);
    hi2[2 * i]     = __halves2bfloat162(h0, h1);
    hi2[2 * i + 1] = __halves2bfloat162(h2, h3);
    lo2[2 * i]     = __halves2bfloat162(__float2bfloat16(v.x - __bfloat162float(h0)),
                                        __float2bfloat16(v.y - __bfloat162float(h1)));
    lo2[2 * i + 1] = __halves2bfloat162(__float2bfloat16(v.z - __bfloat162float(h2)),
                                        __float2bfloat16(v.w - __bfloat162float(h3)));
}

// all 4 weight matrices: W [K,N] fp32 -> WT_hi/lo [N,K] bf16
#define W1_ELEMS (512 * 512)
#define W2_END   (2 * W1_ELEMS)
#define W3_END   (W2_END + 256 * 512)
#define W4_END   (W3_END + 256 * 256)
__global__ void convertW_all_kernel(const float* __restrict__ W1, const float* __restrict__ W2,
                                    const float* __restrict__ W3, const float* __restrict__ W4,
                                    __nv_bfloat16* w1h, __nv_bfloat16* w1l,
                                    __nv_bfloat16* w2h, __nv_bfloat16* w2l,
                                    __nv_bfloat16* w3h, __nv_bfloat16* w3l,
                                    __nv_bfloat16* w4h, __nv_bfloat16* w4l) {
    int idx = blockIdx.x * blockDim.x + threadIdx.x;
    const float* W; __nv_bfloat16 *h, *l; int K, N, local;
    if (idx < W1_ELEMS)      { W = W1; h = w1h; l = w1l; K = 512; N = 512; local = idx; }
    else if (idx < W2_END)   { W = W2; h = w2h; l = w2l; K = 512; N = 512; local = idx - W1_ELEMS; }
    else if (idx < W3_END)   { W = W3; h = w3h; l = w3l; K = 512; N = 256; local = idx - W2_END; }
    else if (idx < W4_END)   { W = W4; h = w4h; l = w4l; K = 256; N = 256; local = idx - W3_END; }
    else return;
    int n = local / K, k = local - n * K;
    float v = W[k * N + n];
    __nv_bfloat16 hh = __float2bfloat16(v);
    h[local] = hh;
    l[local] = __float2bfloat16(v - __bfloat162float(hh));
}

// ---------------------------------------------------------------
// WMMA bf16 split-precision GEMM (unchanged from r11).
// ---------------------------------------------------------------
#define TBM 128
#define TBN 128
#define TBK 32
#define WLDA 40
#define TILE_BYTES (128 * WLDA * 2)
#define TILE_ELEMS (128 * WLDA)
#define STAGE_BYTES (4 * TILE_BYTES)
#define GEMM_SMEM (2 * STAGE_BYTES)

__device__ __forceinline__ void cp16(uint32_t s, const void* g, int sz) {
    asm volatile("cp.async.cg.shared.global [%0], [%1], 16, %2;"
                 :: "r"(s), "l"(g), "r"(sz));
}

__global__ void __launch_bounds__(256, 2)
wmma_gemm_kernel(const __nv_bfloat16* __restrict__ Ahi,
                 const __nv_bfloat16* __restrict__ Alo,
                 const __nv_bfloat16* __restrict__ Bhi,
                 const __nv_bfloat16* __restrict__ Blo,
                 float* __restrict__ C, int M, int K, int N) {
    extern __shared__ __nv_bfloat16 sm[];

    const int tid = threadIdx.x;
    const int wid = tid >> 5;
    const int warpM = wid & 1;
    const int warpN = wid >> 1;
    const int mBase = blockIdx.y * TBM;
    const int nBase = blockIdx.x * TBN;

    wmma::fragment<wmma::accumulator, 16, 16, 16, float> acc[4][2];
#pragma unroll
    for (int i = 0; i < 4; i++)
#pragma unroll
        for (int j = 0; j < 2; j++) wmma::fill_fragment(acc[i][j], 0.f);

    const uint32_t sbase = (uint32_t)__cvta_generic_to_shared(sm);
    const int row = tid >> 1;
    const int q0 = (tid & 1) * 2;
    const int grow = mBase + row;
    const int nrow = nBase + row;
    const size_t aoff = (size_t)(grow < M ? grow : 0) * K;
    const size_t boff = (size_t)nrow * K;
    const int szA = (grow < M) ? 16 : 0;
    const uint32_t srow = sbase + (uint32_t)row * (WLDA * 2);

#define LOAD_STAGE(s, kc) do { \
        uint32_t s0 = srow + (uint32_t)(s) * STAGE_BYTES; \
        _Pragma("unroll") \
        for (int qq = 0; qq < 2; qq++) { \
            int q = q0 + qq; \
            cp16(s0 + q * 16,                  Ahi + aoff + (kc) + q * 8, szA); \
            cp16(s0 + q * 16 + TILE_BYTES,     Alo + aoff + (kc) + q * 8, szA); \
            cp16(s0 + q * 16 + 2 * TILE_BYTES, Bhi + boff + (kc) + q * 8, 16); \
            cp16(s0 + q * 16 + 3 * TILE_BYTES, Blo + boff + (kc) + q * 8, 16); \
        } \
    } while (0)

    LOAD_STAGE(0, 0);
    asm volatile("cp.async.commit_group;" ::: "memory");

    const int nCh = K >> 5;
    for (int ch = 0; ch < nCh; ch++) {
        if (ch + 1 < nCh) {
            LOAD_STAGE((ch + 1) & 1, (ch + 1) << 5);
            asm volatile("cp.async.commit_group;" ::: "memory");
            asm volatile("cp.async.wait_group 1;" ::: "memory");
        } else {
            asm volatile("cp.async.wait_group 0;" ::: "memory");
        }
        __syncthreads();

        const __nv_bfloat16* sb   = sm + (ch & 1) * (4 * TILE_ELEMS);
        const __nv_bfloat16* sAhi = sb;
        const __nv_bfloat16* sAlo = sb + TILE_ELEMS;
        const __nv_bfloat16* sBhi = sb + 2 * TILE_ELEMS;
        const __nv_bfloat16* sBlo = sb + 3 * TILE_ELEMS;

#pragma unroll
        for (int ks = 0; ks < TBK; ks += 16) {
            wmma::fragment<wmma::matrix_b, 16, 16, 16, __nv_bfloat16, wmma::col_major> bh[2], bl[2];
#pragma unroll
            for (int j = 0; j < 2; j++) {
                wmma::load_matrix_sync(bh[j], sBhi + (warpN * 32 + j * 16) * WLDA + ks, WLDA);
                wmma::load_matrix_sync(bl[j], sBlo + (warpN * 32 + j * 16) * WLDA + ks, WLDA);
            }
#pragma unroll
            for (int i = 0; i < 4; i++) {
                wmma::fragment<wmma::matrix_a, 16, 16, 16, __nv_bfloat16, wmma::row_major> ah, al;
                wmma::load_matrix_sync(ah, sAhi + (warpM * 64 + i * 16) * WLDA + ks, WLDA);
                wmma::load_matrix_sync(al, sAlo + (warpM * 64 + i * 16) * WLDA + ks, WLDA);
#pragma unroll
                for (int j = 0; j < 2; j++) wmma::mma_sync(acc[i][j], ah, bh[j], acc[i][j]);
#pragma unroll
                for (int j = 0; j < 2; j++) wmma::mma_sync(acc[i][j], ah, bl[j], acc[i][j]);
#pragma unroll
                for (int j = 0; j < 2; j++) wmma::mma_sync(acc[i][j], al, bh[j], acc[i][j]);
            }
        }
        __syncthreads();
    }
#undef LOAD_STAGE

#pragma unroll
    for (int i = 0; i < 4; i++) {
        int r0 = mBase + warpM * 64 + i * 16;
#pragma unroll
        for (int j = 0; j < 2; j++) {
            float* cp = C + (size_t)r0 * N + nBase + warpN * 32 + j * 16;
            wmma::store_matrix_sync(cp, acc[i][j], N, wmma::mem_row_major);
        }
    }
}

// ---------------- CSR build (3-phase coalesced scan) ----------------

__global__ void __launch_bounds__(1024)
scan_partial_kernel(const int* __restrict__ cnt, int* __restrict__ rowptr,
                    int* __restrict__ blocksum, int n) {
    __shared__ int warpsum[32];
    const int tid = threadIdx.x;
    const int i = blockIdx.x * 1024 + tid;
    int v = (i < n) ? cnt[i] : 0;
    const int s = v;

    const int lane = tid & 31, wid = tid >> 5;
#pragma unroll
    for (int off = 1; off < 32; off <<= 1) {
        int u = __shfl_up_sync(0xffffffffu, v, off);
        if (lane >= off) v += u;
    }
    if (lane == 31) warpsum[wid] = v;
    __syncthreads();
    if (wid == 0) {
        int w = warpsum[lane];
#pragma unroll
        for (int off = 1; off < 32; off <<= 1) {
            int u = __shfl_up_sync(0xffffffffu, w, off);
            if (lane >= off) w += u;
        }
        warpsum[lane] = w;
    }
    __syncthreads();
    int excl = v - s + (wid > 0 ? warpsum[wid - 1] : 0);
    if (i < n) rowptr[i] = excl;
    if (tid == 1023) blocksum[blockIdx.x] = excl + s;
}

__global__ void scan_blocksums_kernel(const int* __restrict__ blocksum,
                                      int* __restrict__ blockoff,
                                      int* __restrict__ rowptr,
                                      int nblocks, int n) {
    const int lane = threadIdx.x;
    int v = (lane < nblocks) ? blocksum[lane] : 0;
    const int s = v;
#pragma unroll
    for (int off = 1; off < 32; off <<= 1) {
        int u = __shfl_up_sync(0xffffffffu, v, off);
        if (lane >= off) v += u;
    }
    if (lane < nblocks) blockoff[lane] = v - s;
    if (lane == 31) rowptr[n] = v;
}

// finalize + cursor/dis/newid init fused
__global__ void __launch_bounds__(1024)
scan_finalize_kernel(const int* __restrict__ cnt, int* __restrict__ rowptr,
                     const int* __restrict__ blockoff,
                     int* __restrict__ cursor, float* __restrict__ dis,
                     int* __restrict__ newid, int n) {
    const int i = blockIdx.x * 1024 + threadIdx.x;
    if (i >= n) return;
    int r = rowptr[i] + blockoff[blockIdx.x];
    rowptr[i] = r;
    cursor[i] = r;
    int c = cnt[i];
    dis[i] = (c > 0) ? rsqrtf((float)c) : 0.f;
    newid[i] = -1;
}

__global__ void fill_kernel(const int* __restrict__ src, const int* __restrict__ dst,
                            const float* __restrict__ ew, const float* __restrict__ dis,
                            int* __restrict__ cursor,
                            int* __restrict__ esrc, float* __restrict__ enorm) {
    int e = blockIdx.x * blockDim.x + threadIdx.x;
    if (e >= ETOT) return;
    float w = ew[e];
    if (w == 0.f) return;
    int s = src[e], d = dst[e];
    int pos = atomicAdd(&cursor[d], 1);
    esrc[pos] = s;
    enorm[pos] = dis[s] * dis[d] * w;
}

template <int C>
__global__ void gather_agg_kernel(const float* __restrict__ h,
                                  const int* __restrict__ rowptr,
                                  const int* __restrict__ esrc,
                                  const float* __restrict__ enorm,
                                  const float* __restrict__ bias,
                                  float* __restrict__ out,
                                  float* __restrict__ bnstats) {
    const int node = blockIdx.x;
    const int tid = threadIdx.x;
    if (node == 0)
        for (int k = tid; k < 1024; k += (C / 4)) bnstats[k] = 0.f;
    float4 acc = *(const float4*)(bias + tid * 4);
    int b = rowptr[node];
    const int e = rowptr[node + 1];
    for (; b + 1 < e; b += 2) {
        int s0 = esrc[b],     s1 = esrc[b + 1];
        float n0 = enorm[b],  n1 = enorm[b + 1];
        float4 v0 = *(const float4*)(h + (size_t)s0 * C + tid * 4);
        float4 v1 = *(const float4*)(h + (size_t)s1 * C + tid * 4);
        acc.x += v0.x * n0; acc.y += v0.y * n0; acc.z += v0.z * n0; acc.w += v0.w * n0;
        acc.x += v1.x * n1; acc.y += v1.y * n1; acc.z += v1.z * n1; acc.w += v1.w * n1;
    }
    if (b < e) {
        int s0 = esrc[b];
        float n0 = enorm[b];
        float4 v0 = *(const float4*)(h + (size_t)s0 * C + tid * 4);
        acc.x += v0.x * n0; acc.y += v0.y * n0; acc.z += v0.z * n0; acc.w += v0.w * n0;
    }
    *(float4*)(out + (size_t)node * C + tid * 4) = acc;
}

// ---------------- BN / pool / misc ----------------

__global__ void bn_stats_kernel(const float* __restrict__ h,
                                float* __restrict__ bnstats,
                                int n, int C) {
    int c = blockIdx.x * 256 + threadIdx.x;
    if (c >= C) return;
    int rowsPer = CEILDIV(n, gridDim.y);
    int r0 = blockIdx.y * rowsPer;
    int r1 = min(n, r0 + rowsPer);
    float s = 0.f, sq = 0.f;
    for (int r = r0; r < r1; r++) {
        float v = h[(size_t)r * C + c];
        s += v;
        sq += v * v;
    }
    atomicAdd(&bnstats[c], s);
    atomicAdd(&bnstats[512 + c], sq);
}

__global__ void bn_dots_kernel(float* __restrict__ h,
                               const float* __restrict__ bnstats,
                               const float* __restrict__ gma, const float* __restrict__ bta,
                               const float* __restrict__ relw, const float* __restrict__ rootw,
                               const float* __restrict__ relb,
                               float* __restrict__ t, float* __restrict__ score,
                               int n, int C) {
    int node = (blockIdx.x * blockDim.x + threadIdx.x) >> 5;
    int lane = threadIdx.x & 31;
    if (node >= n) return;
    float* hp = h + (size_t)node * C;
    const float invn = 1.f / (float)n;
    float a = 0.f, b = 0.f;
    for (int c = lane; c < C; c += 32) {
        float mean = bnstats[c] * invn;
        float var = bnstats[512 + c] * invn - mean * mean;
        float y = tanhf((hp[c] - mean) * rsqrtf(var + 1e-5f) * gma[c] + bta[c]);
        hp[c] = y;
        a += y * relw[c];
        b += y * rootw[c];
    }
#pragma unroll
    for (int o = 16; o > 0; o >>= 1) {
        a += __shfl_down_sync(0xffffffffu, a, o);
        b += __shfl_down_sync(0xffffffffu, b, o);
    }
    if (lane == 0) {
        t[node] = a;
        score[node] = b + relb[0];
    }
}

__global__ void score_edge_kernel(const int* __restrict__ src, const int* __restrict__ dst,
                                  const float* __restrict__ ew, const float* __restrict__ t,
                                  float* __restrict__ score) {
    int e = blockIdx.x * blockDim.x + threadIdx.x;
    if (e >= ETOT) return;
    float w = ew[e];
    if (w != 0.f) atomicAdd(&score[dst[e]], w * t[src[e]]);
}

// topk also zeroes icount[0 : B*ksel) for the next layer's counting
template <int SZ>
__global__ void __launch_bounds__(512)
topk_kernel(const float* __restrict__ score, int n_per, int ksel,
            int* __restrict__ perm, float* __restrict__ gain, int* __restrict__ newid,
            int* __restrict__ icount) {
    __shared__ float sk[SZ];
    __shared__ int si[SZ];
    const int g = blockIdx.x;
    const int tid = threadIdx.x;
    for (int i = tid; i < SZ; i += 512) {
        if (i < n_per) { sk[i] = score[g * n_per + i]; si[i] = i; }
        else           { sk[i] = -INFINITY;            si[i] = 0x40000000 + i; }
    }
    __syncthreads();
    for (int kk = 2; kk <= SZ; kk <<= 1) {
        for (int j = kk >> 1; j > 0; j >>= 1) {
            for (int i = tid; i < SZ; i += 512) {
                int ixj = i ^ j;
                if (ixj > i) {
                    bool up = ((i & kk) == 0);
                    float s1 = sk[i], s2 = sk[ixj];
                    int i1 = si[i], i2 = si[ixj];
                    bool after = (s1 < s2) || (s1 == s2 && i1 > i2);
                    if (up == after) {
                        sk[i] = s2; sk[ixj] = s1;
                        si[i] = i2; si[ixj] = i1;
                    }
                }
            }
            __syncthreads();
        }
    }
    for (int r = tid; r < ksel; r += 512) {
        int old = g * n_per + si[r];
        int ng = g * ksel + r;
        perm[ng] = old;
        gain[ng] = tanhf(sk[r]);
        newid[old] = ng;
        icount[ng] = 0;
    }
}

__global__ void gather_split_kernel(const float* __restrict__ hin,
                                    __nv_bfloat16* __restrict__ hi,
                                    __nv_bfloat16* __restrict__ lo,
                                    const int* __restrict__ perm,
                                    const float* __restrict__ gain,
                                    int rows, int C4) {
    int idx = blockIdx.x * blockDim.x + threadIdx.x;
    if (idx >= rows * C4) return;
    int row = idx / C4;
    int c = idx - row * C4;
    float gn = gain[row];
    float4 v = ((const float4*)hin)[(size_t)perm[row] * C4 + c];
    v.x *= gn; v.y *= gn; v.z *= gn; v.w *= gn;
    __nv_bfloat16 h0 = __float2bfloat16(v.x);
    __nv_bfloat16 h1 = __float2bfloat16(v.y);
    __nv_bfloat16 h2 = __float2bfloat16(v.z);
    __nv_bfloat16 h3 = __float2bfloat16(v.w);
    __nv_bfloat162* hp = (__nv_bfloat162*)(hi) + 2 * idx;
    __nv_bfloat162* lp = (__nv_bfloat162*)(lo) + 2 * idx;
    hp[0] = __halves2bfloat162(h0, h1);
    hp[1] = __halves2bfloat162(h2, h3);
    lp[0] = __halves2bfloat162(__float2bfloat16(v.x - __bfloat162float(h0)),
                               __float2bfloat16(v.y - __bfloat162float(h1)));
    lp[1] = __halves2bfloat162(__float2bfloat16(v.z - __bfloat162float(h2)),
                               __float2bfloat16(v.w - __bfloat162float(h3)));
}

__global__ void remap_count_kernel(int* __restrict__ src, int* __restrict__ dst,
                                   float* __restrict__ ew, const int* __restrict__ newid,
                                   int* __restrict__ cnt) {
    int e = blockIdx.x * blockDim.x + threadIdx.x;
    if (e >= ETOT) return;
    int ns = newid[src[e]];
    int nd = newid[dst[e]];
    bool keep = (ns >= 0) && (nd >= 0) && (ew[e] != 0.f);
    src[e] = keep ? ns : 0;
    dst[e] = keep ? nd : 0;
    ew[e] = keep ? ew[e] : 0.f;
    if (keep) atomicAdd(&cnt[nd], 1);
}

__global__ void readout_kernel(const float* __restrict__ h, float* __restrict__ out) {
    int g = blockIdx.x;
    int c = threadIdx.x;
    const float* p = h + (size_t)(g * K3) * 256 + c;
    float mx = -INFINITY, sm = 0.f;
    for (int i = 0; i < K3; i++) {
        float v = p[(size_t)i * 256];
        mx = fmaxf(mx, v);
        sm += v;
    }
    out[g * 512 + c] = mx;
    out[g * 512 + 256 + c] = sm / (float)K3;
}

// ---------------- host orchestration ----------------

extern "C" void kernel_launch(void* const* d_in, const int* in_sizes, int n_in,
                              void* d_out, int out_size) {
    const float* x    = (const float*)d_in[0];
    const int*   ei   = (const int*)d_in[1];
    const float* W1   = (const float*)d_in[2];
    const float* b1   = (const float*)d_in[3];
    const float* W2   = (const float*)d_in[4];
    const float* b2   = (const float*)d_in[5];
    const float* W3   = (const float*)d_in[6];
    const float* b3   = (const float*)d_in[7];
    const float* W4   = (const float*)d_in[8];
    const float* b4   = (const float*)d_in[9];
    const float* g1   = (const float*)d_in[10];
    const float* be1  = (const float*)d_in[11];
    const float* g2   = (const float*)d_in[12];
    const float* be2  = (const float*)d_in[13];
    const float* g3   = (const float*)d_in[14];
    const float* be3  = (const float*)d_in[15];
    const float* p1rw = (const float*)d_in[16];
    const float* p1rb = (const float*)d_in[17];
    const float* p1ow = (const float*)d_in[18];
    const float* p2rw = (const float*)d_in[19];
    const float* p2rb = (const float*)d_in[20];
    const float* p2ow = (const float*)d_in[21];
    const float* p3rw = (const float*)d_in[22];
    const float* p3rb = (const float*)d_in[23];
    const float* p3ow = (const float*)d_in[24];
    float* out = (float*)d_out;

    float *buf0, *buf1, *dis, *score, *t, *gain, *ew, *bnstats, *enorm;
    int *src, *dst, *newid, *perm, *icount, *rowptr, *cursor, *esrc, *blocksum, *blockoff;
    __nv_bfloat16 *aHi, *aLo;
    __nv_bfloat16 *w1h, *w1l, *w2h, *w2l, *w3h, *w3l, *w4h, *w4l;
    cudaGetSymbolAddress((void**)&buf0, g_buf0);
    cudaGetSymbolAddress((void**)&buf1, g_buf1);
    cudaGetSymbolAddress((void**)&dis, g_dis);
    cudaGetSymbolAddress((void**)&score, g_score);
    cudaGetSymbolAddress((void**)&t, g_t);
    cudaGetSymbolAddress((void**)&gain, g_gain);
    cudaGetSymbolAddress((void**)&ew, g_ew);
    cudaGetSymbolAddress((void**)&bnstats, g_bnstats);
    cudaGetSymbolAddress((void**)&src, g_src);
    cudaGetSymbolAddress((void**)&dst, g_dst);
    cudaGetSymbolAddress((void**)&newid, g_newid);
    cudaGetSymbolAddress((void**)&perm, g_perm);
    cudaGetSymbolAddress((void**)&icount, g_icount);
    cudaGetSymbolAddress((void**)&rowptr, g_rowptr);
    cudaGetSymbolAddress((void**)&cursor, g_cursor);
    cudaGetSymbolAddress((void**)&esrc, g_esrc);
    cudaGetSymbolAddress((void**)&enorm, g_enorm);
    cudaGetSymbolAddress((void**)&blocksum, g_blocksum);
    cudaGetSymbolAddress((void**)&blockoff, g_blockoff);
    cudaGetSymbolAddress((void**)&aHi, g_aHi);
    cudaGetSymbolAddress((void**)&aLo, g_aLo);
    cudaGetSymbolAddress((void**)&w1h, g_w1Hi);
    cudaGetSymbolAddress((void**)&w1l, g_w1Lo);
    cudaGetSymbolAddress((void**)&w2h, g_w2Hi);
    cudaGetSymbolAddress((void**)&w2l, g_w2Lo);
    cudaGetSymbolAddress((void**)&w3h, g_w3Hi);
    cudaGetSymbolAddress((void**)&w3l, g_w3Lo);
    cudaGetSymbolAddress((void**)&w4h, g_w4Hi);
    cudaGetSymbolAddress((void**)&w4l, g_w4Lo);

    cudaFuncSetAttribute(wmma_gemm_kernel,
                         cudaFuncAttributeMaxDynamicSharedMemorySize, GEMM_SMEM);

    // persistent side stream + events
    static cudaStream_t s2 = nullptr;
    static cudaEvent_t evRoot, evW, evE, evCSR[4], evT[3];
    if (s2 == nullptr) {
        cudaStreamCreateWithFlags(&s2, cudaStreamNonBlocking);
        cudaEventCreateWithFlags(&evRoot, cudaEventDisableTiming);
        cudaEventCreateWithFlags(&evW, cudaEventDisableTiming);
        cudaEventCreateWithFlags(&evE, cudaEventDisableTiming);
        for (int i = 0; i < 4; i++) cudaEventCreateWithFlags(&evCSR[i], cudaEventDisableTiming);
        for (int i = 0; i < 3; i++) cudaEventCreateWithFlags(&evT[i], cudaEventDisableTiming);
    }

    const int EB = CEILDIV(ETOT, 256);
    const cudaStream_t s0 = 0;

    // ---- fork side stream; weight conversion there ----
    cudaEventRecord(evRoot, s0);
    cudaStreamWaitEvent(s2, evRoot, 0);
    convertW_all_kernel<<<CEILDIV(W4_END, 256), 256, 0, s2>>>(W1, W2, W3, W4,
                                                              w1h, w1l, w2h, w2l,
                                                              w3h, w3l, w4h, w4l);
    cudaEventRecord(evW, s2);

    // ---- main stream: activation split (+icount zero) and edge init ----
    {
        int n4 = N1 * 512 / 4;
        convertA_kernel<<<CEILDIV(n4, 256), 256, 0, s0>>>((const float4*)x,
                                                          (__nv_bfloat162*)aHi,
                                                          (__nv_bfloat162*)aLo, n4, icount);
    }
    edge_init_count_kernel<<<EB, 256, 0, s0>>>(ei, src, dst, ew, icount);
    cudaEventRecord(evE, s0);

    // 3-phase CSR build on side stream
    auto csr_chain = [&](int n) {
        int nb = CEILDIV(n, 1024);
        scan_partial_kernel<<<nb, 1024, 0, s2>>>(icount, rowptr, blocksum, n);
        scan_blocksums_kernel<<<1, 32, 0, s2>>>(blocksum, blockoff, rowptr, nb, n);
        scan_finalize_kernel<<<nb, 1024, 0, s2>>>(icount, rowptr, blockoff,
                                                  cursor, dis, newid, n);
        fill_kernel<<<EB, 256, 0, s2>>>(src, dst, ew, dis, cursor, esrc, enorm);
    };

    // ---- layer-1 CSR on side stream ----
    cudaStreamWaitEvent(s2, evE, 0);
    csr_chain(N1);
    cudaEventRecord(evCSR[0], s2);

    auto gemm = [&](int n, int Cin, int Cout,
                    const __nv_bfloat16* wh, const __nv_bfloat16* wl) {
        wmma_gemm_kernel<<<dim3(Cout / TBN, CEILDIV(n, TBM)), 256, GEMM_SMEM, s0>>>(
            aHi, aLo, wh, wl, buf1, n, Cin, Cout);
    };
    auto agg_bn_pool = [&](int n, int C, const float* b,
                           const float* gma, const float* bta,
                           const float* rw, const float* rb, const float* ow) {
        if (C == 512)
            gather_agg_kernel<512><<<n, 128, 0, s0>>>(buf1, rowptr, esrc, enorm, b, buf0, bnstats);
        else
            gather_agg_kernel<256><<<n, 64, 0, s0>>>(buf1, rowptr, esrc, enorm, b, buf0, bnstats);
        bn_stats_kernel<<<dim3(CEILDIV(C, 256), 64), 256, 0, s0>>>(buf0, bnstats, n, C);
        bn_dots_kernel<<<CEILDIV(n * 32, 256), 256, 0, s0>>>(buf0, bnstats, gma, bta,
                                                             rw, ow, rb, t, score, n, C);
        score_edge_kernel<<<EB, 256, 0, s0>>>(src, dst, ew, t, score);
    };
    auto side_csr = [&](int li, int nNext) {
        cudaStreamWaitEvent(s2, evT[li], 0);
        remap_count_kernel<<<EB, 256, 0, s2>>>(src, dst, ew, newid, icount);
        csr_chain(nNext);
        cudaEventRecord(evCSR[li + 1], s2);
    };

    // ---------- Layer 1 ----------
    cudaStreamWaitEvent(s0, evW, 0);
    gemm(N1, 512, 512, w1h, w1l);
    cudaStreamWaitEvent(s0, evCSR[0], 0);
    agg_bn_pool(N1, 512, b1, g1, be1, p1rw, p1rb, p1ow);
    topk_kernel<1024><<<BATCH, 512, 0, s0>>>(score, 1024, K1, perm, gain, newid, icount);
    cudaEventRecord(evT[0], s0);
    side_csr(0, N2);
    gather_split_kernel<<<CEILDIV(N2 * 128, 256), 256, 0, s0>>>(buf0, aHi, aLo, perm, gain,
                                                                N2, 128);

    // ---------- Layer 2 ----------
    gemm(N2, 512, 512, w2h, w2l);
    cudaStreamWaitEvent(s0, evCSR[1], 0);
    agg_bn_pool(N2, 512, b2, g2, be2, p2rw, p2rb, p2ow);
    topk_kernel<1024><<<BATCH, 512, 0, s0>>>(score, K1, K2, perm, gain, newid, icount);
    cudaEventRecord(evT[1], s0);
    side_csr(1, N3);
    gather_split_kernel<<<CEILDIV(N3 * 128, 256), 256, 0, s0>>>(buf0, aHi, aLo, perm, gain,
                                                                N3, 128);

    // ---------- Layer 3 ----------
    gemm(N3, 512, 256, w3h, w3l);
    cudaStreamWaitEvent(s0, evCSR[2], 0);
    agg_bn_pool(N3, 256, b3, g3, be3, p3rw, p3rb, p3ow);
    topk_kernel<512><<<BATCH, 512, 0, s0>>>(score, K2, K3, perm, gain, newid, icount);
    cudaEventRecord(evT[2], s0);
    side_csr(2, N4);
    gather_split_kernel<<<CEILDIV(N4 * 64, 256), 256, 0, s0>>>(buf0, aHi, aLo, perm, gain,
                                                               N4, 64);

    // ---------- Layer 4 (no BN / pool) ----------
    gemm(N4, 256, 256, w4h, w4l);
    cudaStreamWaitEvent(s0, evCSR[3], 0);
    gather_agg_kernel<256><<<N4, 64, 0, s0>>>(buf1, rowptr, esrc, enorm, b4, buf0, bnstats);

    // ---------- readout ----------
    readout_kernel<<<BATCH, 256, 0, s0>>>(buf0, out);
    (void)in_sizes; (void)n_in; (void)out_size;
}

// round 15
// speedup vs baseline: 1.1758x; 1.0034x over previous
#include <cuda_runtime.h>
#include <cuda_bf16.h>
#include <mma.h>
#include <math.h>
#include <stdint.h>

using namespace nvcuda;

// ---------------- problem constants ----------------
#define BATCH   32
#define ETOT    262144
#define NMAX    32768
#define K1      615
#define K2      369
#define K3      185
#define N1      32768
#define N2      (BATCH*K1)      // 19680
#define N3      (BATCH*K2)      // 11808
#define N4      (BATCH*K3)      // 5920

#define CEILDIV(a,b) (((a)+(b)-1)/(b))

// ---------------- static device scratch ----------------
__device__ float g_buf0[(size_t)NMAX * 512];
__device__ float g_buf1[(size_t)NMAX * 512];
__device__ float g_dis[NMAX];
__device__ float g_score[NMAX];
__device__ float g_t[NMAX];
__device__ float g_gain[NMAX];
__device__ int   g_newid[NMAX];
__device__ int   g_perm[NMAX];
__device__ int   g_src[ETOT];
__device__ int   g_dst[ETOT];
__device__ float g_ew[ETOT];
__device__ float g_bnstats[1024];
// CSR scratch
__device__ int   g_icount[NMAX];
__device__ int   g_rowptr[NMAX + 1];
__device__ int   g_cursor[NMAX];
__device__ int   g_esrc[ETOT];
__device__ float g_enorm[ETOT];
__device__ int   g_blocksum[32];
__device__ int   g_blockoff[32];
// bf16 split-precision GEMM scratch
__device__ __nv_bfloat16 g_aHi[(size_t)NMAX * 512];
__device__ __nv_bfloat16 g_aLo[(size_t)NMAX * 512];
__device__ __nv_bfloat16 g_w1Hi[512 * 512], g_w1Lo[512 * 512];
__device__ __nv_bfloat16 g_w2Hi[512 * 512], g_w2Lo[512 * 512];
__device__ __nv_bfloat16 g_w3Hi[256 * 512], g_w3Lo[256 * 512];
__device__ __nv_bfloat16 g_w4Hi[256 * 256], g_w4Lo[256 * 256];

// ---------------- kernels ----------------

__global__ void edge_init_count_kernel(const int* __restrict__ ei,
                                       int* __restrict__ src, int* __restrict__ dst,
                                       float* __restrict__ ew, int* __restrict__ cnt) {
    int e = blockIdx.x * blockDim.x + threadIdx.x;
    if (e >= ETOT) return;
    int d = ei[ETOT + e];
    src[e] = ei[e];
    dst[e] = d;
    ew[e]  = 1.0f;
    atomicAdd(&cnt[d], 1);
}

// layer-1 activations; also zeroes icount[0:N1)
__global__ void convertA_kernel(const float4* __restrict__ A,
                                __nv_bfloat162* __restrict__ hi2,
                                __nv_bfloat162* __restrict__ lo2, int n4,
                                int* __restrict__ icount) {
    int i = blockIdx.x * blockDim.x + threadIdx.x;
    if (i >= n4) return;
    if (i < N1) icount[i] = 0;
    float4 v = A[i];
    __nv_bfloat16 h0 = __float2bfloat16(v.x);
    __nv_bfloat16 h1 = __float2bfloat16(v.y);
    __nv_bfloat16 h2 = __float2bfloat16(v.z);
    __nv_bfloat16 h3 = __float2bfloat16(v.w);
    hi2[2 * i]     = __halves2bfloat162(h0, h1);
    hi2[2 * i + 1] = __halves2bfloat162(h2, h3);
    lo2[2 * i]     = __halves2bfloat162(__float2bfloat16(v.x - __bfloat162float(h0)),
                                        __float2bfloat16(v.y - __bfloat162float(h1)));
    lo2[2 * i + 1] = __halves2bfloat162(__float2bfloat16(v.z - __bfloat162float(h2)),
                                        __float2bfloat16(v.w - __bfloat162float(h3)));
}

// all 4 weight matrices: W [K,N] fp32 -> WT_hi/lo [N,K] bf16
#define W1_ELEMS (512 * 512)
#define W2_END   (2 * W1_ELEMS)
#define W3_END   (W2_END + 256 * 512)
#define W4_END   (W3_END + 256 * 256)
__global__ void convertW_all_kernel(const float* __restrict__ W1, const float* __restrict__ W2,
                                    const float* __restrict__ W3, const float* __restrict__ W4,
                                    __nv_bfloat16* w1h, __nv_bfloat16* w1l,
                                    __nv_bfloat16* w2h, __nv_bfloat16* w2l,
                                    __nv_bfloat16* w3h, __nv_bfloat16* w3l,
                                    __nv_bfloat16* w4h, __nv_bfloat16* w4l) {
    int idx = blockIdx.x * blockDim.x + threadIdx.x;
    const float* W; __nv_bfloat16 *h, *l; int K, N, local;
    if (idx < W1_ELEMS)      { W = W1; h = w1h; l = w1l; K = 512; N = 512; local = idx; }
    else if (idx < W2_END)   { W = W2; h = w2h; l = w2l; K = 512; N = 512; local = idx - W1_ELEMS; }
    else if (idx < W3_END)   { W = W3; h = w3h; l = w3l; K = 512; N = 256; local = idx - W2_END; }
    else if (idx < W4_END)   { W = W4; h = w4h; l = w4l; K = 256; N = 256; local = idx - W3_END; }
    else return;
    int n = local / K, k = local - n * K;
    float v = W[k * N + n];
    __nv_bfloat16 hh = __float2bfloat16(v);
    h[local] = hh;
    l[local] = __float2bfloat16(v - __bfloat162float(hh));
}

// ---------------------------------------------------------------
// WMMA bf16 split-precision GEMM (unchanged).
// ---------------------------------------------------------------
#define TBM 128
#define TBN 128
#define TBK 32
#define WLDA 40
#define TILE_BYTES (128 * WLDA * 2)
#define TILE_ELEMS (128 * WLDA)
#define STAGE_BYTES (4 * TILE_BYTES)
#define GEMM_SMEM (2 * STAGE_BYTES)

__device__ __forceinline__ void cp16(uint32_t s, const void* g, int sz) {
    asm volatile("cp.async.cg.shared.global [%0], [%1], 16, %2;"
                 :: "r"(s), "l"(g), "r"(sz));
}

__global__ void __launch_bounds__(256, 2)
wmma_gemm_kernel(const __nv_bfloat16* __restrict__ Ahi,
                 const __nv_bfloat16* __restrict__ Alo,
                 const __nv_bfloat16* __restrict__ Bhi,
                 const __nv_bfloat16* __restrict__ Blo,
                 float* __restrict__ C, int M, int K, int N) {
    extern __shared__ __nv_bfloat16 sm[];

    const int tid = threadIdx.x;
    const int wid = tid >> 5;
    const int warpM = wid & 1;
    const int warpN = wid >> 1;
    const int mBase = blockIdx.y * TBM;
    const int nBase = blockIdx.x * TBN;

    wmma::fragment<wmma::accumulator, 16, 16, 16, float> acc[4][2];
#pragma unroll
    for (int i = 0; i < 4; i++)
#pragma unroll
        for (int j = 0; j < 2; j++) wmma::fill_fragment(acc[i][j], 0.f);

    const uint32_t sbase = (uint32_t)__cvta_generic_to_shared(sm);
    const int row = tid >> 1;
    const int q0 = (tid & 1) * 2;
    const int grow = mBase + row;
    const int nrow = nBase + row;
    const size_t aoff = (size_t)(grow < M ? grow : 0) * K;
    const size_t boff = (size_t)nrow * K;
    const int szA = (grow < M) ? 16 : 0;
    const uint32_t srow = sbase + (uint32_t)row * (WLDA * 2);

#define LOAD_STAGE(s, kc) do { \
        uint32_t s0 = srow + (uint32_t)(s) * STAGE_BYTES; \
        _Pragma("unroll") \
        for (int qq = 0; qq < 2; qq++) { \
            int q = q0 + qq; \
            cp16(s0 + q * 16,                  Ahi + aoff + (kc) + q * 8, szA); \
            cp16(s0 + q * 16 + TILE_BYTES,     Alo + aoff + (kc) + q * 8, szA); \
            cp16(s0 + q * 16 + 2 * TILE_BYTES, Bhi + boff + (kc) + q * 8, 16); \
            cp16(s0 + q * 16 + 3 * TILE_BYTES, Blo + boff + (kc) + q * 8, 16); \
        } \
    } while (0)

    LOAD_STAGE(0, 0);
    asm volatile("cp.async.commit_group;" ::: "memory");

    const int nCh = K >> 5;
    for (int ch = 0; ch < nCh; ch++) {
        if (ch + 1 < nCh) {
            LOAD_STAGE((ch + 1) & 1, (ch + 1) << 5);
            asm volatile("cp.async.commit_group;" ::: "memory");
            asm volatile("cp.async.wait_group 1;" ::: "memory");
        } else {
            asm volatile("cp.async.wait_group 0;" ::: "memory");
        }
        __syncthreads();

        const __nv_bfloat16* sb   = sm + (ch & 1) * (4 * TILE_ELEMS);
        const __nv_bfloat16* sAhi = sb;
        const __nv_bfloat16* sAlo = sb + TILE_ELEMS;
        const __nv_bfloat16* sBhi = sb + 2 * TILE_ELEMS;
        const __nv_bfloat16* sBlo = sb + 3 * TILE_ELEMS;

#pragma unroll
        for (int ks = 0; ks < TBK; ks += 16) {
            wmma::fragment<wmma::matrix_b, 16, 16, 16, __nv_bfloat16, wmma::col_major> bh[2], bl[2];
#pragma unroll
            for (int j = 0; j < 2; j++) {
                wmma::load_matrix_sync(bh[j], sBhi + (warpN * 32 + j * 16) * WLDA + ks, WLDA);
                wmma::load_matrix_sync(bl[j], sBlo + (warpN * 32 + j * 16) * WLDA + ks, WLDA);
            }
#pragma unroll
            for (int i = 0; i < 4; i++) {
                wmma::fragment<wmma::matrix_a, 16, 16, 16, __nv_bfloat16, wmma::row_major> ah, al;
                wmma::load_matrix_sync(ah, sAhi + (warpM * 64 + i * 16) * WLDA + ks, WLDA);
                wmma::load_matrix_sync(al, sAlo + (warpM * 64 + i * 16) * WLDA + ks, WLDA);
#pragma unroll
                for (int j = 0; j < 2; j++) wmma::mma_sync(acc[i][j], ah, bh[j], acc[i][j]);
#pragma unroll
                for (int j = 0; j < 2; j++) wmma::mma_sync(acc[i][j], ah, bl[j], acc[i][j]);
#pragma unroll
                for (int j = 0; j < 2; j++) wmma::mma_sync(acc[i][j], al, bh[j], acc[i][j]);
            }
        }
        __syncthreads();
    }
#undef LOAD_STAGE

#pragma unroll
    for (int i = 0; i < 4; i++) {
        int r0 = mBase + warpM * 64 + i * 16;
#pragma unroll
        for (int j = 0; j < 2; j++) {
            float* cp = C + (size_t)r0 * N + nBase + warpN * 32 + j * 16;
            wmma::store_matrix_sync(cp, acc[i][j], N, wmma::mem_row_major);
        }
    }
}

// ---------------- CSR build (3-phase coalesced scan) ----------------

__global__ void __launch_bounds__(1024)
scan_partial_kernel(const int* __restrict__ cnt, int* __restrict__ rowptr,
                    int* __restrict__ blocksum, int n) {
    __shared__ int warpsum[32];
    const int tid = threadIdx.x;
    const int i = blockIdx.x * 1024 + tid;
    int v = (i < n) ? cnt[i] : 0;
    const int s = v;

    const int lane = tid & 31, wid = tid >> 5;
#pragma unroll
    for (int off = 1; off < 32; off <<= 1) {
        int u = __shfl_up_sync(0xffffffffu, v, off);
        if (lane >= off) v += u;
    }
    if (lane == 31) warpsum[wid] = v;
    __syncthreads();
    if (wid == 0) {
        int w = warpsum[lane];
#pragma unroll
        for (int off = 1; off < 32; off <<= 1) {
            int u = __shfl_up_sync(0xffffffffu, w, off);
            if (lane >= off) w += u;
        }
        warpsum[lane] = w;
    }
    __syncthreads();
    int excl = v - s + (wid > 0 ? warpsum[wid - 1] : 0);
    if (i < n) rowptr[i] = excl;
    if (tid == 1023) blocksum[blockIdx.x] = excl + s;
}

__global__ void scan_blocksums_kernel(const int* __restrict__ blocksum,
                                      int* __restrict__ blockoff,
                                      int* __restrict__ rowptr,
                                      int nblocks, int n) {
    const int lane = threadIdx.x;
    int v = (lane < nblocks) ? blocksum[lane] : 0;
    const int s = v;
#pragma unroll
    for (int off = 1; off < 32; off <<= 1) {
        int u = __shfl_up_sync(0xffffffffu, v, off);
        if (lane >= off) v += u;
    }
    if (lane < nblocks) blockoff[lane] = v - s;
    if (lane == 31) rowptr[n] = v;
}

__global__ void __launch_bounds__(1024)
scan_finalize_kernel(const int* __restrict__ cnt, int* __restrict__ rowptr,
                     const int* __restrict__ blockoff,
                     int* __restrict__ cursor, float* __restrict__ dis,
                     int* __restrict__ newid, int n) {
    const int i = blockIdx.x * 1024 + threadIdx.x;
    if (i >= n) return;
    int r = rowptr[i] + blockoff[blockIdx.x];
    rowptr[i] = r;
    cursor[i] = r;
    int c = cnt[i];
    dis[i] = (c > 0) ? rsqrtf((float)c) : 0.f;
    newid[i] = -1;
}

__global__ void fill_kernel(const int* __restrict__ src, const int* __restrict__ dst,
                            const float* __restrict__ ew, const float* __restrict__ dis,
                            int* __restrict__ cursor,
                            int* __restrict__ esrc, float* __restrict__ enorm) {
    int e = blockIdx.x * blockDim.x + threadIdx.x;
    if (e >= ETOT) return;
    float w = ew[e];
    if (w == 0.f) return;
    int s = src[e], d = dst[e];
    int pos = atomicAdd(&cursor[d], 1);
    esrc[pos] = s;
    enorm[pos] = dis[s] * dis[d] * w;
}

// one block per node, C/4 threads; 4-deep unrolled edge loop; block 0 zeroes bnstats
template <int C>
__global__ void gather_agg_kernel(const float* __restrict__ h,
                                  const int* __restrict__ rowptr,
                                  const int* __restrict__ esrc,
                                  const float* __restrict__ enorm,
                                  const float* __restrict__ bias,
                                  float* __restrict__ out,
                                  float* __restrict__ bnstats) {
    const int node = blockIdx.x;
    const int tid = threadIdx.x;
    if (node == 0)
        for (int k = tid; k < 1024; k += (C / 4)) bnstats[k] = 0.f;
    float4 acc = *(const float4*)(bias + tid * 4);
    int b = rowptr[node];
    const int e = rowptr[node + 1];
    for (; b + 3 < e; b += 4) {
        int s0 = esrc[b],     s1 = esrc[b + 1], s2 = esrc[b + 2], s3 = esrc[b + 3];
        float n0 = enorm[b],  n1 = enorm[b + 1], n2 = enorm[b + 2], n3 = enorm[b + 3];
        float4 v0 = *(const float4*)(h + (size_t)s0 * C + tid * 4);
        float4 v1 = *(const float4*)(h + (size_t)s1 * C + tid * 4);
        float4 v2 = *(const float4*)(h + (size_t)s2 * C + tid * 4);
        float4 v3 = *(const float4*)(h + (size_t)s3 * C + tid * 4);
        acc.x += v0.x * n0; acc.y += v0.y * n0; acc.z += v0.z * n0; acc.w += v0.w * n0;
        acc.x += v1.x * n1; acc.y += v1.y * n1; acc.z += v1.z * n1; acc.w += v1.w * n1;
        acc.x += v2.x * n2; acc.y += v2.y * n2; acc.z += v2.z * n2; acc.w += v2.w * n2;
        acc.x += v3.x * n3; acc.y += v3.y * n3; acc.z += v3.z * n3; acc.w += v3.w * n3;
    }
    for (; b < e; b++) {
        int s0 = esrc[b];
        float n0 = enorm[b];
        float4 v0 = *(const float4*)(h + (size_t)s0 * C + tid * 4);
        acc.x += v0.x * n0; acc.y += v0.y * n0; acc.z += v0.z * n0; acc.w += v0.w * n0;
    }
    *(float4*)(out + (size_t)node * C + tid * 4) = acc;
}

// ---------------- BN / pool / misc ----------------

__global__ void bn_stats_kernel(const float* __restrict__ h,
                                float* __restrict__ bnstats,
                                int n, int C) {
    int c = blockIdx.x * 256 + threadIdx.x;
    if (c >= C) return;
    int rowsPer = CEILDIV(n, gridDim.y);
    int r0 = blockIdx.y * rowsPer;
    int r1 = min(n, r0 + rowsPer);
    float s = 0.f, sq = 0.f;
    for (int r = r0; r < r1; r++) {
        float v = h[(size_t)r * C + c];
        s += v;
        sq += v * v;
    }
    atomicAdd(&bnstats[c], s);
    atomicAdd(&bnstats[512 + c], sq);
}

// BN(apply)+tanh + pool dot-products, READ-ONLY on h (no writeback)
__global__ void bn_dots_kernel(const float* __restrict__ h,
                               const float* __restrict__ bnstats,
                               const float* __restrict__ gma, const float* __restrict__ bta,
                               const float* __restrict__ relw, const float* __restrict__ rootw,
                               const float* __restrict__ relb,
                               float* __restrict__ t, float* __restrict__ score,
                               int n, int C) {
    int node = (blockIdx.x * blockDim.x + threadIdx.x) >> 5;
    int lane = threadIdx.x & 31;
    if (node >= n) return;
    const float* hp = h + (size_t)node * C;
    const float invn = 1.f / (float)n;
    float a = 0.f, b = 0.f;
    for (int c = lane; c < C; c += 32) {
        float mean = bnstats[c] * invn;
        float var = bnstats[512 + c] * invn - mean * mean;
        float y = tanhf((hp[c] - mean) * rsqrtf(var + 1e-5f) * gma[c] + bta[c]);
        a += y * relw[c];
        b += y * rootw[c];
    }
#pragma unroll
    for (int o = 16; o > 0; o >>= 1) {
        a += __shfl_down_sync(0xffffffffu, a, o);
        b += __shfl_down_sync(0xffffffffu, b, o);
    }
    if (lane == 0) {
        t[node] = a;
        score[node] = b + relb[0];
    }
}

__global__ void score_edge_kernel(const int* __restrict__ src, const int* __restrict__ dst,
                                  const float* __restrict__ ew, const float* __restrict__ t,
                                  float* __restrict__ score) {
    int e = blockIdx.x * blockDim.x + threadIdx.x;
    if (e >= ETOT) return;
    float w = ew[e];
    if (w != 0.f) atomicAdd(&score[dst[e]], w * t[src[e]]);
}

// topk also zeroes icount[0 : B*ksel)
template <int SZ>
__global__ void __launch_bounds__(512)
topk_kernel(const float* __restrict__ score, int n_per, int ksel,
            int* __restrict__ perm, float* __restrict__ gain, int* __restrict__ newid,
            int* __restrict__ icount) {
    __shared__ float sk[SZ];
    __shared__ int si[SZ];
    const int g = blockIdx.x;
    const int tid = threadIdx.x;
    for (int i = tid; i < SZ; i += 512) {
        if (i < n_per) { sk[i] = score[g * n_per + i]; si[i] = i; }
        else           { sk[i] = -INFINITY;            si[i] = 0x40000000 + i; }
    }
    __syncthreads();
    for (int kk = 2; kk <= SZ; kk <<= 1) {
        for (int j = kk >> 1; j > 0; j >>= 1) {
            for (int i = tid; i < SZ; i += 512) {
                int ixj = i ^ j;
                if (ixj > i) {
                    bool up = ((i & kk) == 0);
                    float s1 = sk[i], s2 = sk[ixj];
                    int i1 = si[i], i2 = si[ixj];
                    bool after = (s1 < s2) || (s1 == s2 && i1 > i2);
                    if (up == after) {
                        sk[i] = s2; sk[ixj] = s1;
                        si[i] = i2; si[ixj] = i1;
                    }
                }
            }
            __syncthreads();
        }
    }
    for (int r = tid; r < ksel; r += 512) {
        int old = g * n_per + si[r];
        int ng = g * ksel + r;
        perm[ng] = old;
        gain[ng] = tanhf(sk[r]);
        newid[old] = ng;
        icount[ng] = 0;
    }
}

// pool gather: applies BN+tanh (from raw agg) then *gain, then bf16 hi/lo split
__global__ void gather_split_kernel(const float* __restrict__ hin,
                                    __nv_bfloat16* __restrict__ hi,
                                    __nv_bfloat16* __restrict__ lo,
                                    const int* __restrict__ perm,
                                    const float* __restrict__ gain,
                                    const float* __restrict__ bnstats,
                                    const float* __restrict__ gma,
                                    const float* __restrict__ bta,
                                    float invn,
                                    int rows, int C4) {
    int idx = blockIdx.x * blockDim.x + threadIdx.x;
    if (idx >= rows * C4) return;
    int row = idx / C4;
    int c4 = idx - row * C4;
    int c = c4 * 4;
    float gn = gain[row];
    float4 v = ((const float4*)hin)[(size_t)perm[row] * C4 + c4];
    float m0 = bnstats[c + 0] * invn, m1 = bnstats[c + 1] * invn;
    float m2 = bnstats[c + 2] * invn, m3 = bnstats[c + 3] * invn;
    float r0 = rsqrtf(bnstats[512 + c + 0] * invn - m0 * m0 + 1e-5f) * gma[c + 0];
    float r1 = rsqrtf(bnstats[512 + c + 1] * invn - m1 * m1 + 1e-5f) * gma[c + 1];
    float r2 = rsqrtf(bnstats[512 + c + 2] * invn - m2 * m2 + 1e-5f) * gma[c + 2];
    float r3 = rsqrtf(bnstats[512 + c + 3] * invn - m3 * m3 + 1e-5f) * gma[c + 3];
    v.x = tanhf((v.x - m0) * r0 + bta[c + 0]) * gn;
    v.y = tanhf((v.y - m1) * r1 + bta[c + 1]) * gn;
    v.z = tanhf((v.z - m2) * r2 + bta[c + 2]) * gn;
    v.w = tanhf((v.w - m3) * r3 + bta[c + 3]) * gn;
    __nv_bfloat16 h0 = __float2bfloat16(v.x);
    __nv_bfloat16 h1 = __float2bfloat16(v.y);
    __nv_bfloat16 h2 = __float2bfloat16(v.z);
    __nv_bfloat16 h3 = __float2bfloat16(v.w);
    __nv_bfloat162* hp = (__nv_bfloat162*)(hi) + 2 * idx;
    __nv_bfloat162* lp = (__nv_bfloat162*)(lo) + 2 * idx;
    hp[0] = __halves2bfloat162(h0, h1);
    hp[1] = __halves2bfloat162(h2, h3);
    lp[0] = __halves2bfloat162(__float2bfloat16(v.x - __bfloat162float(h0)),
                               __float2bfloat16(v.y - __bfloat162float(h1)));
    lp[1] = __halves2bfloat162(__float2bfloat16(v.z - __bfloat162float(h2)),
                               __float2bfloat16(v.w - __bfloat162float(h3)));
}

__global__ void remap_count_kernel(int* __restrict__ src, int* __restrict__ dst,
                                   float* __restrict__ ew, const int* __restrict__ newid,
                                   int* __restrict__ cnt) {
    int e = blockIdx.x * blockDim.x + threadIdx.x;
    if (e >= ETOT) return;
    int ns = newid[src[e]];
    int nd = newid[dst[e]];
    bool keep = (ns >= 0) && (nd >= 0) && (ew[e] != 0.f);
    src[e] = keep ? ns : 0;
    dst[e] = keep ? nd : 0;
    ew[e] = keep ? ew[e] : 0.f;
    if (keep) atomicAdd(&cnt[nd], 1);
}

__global__ void readout_kernel(const float* __restrict__ h, float* __restrict__ out) {
    int g = blockIdx.x;
    int c = threadIdx.x;
    const float* p = h + (size_t)(g * K3) * 256 + c;
    float mx = -INFINITY, sm = 0.f;
    for (int i = 0; i < K3; i++) {
        float v = p[(size_t)i * 256];
        mx = fmaxf(mx, v);
        sm += v;
    }
    out[g * 512 + c] = mx;
    out[g * 512 + 256 + c] = sm / (float)K3;
}

// ---------------- host orchestration ----------------

extern "C" void kernel_launch(void* const* d_in, const int* in_sizes, int n_in,
                              void* d_out, int out_size) {
    const float* x    = (const float*)d_in[0];
    const int*   ei   = (const int*)d_in[1];
    const float* W1   = (const float*)d_in[2];
    const float* b1   = (const float*)d_in[3];
    const float* W2   = (const float*)d_in[4];
    const float* b2   = (const float*)d_in[5];
    const float* W3   = (const float*)d_in[6];
    const float* b3   = (const float*)d_in[7];
    const float* W4   = (const float*)d_in[8];
    const float* b4   = (const float*)d_in[9];
    const float* g1   = (const float*)d_in[10];
    const float* be1  = (const float*)d_in[11];
    const float* g2   = (const float*)d_in[12];
    const float* be2  = (const float*)d_in[13];
    const float* g3   = (const float*)d_in[14];
    const float* be3  = (const float*)d_in[15];
    const float* p1rw = (const float*)d_in[16];
    const float* p1rb = (const float*)d_in[17];
    const float* p1ow = (const float*)d_in[18];
    const float* p2rw = (const float*)d_in[19];
    const float* p2rb = (const float*)d_in[20];
    const float* p2ow = (const float*)d_in[21];
    const float* p3rw = (const float*)d_in[22];
    const float* p3rb = (const float*)d_in[23];
    const float* p3ow = (const float*)d_in[24];
    float* out = (float*)d_out;

    float *buf0, *buf1, *dis, *score, *t, *gain, *ew, *bnstats, *enorm;
    int *src, *dst, *newid, *perm, *icount, *rowptr, *cursor, *esrc, *blocksum, *blockoff;
    __nv_bfloat16 *aHi, *aLo;
    __nv_bfloat16 *w1h, *w1l, *w2h, *w2l, *w3h, *w3l, *w4h, *w4l;
    cudaGetSymbolAddress((void**)&buf0, g_buf0);
    cudaGetSymbolAddress((void**)&buf1, g_buf1);
    cudaGetSymbolAddress((void**)&dis, g_dis);
    cudaGetSymbolAddress((void**)&score, g_score);
    cudaGetSymbolAddress((void**)&t, g_t);
    cudaGetSymbolAddress((void**)&gain, g_gain);
    cudaGetSymbolAddress((void**)&ew, g_ew);
    cudaGetSymbolAddress((void**)&bnstats, g_bnstats);
    cudaGetSymbolAddress((void**)&src, g_src);
    cudaGetSymbolAddress((void**)&dst, g_dst);
    cudaGetSymbolAddress((void**)&newid, g_newid);
    cudaGetSymbolAddress((void**)&perm, g_perm);
    cudaGetSymbolAddress((void**)&icount, g_icount);
    cudaGetSymbolAddress((void**)&rowptr, g_rowptr);
    cudaGetSymbolAddress((void**)&cursor, g_cursor);
    cudaGetSymbolAddress((void**)&esrc, g_esrc);
    cudaGetSymbolAddress((void**)&enorm, g_enorm);
    cudaGetSymbolAddress((void**)&blocksum, g_blocksum);
    cudaGetSymbolAddress((void**)&blockoff, g_blockoff);
    cudaGetSymbolAddress((void**)&aHi, g_aHi);
    cudaGetSymbolAddress((void**)&aLo, g_aLo);
    cudaGetSymbolAddress((void**)&w1h, g_w1Hi);
    cudaGetSymbolAddress((void**)&w1l, g_w1Lo);
    cudaGetSymbolAddress((void**)&w2h, g_w2Hi);
    cudaGetSymbolAddress((void**)&w2l, g_w2Lo);
    cudaGetSymbolAddress((void**)&w3h, g_w3Hi);
    cudaGetSymbolAddress((void**)&w3l, g_w3Lo);
    cudaGetSymbolAddress((void**)&w4h, g_w4Hi);
    cudaGetSymbolAddress((void**)&w4l, g_w4Lo);

    cudaFuncSetAttribute(wmma_gemm_kernel,
                         cudaFuncAttributeMaxDynamicSharedMemorySize, GEMM_SMEM);

    static cudaStream_t s2 = nullptr;
    static cudaEvent_t evRoot, evW, evE, evCSR[4], evT[3];
    if (s2 == nullptr) {
        cudaStreamCreateWithFlags(&s2, cudaStreamNonBlocking);
        cudaEventCreateWithFlags(&evRoot, cudaEventDisableTiming);
        cudaEventCreateWithFlags(&evW, cudaEventDisableTiming);
        cudaEventCreateWithFlags(&evE, cudaEventDisableTiming);
        for (int i = 0; i < 4; i++) cudaEventCreateWithFlags(&evCSR[i], cudaEventDisableTiming);
        for (int i = 0; i < 3; i++) cudaEventCreateWithFlags(&evT[i], cudaEventDisableTiming);
    }

    const int EB = CEILDIV(ETOT, 256);
    const cudaStream_t s0 = 0;

    cudaEventRecord(evRoot, s0);
    cudaStreamWaitEvent(s2, evRoot, 0);
    convertW_all_kernel<<<CEILDIV(W4_END, 256), 256, 0, s2>>>(W1, W2, W3, W4,
                                                              w1h, w1l, w2h, w2l,
                                                              w3h, w3l, w4h, w4l);
    cudaEventRecord(evW, s2);

    {
        int n4 = N1 * 512 / 4;
        convertA_kernel<<<CEILDIV(n4, 256), 256, 0, s0>>>((const float4*)x,
                                                          (__nv_bfloat162*)aHi,
                                                          (__nv_bfloat162*)aLo, n4, icount);
    }
    edge_init_count_kernel<<<EB, 256, 0, s0>>>(ei, src, dst, ew, icount);
    cudaEventRecord(evE, s0);

    auto csr_chain = [&](int n) {
        int nb = CEILDIV(n, 1024);
        scan_partial_kernel<<<nb, 1024, 0, s2>>>(icount, rowptr, blocksum, n);
        scan_blocksums_kernel<<<1, 32, 0, s2>>>(blocksum, blockoff, rowptr, nb, n);
        scan_finalize_kernel<<<nb, 1024, 0, s2>>>(icount, rowptr, blockoff,
                                                  cursor, dis, newid, n);
        fill_kernel<<<EB, 256, 0, s2>>>(src, dst, ew, dis, cursor, esrc, enorm);
    };

    cudaStreamWaitEvent(s2, evE, 0);
    csr_chain(N1);
    cudaEventRecord(evCSR[0], s2);

    auto gemm = [&](int n, int Cin, int Cout,
                    const __nv_bfloat16* wh, const __nv_bfloat16* wl) {
        wmma_gemm_kernel<<<dim3(Cout / TBN, CEILDIV(n, TBM)), 256, GEMM_SMEM, s0>>>(
            aHi, aLo, wh, wl, buf1, n, Cin, Cout);
    };
    auto agg_bn_pool = [&](int n, int C, const float* b,
                           const float* gma, const float* bta,
                           const float* rw, const float* rb, const float* ow) {
        if (C == 512)
            gather_agg_kernel<512><<<n, 128, 0, s0>>>(buf1, rowptr, esrc, enorm, b, buf0, bnstats);
        else
            gather_agg_kernel<256><<<n, 64, 0, s0>>>(buf1, rowptr, esrc, enorm, b, buf0, bnstats);
        bn_stats_kernel<<<dim3(CEILDIV(C, 256), 128), 256, 0, s0>>>(buf0, bnstats, n, C);
        bn_dots_kernel<<<CEILDIV(n * 32, 256), 256, 0, s0>>>(buf0, bnstats, gma, bta,
                                                             rw, ow, rb, t, score, n, C);
        score_edge_kernel<<<EB, 256, 0, s0>>>(src, dst, ew, t, score);
    };
    auto side_csr = [&](int li, int nNext) {
        cudaStreamWaitEvent(s2, evT[li], 0);
        remap_count_kernel<<<EB, 256, 0, s2>>>(src, dst, ew, newid, icount);
        csr_chain(nNext);
        cudaEventRecord(evCSR[li + 1], s2);
    };

    // ---------- Layer 1 ----------
    cudaStreamWaitEvent(s0, evW, 0);
    gemm(N1, 512, 512, w1h, w1l);
    cudaStreamWaitEvent(s0, evCSR[0], 0);
    agg_bn_pool(N1, 512, b1, g1, be1, p1rw, p1rb, p1ow);
    topk_kernel<1024><<<BATCH, 512, 0, s0>>>(score, 1024, K1, perm, gain, newid, icount);
    cudaEventRecord(evT[0], s0);
    side_csr(0, N2);
    gather_split_kernel<<<CEILDIV(N2 * 128, 256), 256, 0, s0>>>(
        buf0, aHi, aLo, perm, gain, bnstats, g1, be1, 1.f / (float)N1, N2, 128);

    // ---------- Layer 2 ----------
    gemm(N2, 512, 512, w2h, w2l);
    cudaStreamWaitEvent(s0, evCSR[1], 0);
    agg_bn_pool(N2, 512, b2, g2, be2, p2rw, p2rb, p2ow);
    topk_kernel<1024><<<BATCH, 512, 0, s0>>>(score, K1, K2, perm, gain, newid, icount);
    cudaEventRecord(evT[1], s0);
    side_csr(1, N3);
    gather_split_kernel<<<CEILDIV(N3 * 128, 256), 256, 0, s0>>>(
        buf0, aHi, aLo, perm, gain, bnstats, g2, be2, 1.f / (float)N2, N3, 128);

    // ---------- Layer 3 ----------
    gemm(N3, 512, 256, w3h, w3l);
    cudaStreamWaitEvent(s0, evCSR[2], 0);
    agg_bn_pool(N3, 256, b3, g3, be3, p3rw, p3rb, p3ow);
    topk_kernel<512><<<BATCH, 512, 0, s0>>>(score, K2, K3, perm, gain, newid, icount);
    cudaEventRecord(evT[2], s0);
    side_csr(2, N4);
    gather_split_kernel<<<CEILDIV(N4 * 64, 256), 256, 0, s0>>>(
        buf0, aHi, aLo, perm, gain, bnstats, g3, be3, 1.f / (float)N3, N4, 64);

    // ---------- Layer 4 (no BN / pool) ----------
    gemm(N4, 256, 256, w4h, w4l);
    cudaStreamWaitEvent(s0, evCSR[3], 0);
    gather_agg_kernel<256><<<N4, 64, 0, s0>>>(buf1, rowptr, esrc, enorm, b4, buf0, bnstats);

    // ---------- readout ----------
    readout_kernel<<<BATCH, 256, 0, s0>>>(buf0, out);
    (void)in_sizes; (void)n_in; (void)out_size;
}

// round 16
// speedup vs baseline: 1.1823x; 1.0056x over previous
#include <cuda_runtime.h>
#include <cuda_bf16.h>
#include <mma.h>
#include <math.h>
#include <stdint.h>

using namespace nvcuda;

// ---------------- problem constants ----------------
#define BATCH   32
#define ETOT    262144
#define NMAX    32768
#define K1      615
#define K2      369
#define K3      185
#define N1      32768
#define N2      (BATCH*K1)      // 19680
#define N3      (BATCH*K2)      // 11808
#define N4      (BATCH*K3)      // 5920

#define CEILDIV(a,b) (((a)+(b)-1)/(b))

// ---------------- static device scratch ----------------
__device__ float g_buf0[(size_t)NMAX * 512];
__device__ float g_buf1[(size_t)NMAX * 512];
__device__ float g_dis[NMAX];
__device__ float g_score[NMAX];
__device__ float g_t[NMAX];
__device__ float g_gain[NMAX];
__device__ int   g_newid[NMAX];
__device__ int   g_perm[NMAX];
__device__ int   g_src[ETOT];
__device__ int   g_dst[ETOT];
__device__ float g_ew[ETOT];
__device__ float g_bnstats[1024];
// CSR scratch
__device__ int   g_icount[NMAX];
__device__ int   g_rowptr[NMAX + 1];
__device__ int   g_cursor[NMAX];
__device__ int   g_esrc[ETOT];
__device__ float g_enorm[ETOT];
__device__ int   g_blocksum[32];
__device__ int   g_blockoff[32];
// bf16 split-precision GEMM scratch
__device__ __nv_bfloat16 g_aHi[(size_t)NMAX * 512];
__device__ __nv_bfloat16 g_aLo[(size_t)NMAX * 512];
__device__ __nv_bfloat16 g_w1Hi[512 * 512], g_w1Lo[512 * 512];
__device__ __nv_bfloat16 g_w2Hi[512 * 512], g_w2Lo[512 * 512];
__device__ __nv_bfloat16 g_w3Hi[256 * 512], g_w3Lo[256 * 512];
__device__ __nv_bfloat16 g_w4Hi[256 * 256], g_w4Lo[256 * 256];

// ---------------- kernels ----------------

__global__ void edge_init_count_kernel(const int* __restrict__ ei,
                                       int* __restrict__ src, int* __restrict__ dst,
                                       float* __restrict__ ew, int* __restrict__ cnt) {
    int e = blockIdx.x * blockDim.x + threadIdx.x;
    if (e >= ETOT) return;
    int d = ei[ETOT + e];
    src[e] = ei[e];
    dst[e] = d;
    ew[e]  = 1.0f;
    atomicAdd(&cnt[d], 1);
}

// layer-1 activations (icount zeroing moved to convertW on side stream)
__global__ void convertA_kernel(const float4* __restrict__ A,
                                __nv_bfloat162* __restrict__ hi2,
                                __nv_bfloat162* __restrict__ lo2, int n4) {
    int i = blockIdx.x * blockDim.x + threadIdx.x;
    if (i >= n4) return;
    float4 v = A[i];
    __nv_bfloat16 h0 = __float2bfloat16(v.x);
    __nv_bfloat16 h1 = __float2bfloat16(v.y);
    __nv_bfloat16 h2 = __float2bfloat16(v.z);
    __nv_bfloat16 h3 = __float2bfloat16(v.w);
    hi2[2 * i]     = __halves2bfloat162(h0, h1);
    hi2[2 * i + 1] = __halves2bfloat162(h2, h3);
    lo2[2 * i]     = __halves2bfloat162(__float2bfloat16(v.x - __bfloat162float(h0)),
                                        __float2bfloat16(v.y - __bfloat162float(h1)));
    lo2[2 * i + 1] = __halves2bfloat162(__float2bfloat16(v.z - __bfloat162float(h2)),
                                        __float2bfloat16(v.w - __bfloat162float(h3)));
}

// all 4 weight matrices: W [K,N] fp32 -> WT_hi/lo [N,K] bf16; also zeroes icount[0:N1)
#define W1_ELEMS (512 * 512)
#define W2_END   (2 * W1_ELEMS)
#define W3_END   (W2_END + 256 * 512)
#define W4_END   (W3_END + 256 * 256)
__global__ void convertW_all_kernel(const float* __restrict__ W1, const float* __restrict__ W2,
                                    const float* __restrict__ W3, const float* __restrict__ W4,
                                    __nv_bfloat16* w1h, __nv_bfloat16* w1l,
                                    __nv_bfloat16* w2h, __nv_bfloat16* w2l,
                                    __nv_bfloat16* w3h, __nv_bfloat16* w3l,
                                    __nv_bfloat16* w4h, __nv_bfloat16* w4l,
                                    int* __restrict__ icount) {
    int idx = blockIdx.x * blockDim.x + threadIdx.x;
    if (idx < N1) icount[idx] = 0;
    const float* W; __nv_bfloat16 *h, *l; int K, N, local;
    if (idx < W1_ELEMS)      { W = W1; h = w1h; l = w1l; K = 512; N = 512; local = idx; }
    else if (idx < W2_END)   { W = W2; h = w2h; l = w2l; K = 512; N = 512; local = idx - W1_ELEMS; }
    else if (idx < W3_END)   { W = W3; h = w3h; l = w3l; K = 512; N = 256; local = idx - W2_END; }
    else if (idx < W4_END)   { W = W4; h = w4h; l = w4l; K = 256; N = 256; local = idx - W3_END; }
    else return;
    int n = local / K, k = local - n * K;
    float v = W[k * N + n];
    __nv_bfloat16 hh = __float2bfloat16(v);
    h[local] = hh;
    l[local] = __float2bfloat16(v - __bfloat162float(hh));
}

// ---------------------------------------------------------------
// WMMA bf16 split-precision GEMM (unchanged).
// ---------------------------------------------------------------
#define TBM 128
#define TBN 128
#define TBK 32
#define WLDA 40
#define TILE_BYTES (128 * WLDA * 2)
#define TILE_ELEMS (128 * WLDA)
#define STAGE_BYTES (4 * TILE_BYTES)
#define GEMM_SMEM (2 * STAGE_BYTES)

__device__ __forceinline__ void cp16(uint32_t s, const void* g, int sz) {
    asm volatile("cp.async.cg.shared.global [%0], [%1], 16, %2;"
                 :: "r"(s), "l"(g), "r"(sz));
}

__global__ void __launch_bounds__(256, 2)
wmma_gemm_kernel(const __nv_bfloat16* __restrict__ Ahi,
                 const __nv_bfloat16* __restrict__ Alo,
                 const __nv_bfloat16* __restrict__ Bhi,
                 const __nv_bfloat16* __restrict__ Blo,
                 float* __restrict__ C, int M, int K, int N) {
    extern __shared__ __nv_bfloat16 sm[];

    const int tid = threadIdx.x;
    const int wid = tid >> 5;
    const int warpM = wid & 1;
    const int warpN = wid >> 1;
    const int mBase = blockIdx.y * TBM;
    const int nBase = blockIdx.x * TBN;

    wmma::fragment<wmma::accumulator, 16, 16, 16, float> acc[4][2];
#pragma unroll
    for (int i = 0; i < 4; i++)
#pragma unroll
        for (int j = 0; j < 2; j++) wmma::fill_fragment(acc[i][j], 0.f);

    const uint32_t sbase = (uint32_t)__cvta_generic_to_shared(sm);
    const int row = tid >> 1;
    const int q0 = (tid & 1) * 2;
    const int grow = mBase + row;
    const int nrow = nBase + row;
    const size_t aoff = (size_t)(grow < M ? grow : 0) * K;
    const size_t boff = (size_t)nrow * K;
    const int szA = (grow < M) ? 16 : 0;
    const uint32_t srow = sbase + (uint32_t)row * (WLDA * 2);

#define LOAD_STAGE(s, kc) do { \
        uint32_t s0 = srow + (uint32_t)(s) * STAGE_BYTES; \
        _Pragma("unroll") \
        for (int qq = 0; qq < 2; qq++) { \
            int q = q0 + qq; \
            cp16(s0 + q * 16,                  Ahi + aoff + (kc) + q * 8, szA); \
            cp16(s0 + q * 16 + TILE_BYTES,     Alo + aoff + (kc) + q * 8, szA); \
            cp16(s0 + q * 16 + 2 * TILE_BYTES, Bhi + boff + (kc) + q * 8, 16); \
            cp16(s0 + q * 16 + 3 * TILE_BYTES, Blo + boff + (kc) + q * 8, 16); \
        } \
    } while (0)

    LOAD_STAGE(0, 0);
    asm volatile("cp.async.commit_group;" ::: "memory");

    const int nCh = K >> 5;
    for (int ch = 0; ch < nCh; ch++) {
        if (ch + 1 < nCh) {
            LOAD_STAGE((ch + 1) & 1, (ch + 1) << 5);
            asm volatile("cp.async.commit_group;" ::: "memory");
            asm volatile("cp.async.wait_group 1;" ::: "memory");
        } else {
            asm volatile("cp.async.wait_group 0;" ::: "memory");
        }
        __syncthreads();

        const __nv_bfloat16* sb   = sm + (ch & 1) * (4 * TILE_ELEMS);
        const __nv_bfloat16* sAhi = sb;
        const __nv_bfloat16* sAlo = sb + TILE_ELEMS;
        const __nv_bfloat16* sBhi = sb + 2 * TILE_ELEMS;
        const __nv_bfloat16* sBlo = sb + 3 * TILE_ELEMS;

#pragma unroll
        for (int ks = 0; ks < TBK; ks += 16) {
            wmma::fragment<wmma::matrix_b, 16, 16, 16, __nv_bfloat16, wmma::col_major> bh[2], bl[2];
#pragma unroll
            for (int j = 0; j < 2; j++) {
                wmma::load_matrix_sync(bh[j], sBhi + (warpN * 32 + j * 16) * WLDA + ks, WLDA);
                wmma::load_matrix_sync(bl[j], sBlo + (warpN * 32 + j * 16) * WLDA + ks, WLDA);
            }
#pragma unroll
            for (int i = 0; i < 4; i++) {
                wmma::fragment<wmma::matrix_a, 16, 16, 16, __nv_bfloat16, wmma::row_major> ah, al;
                wmma::load_matrix_sync(ah, sAhi + (warpM * 64 + i * 16) * WLDA + ks, WLDA);
                wmma::load_matrix_sync(al, sAlo + (warpM * 64 + i * 16) * WLDA + ks, WLDA);
#pragma unroll
                for (int j = 0; j < 2; j++) wmma::mma_sync(acc[i][j], ah, bh[j], acc[i][j]);
#pragma unroll
                for (int j = 0; j < 2; j++) wmma::mma_sync(acc[i][j], ah, bl[j], acc[i][j]);
#pragma unroll
                for (int j = 0; j < 2; j++) wmma::mma_sync(acc[i][j], al, bh[j], acc[i][j]);
            }
        }
        __syncthreads();
    }
#undef LOAD_STAGE

#pragma unroll
    for (int i = 0; i < 4; i++) {
        int r0 = mBase + warpM * 64 + i * 16;
#pragma unroll
        for (int j = 0; j < 2; j++) {
            float* cp = C + (size_t)r0 * N + nBase + warpN * 32 + j * 16;
            wmma::store_matrix_sync(cp, acc[i][j], N, wmma::mem_row_major);
        }
    }
}

// ---------------- CSR build (3-phase coalesced scan) ----------------

__global__ void __launch_bounds__(1024)
scan_partial_kernel(const int* __restrict__ cnt, int* __restrict__ rowptr,
                    int* __restrict__ blocksum, int n) {
    __shared__ int warpsum[32];
    const int tid = threadIdx.x;
    const int i = blockIdx.x * 1024 + tid;
    int v = (i < n) ? cnt[i] : 0;
    const int s = v;

    const int lane = tid & 31, wid = tid >> 5;
#pragma unroll
    for (int off = 1; off < 32; off <<= 1) {
        int u = __shfl_up_sync(0xffffffffu, v, off);
        if (lane >= off) v += u;
    }
    if (lane == 31) warpsum[wid] = v;
    __syncthreads();
    if (wid == 0) {
        int w = warpsum[lane];
#pragma unroll
        for (int off = 1; off < 32; off <<= 1) {
            int u = __shfl_up_sync(0xffffffffu, w, off);
            if (lane >= off) w += u;
        }
        warpsum[lane] = w;
    }
    __syncthreads();
    int excl = v - s + (wid > 0 ? warpsum[wid - 1] : 0);
    if (i < n) rowptr[i] = excl;
    if (tid == 1023) blocksum[blockIdx.x] = excl + s;
}

__global__ void scan_blocksums_kernel(const int* __restrict__ blocksum,
                                      int* __restrict__ blockoff,
                                      int* __restrict__ rowptr,
                                      int nblocks, int n) {
    const int lane = threadIdx.x;
    int v = (lane < nblocks) ? blocksum[lane] : 0;
    const int s = v;
#pragma unroll
    for (int off = 1; off < 32; off <<= 1) {
        int u = __shfl_up_sync(0xffffffffu, v, off);
        if (lane >= off) v += u;
    }
    if (lane < nblocks) blockoff[lane] = v - s;
    if (lane == 31) rowptr[n] = v;
}

__global__ void __launch_bounds__(1024)
scan_finalize_kernel(const int* __restrict__ cnt, int* __restrict__ rowptr,
                     const int* __restrict__ blockoff,
                     int* __restrict__ cursor, float* __restrict__ dis,
                     int* __restrict__ newid, int n) {
    const int i = blockIdx.x * 1024 + threadIdx.x;
    if (i >= n) return;
    int r = rowptr[i] + blockoff[blockIdx.x];
    rowptr[i] = r;
    cursor[i] = r;
    int c = cnt[i];
    dis[i] = (c > 0) ? rsqrtf((float)c) : 0.f;
    newid[i] = -1;
}

__global__ void fill_kernel(const int* __restrict__ src, const int* __restrict__ dst,
                            const float* __restrict__ ew, const float* __restrict__ dis,
                            int* __restrict__ cursor,
                            int* __restrict__ esrc, float* __restrict__ enorm) {
    int e = blockIdx.x * blockDim.x + threadIdx.x;
    if (e >= ETOT) return;
    float w = ew[e];
    if (w == 0.f) return;
    int s = src[e], d = dst[e];
    int pos = atomicAdd(&cursor[d], 1);
    esrc[pos] = s;
    enorm[pos] = dis[s] * dis[d] * w;
}

// one block per node, C/4 threads; 4-deep unrolled edge loop; block 0 zeroes bnstats
template <int C>
__global__ void gather_agg_kernel(const float* __restrict__ h,
                                  const int* __restrict__ rowptr,
                                  const int* __restrict__ esrc,
                                  const float* __restrict__ enorm,
                                  const float* __restrict__ bias,
                                  float* __restrict__ out,
                                  float* __restrict__ bnstats) {
    const int node = blockIdx.x;
    const int tid = threadIdx.x;
    if (node == 0)
        for (int k = tid; k < 1024; k += (C / 4)) bnstats[k] = 0.f;
    float4 acc = *(const float4*)(bias + tid * 4);
    int b = rowptr[node];
    const int e = rowptr[node + 1];
    for (; b + 3 < e; b += 4) {
        int s0 = esrc[b],     s1 = esrc[b + 1], s2 = esrc[b + 2], s3 = esrc[b + 3];
        float n0 = enorm[b],  n1 = enorm[b + 1], n2 = enorm[b + 2], n3 = enorm[b + 3];
        float4 v0 = *(const float4*)(h + (size_t)s0 * C + tid * 4);
        float4 v1 = *(const float4*)(h + (size_t)s1 * C + tid * 4);
        float4 v2 = *(const float4*)(h + (size_t)s2 * C + tid * 4);
        float4 v3 = *(const float4*)(h + (size_t)s3 * C + tid * 4);
        acc.x += v0.x * n0; acc.y += v0.y * n0; acc.z += v0.z * n0; acc.w += v0.w * n0;
        acc.x += v1.x * n1; acc.y += v1.y * n1; acc.z += v1.z * n1; acc.w += v1.w * n1;
        acc.x += v2.x * n2; acc.y += v2.y * n2; acc.z += v2.z * n2; acc.w += v2.w * n2;
        acc.x += v3.x * n3; acc.y += v3.y * n3; acc.z += v3.z * n3; acc.w += v3.w * n3;
    }
    for (; b < e; b++) {
        int s0 = esrc[b];
        float n0 = enorm[b];
        float4 v0 = *(const float4*)(h + (size_t)s0 * C + tid * 4);
        acc.x += v0.x * n0; acc.y += v0.y * n0; acc.z += v0.z * n0; acc.w += v0.w * n0;
    }
    *(float4*)(out + (size_t)node * C + tid * 4) = acc;
}

// ---------------- BN / pool / misc ----------------

__global__ void bn_stats_kernel(const float* __restrict__ h,
                                float* __restrict__ bnstats,
                                int n, int C) {
    int c = blockIdx.x * 256 + threadIdx.x;
    if (c >= C) return;
    int rowsPer = CEILDIV(n, gridDim.y);
    int r0 = blockIdx.y * rowsPer;
    int r1 = min(n, r0 + rowsPer);
    float s = 0.f, sq = 0.f;
    for (int r = r0; r < r1; r++) {
        float v = h[(size_t)r * C + c];
        s += v;
        sq += v * v;
    }
    atomicAdd(&bnstats[c], s);
    atomicAdd(&bnstats[512 + c], sq);
}

// BN(apply)+tanh + pool dot-products, READ-ONLY on h
__global__ void bn_dots_kernel(const float* __restrict__ h,
                               const float* __restrict__ bnstats,
                               const float* __restrict__ gma, const float* __restrict__ bta,
                               const float* __restrict__ relw, const float* __restrict__ rootw,
                               const float* __restrict__ relb,
                               float* __restrict__ t, float* __restrict__ score,
                               int n, int C) {
    int node = (blockIdx.x * blockDim.x + threadIdx.x) >> 5;
    int lane = threadIdx.x & 31;
    if (node >= n) return;
    const float* hp = h + (size_t)node * C;
    const float invn = 1.f / (float)n;
    float a = 0.f, b = 0.f;
    for (int c = lane; c < C; c += 32) {
        float mean = bnstats[c] * invn;
        float var = bnstats[512 + c] * invn - mean * mean;
        float y = tanhf((hp[c] - mean) * rsqrtf(var + 1e-5f) * gma[c] + bta[c]);
        a += y * relw[c];
        b += y * rootw[c];
    }
#pragma unroll
    for (int o = 16; o > 0; o >>= 1) {
        a += __shfl_down_sync(0xffffffffu, a, o);
        b += __shfl_down_sync(0xffffffffu, b, o);
    }
    if (lane == 0) {
        t[node] = a;
        score[node] = b + relb[0];
    }
}

// topk: computes final score inline via CSR gather of t (replaces score_edge),
// then per-graph bitonic top-k; also zeroes icount[0 : B*ksel)
template <int SZ>
__global__ void __launch_bounds__(512)
topk_kernel(const float* __restrict__ score, const float* __restrict__ t,
            const int* __restrict__ rowptr, const int* __restrict__ esrc,
            int n_per, int ksel,
            int* __restrict__ perm, float* __restrict__ gain, int* __restrict__ newid,
            int* __restrict__ icount) {
    __shared__ float sk[SZ];
    __shared__ int si[SZ];
    const int g = blockIdx.x;
    const int tid = threadIdx.x;
    for (int i = tid; i < SZ; i += 512) {
        if (i < n_per) {
            int node = g * n_per + i;
            float s = score[node];
            int b = rowptr[node];
            const int e = rowptr[node + 1];
            for (; b < e; b++) s += t[esrc[b]];
            sk[i] = s;
            si[i] = i;
        } else {
            sk[i] = -INFINITY;
            si[i] = 0x40000000 + i;
        }
    }
    __syncthreads();
    for (int kk = 2; kk <= SZ; kk <<= 1) {
        for (int j = kk >> 1; j > 0; j >>= 1) {
            for (int i = tid; i < SZ; i += 512) {
                int ixj = i ^ j;
                if (ixj > i) {
                    bool up = ((i & kk) == 0);
                    float s1 = sk[i], s2 = sk[ixj];
                    int i1 = si[i], i2 = si[ixj];
                    bool after = (s1 < s2) || (s1 == s2 && i1 > i2);
                    if (up == after) {
                        sk[i] = s2; sk[ixj] = s1;
                        si[i] = i2; si[ixj] = i1;
                    }
                }
            }
            __syncthreads();
        }
    }
    for (int r = tid; r < ksel; r += 512) {
        int old = g * n_per + si[r];
        int ng = g * ksel + r;
        perm[ng] = old;
        gain[ng] = tanhf(sk[r]);
        newid[old] = ng;
        icount[ng] = 0;
    }
}

// pool gather: applies BN+tanh (from raw agg) then *gain, then bf16 hi/lo split
__global__ void gather_split_kernel(const float* __restrict__ hin,
                                    __nv_bfloat16* __restrict__ hi,
                                    __nv_bfloat16* __restrict__ lo,
                                    const int* __restrict__ perm,
                                    const float* __restrict__ gain,
                                    const float* __restrict__ bnstats,
                                    const float* __restrict__ gma,
                                    const float* __restrict__ bta,
                                    float invn,
                                    int rows, int C4) {
    int idx = blockIdx.x * blockDim.x + threadIdx.x;
    if (idx >= rows * C4) return;
    int row = idx / C4;
    int c4 = idx - row * C4;
    int c = c4 * 4;
    float gn = gain[row];
    float4 v = ((const float4*)hin)[(size_t)perm[row] * C4 + c4];
    float m0 = bnstats[c + 0] * invn, m1 = bnstats[c + 1] * invn;
    float m2 = bnstats[c + 2] * invn, m3 = bnstats[c + 3] * invn;
    float r0 = rsqrtf(bnstats[512 + c + 0] * invn - m0 * m0 + 1e-5f) * gma[c + 0];
    float r1 = rsqrtf(bnstats[512 + c + 1] * invn - m1 * m1 + 1e-5f) * gma[c + 1];
    float r2 = rsqrtf(bnstats[512 + c + 2] * invn - m2 * m2 + 1e-5f) * gma[c + 2];
    float r3 = rsqrtf(bnstats[512 + c + 3] * invn - m3 * m3 + 1e-5f) * gma[c + 3];
    v.x = tanhf((v.x - m0) * r0 + bta[c + 0]) * gn;
    v.y = tanhf((v.y - m1) * r1 + bta[c + 1]) * gn;
    v.z = tanhf((v.z - m2) * r2 + bta[c + 2]) * gn;
    v.w = tanhf((v.w - m3) * r3 + bta[c + 3]) * gn;
    __nv_bfloat16 h0 = __float2bfloat16(v.x);
    __nv_bfloat16 h1 = __float2bfloat16(v.y);
    __nv_bfloat16 h2 = __float2bfloat16(v.z);
    __nv_bfloat16 h3 = __float2bfloat16(v.w);
    __nv_bfloat162* hp = (__nv_bfloat162*)(hi) + 2 * idx;
    __nv_bfloat162* lp = (__nv_bfloat162*)(lo) + 2 * idx;
    hp[0] = __halves2bfloat162(h0, h1);
    hp[1] = __halves2bfloat162(h2, h3);
    lp[0] = __halves2bfloat162(__float2bfloat16(v.x - __bfloat162float(h0)),
                               __float2bfloat16(v.y - __bfloat162float(h1)));
    lp[1] = __halves2bfloat162(__float2bfloat16(v.z - __bfloat162float(h2)),
                               __float2bfloat16(v.w - __bfloat162float(h3)));
}

__global__ void remap_count_kernel(int* __restrict__ src, int* __restrict__ dst,
                                   float* __restrict__ ew, const int* __restrict__ newid,
                                   int* __restrict__ cnt) {
    int e = blockIdx.x * blockDim.x + threadIdx.x;
    if (e >= ETOT) return;
    int ns = newid[src[e]];
    int nd = newid[dst[e]];
    bool keep = (ns >= 0) && (nd >= 0) && (ew[e] != 0.f);
    src[e] = keep ? ns : 0;
    dst[e] = keep ? nd : 0;
    ew[e] = keep ? ew[e] : 0.f;
    if (keep) atomicAdd(&cnt[nd], 1);
}

__global__ void readout_kernel(const float* __restrict__ h, float* __restrict__ out) {
    int g = blockIdx.x;
    int c = threadIdx.x;
    const float* p = h + (size_t)(g * K3) * 256 + c;
    float mx = -INFINITY, sm = 0.f;
    for (int i = 0; i < K3; i++) {
        float v = p[(size_t)i * 256];
        mx = fmaxf(mx, v);
        sm += v;
    }
    out[g * 512 + c] = mx;
    out[g * 512 + 256 + c] = sm / (float)K3;
}

// ---------------- host orchestration ----------------

extern "C" void kernel_launch(void* const* d_in, const int* in_sizes, int n_in,
                              void* d_out, int out_size) {
    const float* x    = (const float*)d_in[0];
    const int*   ei   = (const int*)d_in[1];
    const float* W1   = (const float*)d_in[2];
    const float* b1   = (const float*)d_in[3];
    const float* W2   = (const float*)d_in[4];
    const float* b2   = (const float*)d_in[5];
    const float* W3   = (const float*)d_in[6];
    const float* b3   = (const float*)d_in[7];
    const float* W4   = (const float*)d_in[8];
    const float* b4   = (const float*)d_in[9];
    const float* g1   = (const float*)d_in[10];
    const float* be1  = (const float*)d_in[11];
    const float* g2   = (const float*)d_in[12];
    const float* be2  = (const float*)d_in[13];
    const float* g3   = (const float*)d_in[14];
    const float* be3  = (const float*)d_in[15];
    const float* p1rw = (const float*)d_in[16];
    const float* p1rb = (const float*)d_in[17];
    const float* p1ow = (const float*)d_in[18];
    const float* p2rw = (const float*)d_in[19];
    const float* p2rb = (const float*)d_in[20];
    const float* p2ow = (const float*)d_in[21];
    const float* p3rw = (const float*)d_in[22];
    const float* p3rb = (const float*)d_in[23];
    const float* p3ow = (const float*)d_in[24];
    float* out = (float*)d_out;

    float *buf0, *buf1, *dis, *score, *t, *gain, *ew, *bnstats, *enorm;
    int *src, *dst, *newid, *perm, *icount, *rowptr, *cursor, *esrc, *blocksum, *blockoff;
    __nv_bfloat16 *aHi, *aLo;
    __nv_bfloat16 *w1h, *w1l, *w2h, *w2l, *w3h, *w3l, *w4h, *w4l;
    cudaGetSymbolAddress((void**)&buf0, g_buf0);
    cudaGetSymbolAddress((void**)&buf1, g_buf1);
    cudaGetSymbolAddress((void**)&dis, g_dis);
    cudaGetSymbolAddress((void**)&score, g_score);
    cudaGetSymbolAddress((void**)&t, g_t);
    cudaGetSymbolAddress((void**)&gain, g_gain);
    cudaGetSymbolAddress((void**)&ew, g_ew);
    cudaGetSymbolAddress((void**)&bnstats, g_bnstats);
    cudaGetSymbolAddress((void**)&src, g_src);
    cudaGetSymbolAddress((void**)&dst, g_dst);
    cudaGetSymbolAddress((void**)&newid, g_newid);
    cudaGetSymbolAddress((void**)&perm, g_perm);
    cudaGetSymbolAddress((void**)&icount, g_icount);
    cudaGetSymbolAddress((void**)&rowptr, g_rowptr);
    cudaGetSymbolAddress((void**)&cursor, g_cursor);
    cudaGetSymbolAddress((void**)&esrc, g_esrc);
    cudaGetSymbolAddress((void**)&enorm, g_enorm);
    cudaGetSymbolAddress((void**)&blocksum, g_blocksum);
    cudaGetSymbolAddress((void**)&blockoff, g_blockoff);
    cudaGetSymbolAddress((void**)&aHi, g_aHi);
    cudaGetSymbolAddress((void**)&aLo, g_aLo);
    cudaGetSymbolAddress((void**)&w1h, g_w1Hi);
    cudaGetSymbolAddress((void**)&w1l, g_w1Lo);
    cudaGetSymbolAddress((void**)&w2h, g_w2Hi);
    cudaGetSymbolAddress((void**)&w2l, g_w2Lo);
    cudaGetSymbolAddress((void**)&w3h, g_w3Hi);
    cudaGetSymbolAddress((void**)&w3l, g_w3Lo);
    cudaGetSymbolAddress((void**)&w4h, g_w4Hi);
    cudaGetSymbolAddress((void**)&w4l, g_w4Lo);

    cudaFuncSetAttribute(wmma_gemm_kernel,
                         cudaFuncAttributeMaxDynamicSharedMemorySize, GEMM_SMEM);

    static cudaStream_t s2 = nullptr;
    static cudaEvent_t evRoot, evW, evCSR[4], evT[3];
    if (s2 == nullptr) {
        cudaStreamCreateWithFlags(&s2, cudaStreamNonBlocking);
        cudaEventCreateWithFlags(&evRoot, cudaEventDisableTiming);
        cudaEventCreateWithFlags(&evW, cudaEventDisableTiming);
        for (int i = 0; i < 4; i++) cudaEventCreateWithFlags(&evCSR[i], cudaEventDisableTiming);
        for (int i = 0; i < 3; i++) cudaEventCreateWithFlags(&evT[i], cudaEventDisableTiming);
    }

    const int EB = CEILDIV(ETOT, 256);
    const cudaStream_t s0 = 0;

    // ---- fork: side stream does weights(+icount zero), edges, layer-1 CSR ----
    cudaEventRecord(evRoot, s0);
    cudaStreamWaitEvent(s2, evRoot, 0);
    convertW_all_kernel<<<CEILDIV(W4_END, 256), 256, 0, s2>>>(W1, W2, W3, W4,
                                                              w1h, w1l, w2h, w2l,
                                                              w3h, w3l, w4h, w4l, icount);
    cudaEventRecord(evW, s2);
    edge_init_count_kernel<<<EB, 256, 0, s2>>>(ei, src, dst, ew, icount);

    auto csr_chain = [&](int n) {
        int nb = CEILDIV(n, 1024);
        scan_partial_kernel<<<nb, 1024, 0, s2>>>(icount, rowptr, blocksum, n);
        scan_blocksums_kernel<<<1, 32, 0, s2>>>(blocksum, blockoff, rowptr, nb, n);
        scan_finalize_kernel<<<nb, 1024, 0, s2>>>(icount, rowptr, blockoff,
                                                  cursor, dis, newid, n);
        fill_kernel<<<EB, 256, 0, s2>>>(src, dst, ew, dis, cursor, esrc, enorm);
    };
    csr_chain(N1);
    cudaEventRecord(evCSR[0], s2);

    // ---- main stream: activation split ----
    {
        int n4 = N1 * 512 / 4;
        convertA_kernel<<<CEILDIV(n4, 256), 256, 0, s0>>>((const float4*)x,
                                                          (__nv_bfloat162*)aHi,
                                                          (__nv_bfloat162*)aLo, n4);
    }

    auto gemm = [&](int n, int Cin, int Cout,
                    const __nv_bfloat16* wh, const __nv_bfloat16* wl) {
        wmma_gemm_kernel<<<dim3(Cout / TBN, CEILDIV(n, TBM)), 256, GEMM_SMEM, s0>>>(
            aHi, aLo, wh, wl, buf1, n, Cin, Cout);
    };
    auto agg_bn_pool = [&](int n, int C, const float* b,
                           const float* gma, const float* bta,
                           const float* rw, const float* rb, const float* ow) {
        if (C == 512)
            gather_agg_kernel<512><<<n, 128, 0, s0>>>(buf1, rowptr, esrc, enorm, b, buf0, bnstats);
        else
            gather_agg_kernel<256><<<n, 64, 0, s0>>>(buf1, rowptr, esrc, enorm, b, buf0, bnstats);
        bn_stats_kernel<<<dim3(CEILDIV(C, 256), 128), 256, 0, s0>>>(buf0, bnstats, n, C);
        bn_dots_kernel<<<CEILDIV(n * 32, 256), 256, 0, s0>>>(buf0, bnstats, gma, bta,
                                                             rw, ow, rb, t, score, n, C);
    };
    auto side_csr = [&](int li, int nNext) {
        cudaStreamWaitEvent(s2, evT[li], 0);
        remap_count_kernel<<<EB, 256, 0, s2>>>(src, dst, ew, newid, icount);
        csr_chain(nNext);
        cudaEventRecord(evCSR[li + 1], s2);
    };

    // ---------- Layer 1 ----------
    cudaStreamWaitEvent(s0, evW, 0);
    gemm(N1, 512, 512, w1h, w1l);
    cudaStreamWaitEvent(s0, evCSR[0], 0);
    agg_bn_pool(N1, 512, b1, g1, be1, p1rw, p1rb, p1ow);
    topk_kernel<1024><<<BATCH, 512, 0, s0>>>(score, t, rowptr, esrc, 1024, K1,
                                             perm, gain, newid, icount);
    cudaEventRecord(evT[0], s0);
    side_csr(0, N2);
    gather_split_kernel<<<CEILDIV(N2 * 128, 256), 256, 0, s0>>>(
        buf0, aHi, aLo, perm, gain, bnstats, g1, be1, 1.f / (float)N1, N2, 128);

    // ---------- Layer 2 ----------
    gemm(N2, 512, 512, w2h, w2l);
    cudaStreamWaitEvent(s0, evCSR[1], 0);
    agg_bn_pool(N2, 512, b2, g2, be2, p2rw, p2rb, p2ow);
    topk_kernel<1024><<<BATCH, 512, 0, s0>>>(score, t, rowptr, esrc, K1, K2,
                                             perm, gain, newid, icount);
    cudaEventRecord(evT[1], s0);
    side_csr(1, N3);
    gather_split_kernel<<<CEILDIV(N3 * 128, 256), 256, 0, s0>>>(
        buf0, aHi, aLo, perm, gain, bnstats, g2, be2, 1.f / (float)N2, N3, 128);

    // ---------- Layer 3 ----------
    gemm(N3, 512, 256, w3h, w3l);
    cudaStreamWaitEvent(s0, evCSR[2], 0);
    agg_bn_pool(N3, 256, b3, g3, be3, p3rw, p3rb, p3ow);
    topk_kernel<512><<<BATCH, 512, 0, s0>>>(score, t, rowptr, esrc, K2, K3,
                                            perm, gain, newid, icount);
    cudaEventRecord(evT[2], s0);
    side_csr(2, N4);
    gather_split_kernel<<<CEILDIV(N4 * 64, 256), 256, 0, s0>>>(
        buf0, aHi, aLo, perm, gain, bnstats, g3, be3, 1.f / (float)N3, N4, 64);

    // ---------- Layer 4 (no BN / pool) ----------
    gemm(N4, 256, 256, w4h, w4l);
    cudaStreamWaitEvent(s0, evCSR[3], 0);
    gather_agg_kernel<256><<<N4, 64, 0, s0>>>(buf1, rowptr, esrc, enorm, b4, buf0, bnstats);

    // ---------- readout ----------
    readout_kernel<<<BATCH, 256, 0, s0>>>(buf0, out);
    (void)in_sizes; (void)n_in; (void)out_size;
}